// round 6
// baseline (speedup 1.0000x reference)
#include <cuda_runtime.h>
#include <cuda_bf16.h>
#include <math.h>
#include <stdint.h>

// Problem constants
#define Bv      2
#define Tv      2048
#define NTOK    (Bv * Tv)      // 4096
#define Dv      512
#define Hv      8
#define HDv     64
#define FFNv    2048
#define VOCABv  256
#define Lv      2
#define CHUNK   32
#define NCHUNK  (Tv / CHUNK)   // 64
#define QKVN    1536

// weight region offsets (elements) in the hi/lo weight pools ([K,N] row-major)
#define OFF_QKV 0
#define OFF_WU  (OFF_QKV + Lv * Dv * QKVN)
#define OFF_WD  (OFF_WU + Lv * Dv * FFNv)
#define OFF_WO  (OFF_WD + Lv * FFNv * Dv)
#define W_TOTAL (OFF_WO + Dv * VOCABv)

// -------------------- scratch (device globals; no allocs) --------------------
__device__ float g_x[NTOK * Dv];
__device__ float g_a[NTOK * Dv];
__device__ float g_qkv[NTOK * QKVN];
__device__ float g_qf[NTOK * Dv];
__device__ float g_kf[NTOK * Dv];
__device__ float g_S[Bv * Hv * NCHUNK * HDv * HDv];
__device__ float g_z[Bv * Hv * NCHUNK * HDv];
__device__ float g_bqkv[Lv * QKVN];
__device__ float g_part[2 * NTOK * VOCABv];
__device__ __nv_bfloat16 g_xh[NTOK * Dv];
__device__ __nv_bfloat16 g_xl[NTOK * Dv];
__device__ __nv_bfloat16 g_hh[NTOK * FFNv];
__device__ __nv_bfloat16 g_hl[NTOK * FFNv];
__device__ __nv_bfloat16 g_wh[W_TOTAL];
__device__ __nv_bfloat16 g_wl[W_TOTAL];

__device__ __forceinline__ void split_bf16(float v, __nv_bfloat16& h, __nv_bfloat16& l) {
    h = __float2bfloat16(v);
    l = __float2bfloat16(v - __bfloat162float(h));
}

// -------------------- weight fp32 -> bf16 hi/lo (vectorized) --------------------
__global__ void convw4(const float* __restrict__ src, __nv_bfloat16* __restrict__ dh,
                       __nv_bfloat16* __restrict__ dl, int n4) {
    int i = blockIdx.x * blockDim.x + threadIdx.x;
    if (i >= n4) return;
    float4 v = *(const float4*)(src + 4 * i);
    __nv_bfloat16 h0, h1, h2, h3, l0, l1, l2, l3;
    split_bf16(v.x, h0, l0); split_bf16(v.y, h1, l1);
    split_bf16(v.z, h2, l2); split_bf16(v.w, h3, l3);
    ((__nv_bfloat162*)(dh + 4 * i))[0] = __nv_bfloat162(h0, h1);
    ((__nv_bfloat162*)(dh + 4 * i))[1] = __nv_bfloat162(h2, h3);
    ((__nv_bfloat162*)(dl + 4 * i))[0] = __nv_bfloat162(l0, l1);
    ((__nv_bfloat162*)(dl + 4 * i))[1] = __nv_bfloat162(l2, l3);
}

// QKV weight: src [L*512, 512] row-major -> dst rows stride 1536 at column colofs
__global__ void convw_qkv(const float* __restrict__ src, __nv_bfloat16* __restrict__ dh,
                          __nv_bfloat16* __restrict__ dl, int colofs) {
    int i = blockIdx.x * blockDim.x + threadIdx.x;
    if (i >= Lv * Dv * Dv / 4) return;
    int e = 4 * i;
    int k = e >> 9, col = e & 511;
    float4 v = *(const float4*)(src + e);
    size_t dst = (size_t)k * QKVN + colofs + col;
    __nv_bfloat16 h0, h1, h2, h3, l0, l1, l2, l3;
    split_bf16(v.x, h0, l0); split_bf16(v.y, h1, l1);
    split_bf16(v.z, h2, l2); split_bf16(v.w, h3, l3);
    ((__nv_bfloat162*)(dh + dst))[0] = __nv_bfloat162(h0, h1);
    ((__nv_bfloat162*)(dh + dst))[1] = __nv_bfloat162(h2, h3);
    ((__nv_bfloat162*)(dl + dst))[0] = __nv_bfloat162(l0, l1);
    ((__nv_bfloat162*)(dl + dst))[1] = __nv_bfloat162(l2, l3);
}

__global__ void bias_qkv(const float* __restrict__ bq, const float* __restrict__ bk,
                         const float* __restrict__ bvp) {
    int idx = blockIdx.x * blockDim.x + threadIdx.x;
    if (idx >= Lv * QKVN) return;
    int l = idx / QKVN, c = idx % QKVN;
    float v;
    if (c < 512) v = bq[l * Dv + c];
    else if (c < 1024) v = bk[l * Dv + c - 512];
    else v = bvp[l * Dv + c - 1024];
    g_bqkv[idx] = v;
}

// -------------------- embedding + sinusoidal positions --------------------
__global__ void embed_kernel(const int* __restrict__ tokens,
                             const float* __restrict__ emb) {
    int idx = blockIdx.x * blockDim.x + threadIdx.x;
    if (idx >= NTOK * Dv) return;
    int n = idx >> 9;
    int j = idx & 511;
    int t = n & (Tv - 1);
    float val;
    const float c = 9.210340371976184f / 256.f;
    if (j < 256) {
        int tok = tokens[n];
        val = emb[tok * 256 + j];
    } else if (j < 384) {
        int i = j - 256;
        val = sinf((float)t * expf(-(2.f * (float)i) * c));
    } else {
        int i = j - 384;
        val = cosf((float)t * expf(-(2.f * (float)i) * c));
    }
    g_x[idx] = val;
    __nv_bfloat16 h, l;
    split_bf16(val, h, l);
    g_xh[idx] = h;
    g_xl[idx] = l;
}

// -------------------- tensor-core GEMM, BK=64, 2-stage cp.async --------------------
// C = A@B + bias; A[M,K] (stride lda), B[K,N] (stride ldb), bf16 hi/lo pairs.
// A*B ~= AhBh + AlBh + AhBl. BM=BN=128, 256 threads (8 warps, 32x64 warp tiles).
// mode 0: fp32 out + bias. mode 1: gelu -> bf16 hi/lo. mode 2: raw fp32 (no bias).

__device__ __forceinline__ void ldsm_x4(uint32_t* r, const void* p) {
    uint32_t a = (uint32_t)__cvta_generic_to_shared(p);
    asm volatile("ldmatrix.sync.aligned.m8n8.x4.shared.b16 {%0,%1,%2,%3},[%4];"
        : "=r"(r[0]), "=r"(r[1]), "=r"(r[2]), "=r"(r[3]) : "r"(a));
}
__device__ __forceinline__ void ldsm_x4_t(uint32_t* r, const void* p) {
    uint32_t a = (uint32_t)__cvta_generic_to_shared(p);
    asm volatile("ldmatrix.sync.aligned.m8n8.x4.trans.shared.b16 {%0,%1,%2,%3},[%4];"
        : "=r"(r[0]), "=r"(r[1]), "=r"(r[2]), "=r"(r[3]) : "r"(a));
}
__device__ __forceinline__ void mma16816(float* c, const uint32_t* a, const uint32_t* b) {
    asm volatile("mma.sync.aligned.m16n8k16.row.col.f32.bf16.bf16.f32 "
        "{%0,%1,%2,%3},{%4,%5,%6,%7},{%8,%9},{%0,%1,%2,%3};"
        : "+f"(c[0]), "+f"(c[1]), "+f"(c[2]), "+f"(c[3])
        : "r"(a[0]), "r"(a[1]), "r"(a[2]), "r"(a[3]), "r"(b[0]), "r"(b[1]));
}
__device__ __forceinline__ void cp16(void* smem, const void* gmem) {
    uint32_t s = (uint32_t)__cvta_generic_to_shared(smem);
    asm volatile("cp.async.cg.shared.global [%0], [%1], 16;" :: "r"(s), "l"(gmem));
}
#define CP_COMMIT() asm volatile("cp.async.commit_group;")
#define CP_WAIT(n)  asm volatile("cp.async.wait_group %0;" :: "n"(n))

#define PADA 72    // As row stride (bf16): 144B, +16B shift per row -> conflict-free ldsm
#define PADB 136   // Bs row stride (bf16): 272B
// 2 stages: AsH 2*128*72*2=36864 ; AsL same ; BsH 2*64*136*2=34816 ; BsL same
#define SM_ASH 0
#define SM_ASL 36864
#define SM_BSH 73728
#define SM_BSL 108544
#define SM_TOTAL 143360

__global__ void __launch_bounds__(256, 1)
gemm_tc(const __nv_bfloat16* __restrict__ Ahg, const __nv_bfloat16* __restrict__ Alg,
        const __nv_bfloat16* __restrict__ Bhg, const __nv_bfloat16* __restrict__ Blg,
        const float* __restrict__ bias, float* __restrict__ C,
        __nv_bfloat16* __restrict__ Ch, __nv_bfloat16* __restrict__ Cl,
        int M, int N, int lda, int ldb, int Kext, int mode) {
    extern __shared__ char smraw[];
    __nv_bfloat16* AsH = (__nv_bfloat16*)(smraw + SM_ASH);
    __nv_bfloat16* AsL = (__nv_bfloat16*)(smraw + SM_ASL);
    __nv_bfloat16* BsH = (__nv_bfloat16*)(smraw + SM_BSH);
    __nv_bfloat16* BsL = (__nv_bfloat16*)(smraw + SM_BSL);

    int tid = threadIdx.x;
    int wid = tid >> 5, lane = tid & 31;
    int m_w = (wid >> 1) * 32, n_w = (wid & 1) * 64;
    int row0 = blockIdx.y * 128, col0 = blockIdx.x * 128;

    float acc[2][8][4];
#pragma unroll
    for (int i = 0; i < 2; i++)
#pragma unroll
        for (int j = 0; j < 8; j++)
#pragma unroll
            for (int q = 0; q < 4; q++) acc[i][j][q] = 0.f;

    int a_row = tid >> 1, a_colb = (tid & 1) * 32;   // A: 128 rows, 2 thr/row, 4 cp each
    int b_row = tid >> 2, b_colb = (tid & 3) * 32;   // B: 64 rows, 4 thr/row, 4 cp each

    auto loadStage = [&](int stage, int buf) {
        int k0 = stage * 64;
        const __nv_bfloat16* aH = Ahg + (size_t)(row0 + a_row) * lda + k0 + a_colb;
        const __nv_bfloat16* aL = Alg + (size_t)(row0 + a_row) * lda + k0 + a_colb;
        int sa = (buf * 128 + a_row) * PADA + a_colb;
        const __nv_bfloat16* bH = Bhg + (size_t)(k0 + b_row) * ldb + col0 + b_colb;
        const __nv_bfloat16* bL = Blg + (size_t)(k0 + b_row) * ldb + col0 + b_colb;
        int sb = (buf * 64 + b_row) * PADB + b_colb;
#pragma unroll
        for (int i = 0; i < 4; i++) {
            cp16(AsH + sa + i * 8, aH + i * 8);
            cp16(AsL + sa + i * 8, aL + i * 8);
            cp16(BsH + sb + i * 8, bH + i * 8);
            cp16(BsL + sb + i * 8, bL + i * 8);
        }
        CP_COMMIT();
    };

    auto compute = [&](int buf) {
#pragma unroll
        for (int kk = 0; kk < 64; kk += 16) {
            uint32_t Ahf[2][4], Alf[2][4], Bhf[8][2], Blf[8][2];
#pragma unroll
            for (int i = 0; i < 2; i++) {
                int idx = (buf * 128 + m_w + i * 16 + (lane & 15)) * PADA + kk + (lane >> 4) * 8;
                ldsm_x4(Ahf[i], AsH + idx);
                ldsm_x4(Alf[i], AsL + idx);
            }
#pragma unroll
            for (int p = 0; p < 4; p++) {
                int idx = (buf * 64 + kk + (lane & 15)) * PADB + n_w + p * 16 + (lane >> 4) * 8;
                uint32_t r[4];
                ldsm_x4_t(r, BsH + idx);
                Bhf[2 * p][0] = r[0]; Bhf[2 * p][1] = r[1];
                Bhf[2 * p + 1][0] = r[2]; Bhf[2 * p + 1][1] = r[3];
                ldsm_x4_t(r, BsL + idx);
                Blf[2 * p][0] = r[0]; Blf[2 * p][1] = r[1];
                Blf[2 * p + 1][0] = r[2]; Blf[2 * p + 1][1] = r[3];
            }
#pragma unroll
            for (int i = 0; i < 2; i++)
#pragma unroll
                for (int j = 0; j < 8; j++) {
                    mma16816(acc[i][j], Ahf[i], Bhf[j]);
                    mma16816(acc[i][j], Alf[i], Bhf[j]);
                    mma16816(acc[i][j], Ahf[i], Blf[j]);
                }
        }
    };

    int nsteps = Kext >> 6;
    loadStage(0, 0);
    for (int s = 0; s < nsteps; s++) {
        CP_WAIT(0);
        __syncthreads();
        if (s + 1 < nsteps) loadStage(s + 1, (s + 1) & 1);
        compute(s & 1);
    }

    // epilogue
    int g = lane >> 2, tg = lane & 3;
#pragma unroll
    for (int i = 0; i < 2; i++) {
#pragma unroll
        for (int j = 0; j < 8; j++) {
            int cc = col0 + n_w + j * 8 + tg * 2;
            float b0 = 0.f, b1 = 0.f;
            if (mode != 2) { b0 = bias[cc]; b1 = bias[cc + 1]; }
#pragma unroll
            for (int half = 0; half < 2; half++) {
                int r = row0 + m_w + i * 16 + g + half * 8;
                float v0 = acc[i][j][half * 2 + 0] + b0;
                float v1 = acc[i][j][half * 2 + 1] + b1;
                if (mode == 1) {
                    v0 = 0.5f * v0 * (1.f + erff(v0 * 0.7071067811865475f));
                    v1 = 0.5f * v1 * (1.f + erff(v1 * 0.7071067811865475f));
                    __nv_bfloat16 h0, l0, h1, l1;
                    split_bf16(v0, h0, l0);
                    split_bf16(v1, h1, l1);
                    *(__nv_bfloat162*)(Ch + (size_t)r * N + cc) = __nv_bfloat162(h0, h1);
                    *(__nv_bfloat162*)(Cl + (size_t)r * N + cc) = __nv_bfloat162(l0, l1);
                } else {
                    *(float2*)(C + (size_t)r * N + cc) = make_float2(v0, v1);
                }
            }
        }
    }
}

// -------------------- reduce split-K partials for output GEMM --------------------
__global__ void wout_reduce(const float* __restrict__ bias, float* __restrict__ out) {
    int i = blockIdx.x * blockDim.x + threadIdx.x;   // float4 index
    float4 a = ((const float4*)g_part)[i];
    float4 b = ((const float4*)(g_part + (size_t)NTOK * VOCABv))[i];
    int col = (i * 4) & (VOCABv - 1);
    float4 o;
    o.x = a.x + b.x + bias[col + 0];
    o.y = a.y + b.y + bias[col + 1];
    o.z = a.z + b.z + bias[col + 2];
    o.w = a.w + b.w + bias[col + 3];
    ((float4*)out)[i] = o;
}

// -------------------- FAVOR+ feature map (smem-tiled; reads g_qkv) --------------------
__global__ void __launch_bounds__(128)
favor_feat(const float* __restrict__ rfs) {
    int tile = blockIdx.x, h = blockIdx.y;
    __shared__ float rf[64][64];
    __shared__ float sq[32][68], sk[32][68];
    int tid = threadIdx.x;
    const float* rfh = rfs + h * 4096;
    for (int i = tid; i < 4096; i += 128) rf[i >> 6][i & 63] = rfh[i];
    const float sc = 0.3535533905932738f;
    for (int i = tid; i < 2048; i += 128) {
        int tl = i >> 6, d = i & 63;
        size_t gq = (size_t)(tile * 32 + tl) * QKVN + h * HDv + d;
        sq[tl][d] = g_qkv[gq] * sc;
        sk[tl][d] = g_qkv[gq + 512] * sc;
    }
    __syncthreads();
    int tl = tid >> 2, ms = (tid & 3) << 4;
    float s2q = 0.f, s2k = 0.f;
#pragma unroll 8
    for (int d = 0; d < 64; d++) {
        float a = sq[tl][d], b = sk[tl][d];
        s2q += a * a;
        s2k += b * b;
    }
    float dq[16], dk[16];
#pragma unroll
    for (int mi = 0; mi < 16; mi++) { dq[mi] = 0.f; dk[mi] = 0.f; }
#pragma unroll 4
    for (int d = 0; d < 64; d++) {
        float a = sq[tl][d], b = sk[tl][d];
#pragma unroll
        for (int m4 = 0; m4 < 4; m4++) {
            float4 rv = *(const float4*)&rf[d][ms + m4 * 4];
            float rr[4] = {rv.x, rv.y, rv.z, rv.w};
#pragma unroll
            for (int q = 0; q < 4; q++) {
                dq[m4 * 4 + q] += a * rr[q];
                dk[m4 * 4 + q] += b * rr[q];
            }
        }
    }
    int base = (tile * 32 + tl) * Dv + h * HDv + ms;
#pragma unroll
    for (int mi = 0; mi < 16; mi++) {
        g_qf[base + mi] = expf(dq[mi] - 0.5f * s2q);
        g_kf[base + mi] = expf(dk[mi] - 0.5f * s2k);
    }
}

// -------------------- phase 1: per-chunk sums (double-buffered, 1 sync/iter) ------
__global__ void __launch_bounds__(64)
attn_chunk() {
    int c = blockIdx.x, bh = blockIdx.y;
    int b = bh / Hv, h = bh % Hv;
    int d = threadIdx.x;
    float S[64];
#pragma unroll
    for (int m = 0; m < 64; m++) S[m] = 0.f;
    float z = 0.f;
    __shared__ float skb[2][64];
    int t0 = c * CHUNK;
    skb[0][d] = g_kf[(b * Tv + t0) * Dv + h * HDv + d];
    __syncthreads();
    int p = 0;
    for (int t = t0; t < t0 + CHUNK; t++) {
        size_t vbase = (size_t)(b * Tv + t) * QKVN + 1024 + h * HDv;
        float vd = g_qkv[vbase + d];
        z += skb[p][d];
#pragma unroll
        for (int m = 0; m < 64; m++) S[m] += skb[p][m] * vd;
        if (t + 1 < t0 + CHUNK)
            skb[p ^ 1][d] = g_kf[(b * Tv + t + 1) * Dv + h * HDv + d];
        __syncthreads();
        p ^= 1;
    }
    int sb = (bh * NCHUNK + c) * 4096;
#pragma unroll
    for (int m = 0; m < 64; m++) g_S[sb + m * 64 + d] = S[m];
    g_z[(bh * NCHUNK + c) * 64 + d] = z;
}

// -------------------- phase 2: exclusive scans over chunks --------------------
__global__ void __launch_bounds__(64)
attn_scan_S() {
    int bh = blockIdx.x >> 6, m = blockIdx.x & 63, d = threadIdx.x;
    float v[NCHUNK];
#pragma unroll
    for (int c = 0; c < NCHUNK; c++)
        v[c] = g_S[((bh * NCHUNK + c) << 12) + m * 64 + d];
    float acc = 0.f;
#pragma unroll
    for (int c = 0; c < NCHUNK; c++) {
        g_S[((bh * NCHUNK + c) << 12) + m * 64 + d] = acc;
        acc += v[c];
    }
}
__global__ void __launch_bounds__(64)
attn_scan_z() {
    int bh = blockIdx.x, d = threadIdx.x;
    float v[NCHUNK];
#pragma unroll
    for (int c = 0; c < NCHUNK; c++) v[c] = g_z[(bh * NCHUNK + c) * 64 + d];
    float acc = 0.f;
#pragma unroll
    for (int c = 0; c < NCHUNK; c++) {
        g_z[(bh * NCHUNK + c) * 64 + d] = acc;
        acc += v[c];
    }
}

// -------------------- phase 3: replay + output (1 sync/iter) --------------------
__global__ void __launch_bounds__(64)
attn_apply() {
    int c = blockIdx.x, bh = blockIdx.y;
    int b = bh / Hv, h = bh % Hv;
    int d = threadIdx.x;
    int lane = d & 31, w = d >> 5;
    float S[64];
    int sb = (bh * NCHUNK + c) * 4096;
#pragma unroll
    for (int m = 0; m < 64; m++) S[m] = g_S[sb + m * 64 + d];
    float z = g_z[(bh * NCHUNK + c) * 64 + d];
    __shared__ float skb[2][64], sqb[2][64], sred[2][2];
    int t0 = c * CHUNK;
    {
        int base = (b * Tv + t0) * Dv + h * HDv;
        skb[0][d] = g_kf[base + d];
        sqb[0][d] = g_qf[base + d];
    }
    __syncthreads();
    int p = 0;
    for (int t = t0; t < t0 + CHUNK; t++) {
        z += skb[p][d];
        float pd = sqb[p][d] * z;
#pragma unroll
        for (int off = 16; off; off >>= 1) pd += __shfl_down_sync(0xffffffffu, pd, off);
        if (lane == 0) sred[p][w] = pd;
        size_t vbase = (size_t)(b * Tv + t) * QKVN + 1024 + h * HDv;
        float vd = g_qkv[vbase + d];
        float num = 0.f;
#pragma unroll
        for (int m = 0; m < 64; m++) {
            S[m] += skb[p][m] * vd;
            num += sqb[p][m] * S[m];
        }
        if (t + 1 < t0 + CHUNK) {
            int nbase = (b * Tv + t + 1) * Dv + h * HDv;
            skb[p ^ 1][d] = g_kf[nbase + d];
            sqb[p ^ 1][d] = g_qf[nbase + d];
        }
        __syncthreads();
        float den = sred[p][0] + sred[p][1];
        g_a[(b * Tv + t) * Dv + h * HDv + d] = num / (den + 1e-16f);
        p ^= 1;
    }
}

// -------------------- LayerNorm + residual add (+ bf16 hi/lo of new x) ----------
__global__ void __launch_bounds__(128)
ln_add(const float* __restrict__ a, const float* __restrict__ g,
       const float* __restrict__ bl, float* __restrict__ x) {
    int n = blockIdx.x, tid = threadIdx.x;
    int lane = tid & 31, w = tid >> 5;
    const float* ar = a + (size_t)n * Dv;
    float v[4];
    float s = 0.f, s2 = 0.f;
#pragma unroll
    for (int i = 0; i < 4; i++) {
        float t = ar[tid + i * 128];
        v[i] = t;
        s += t;
        s2 += t * t;
    }
    __shared__ float sh[8];
#pragma unroll
    for (int off = 16; off; off >>= 1) {
        s += __shfl_down_sync(0xffffffffu, s, off);
        s2 += __shfl_down_sync(0xffffffffu, s2, off);
    }
    if (lane == 0) { sh[w] = s; sh[4 + w] = s2; }
    __syncthreads();
    float S = sh[0] + sh[1] + sh[2] + sh[3];
    float S2 = sh[4] + sh[5] + sh[6] + sh[7];
    float mu = S * (1.f / Dv);
    float var = S2 * (1.f / Dv) - mu * mu;
    float rs = rsqrtf(var + 1e-5f);
#pragma unroll
    for (int i = 0; i < 4; i++) {
        int j = tid + i * 128;
        size_t idx = (size_t)n * Dv + j;
        float nv = x[idx] + (v[i] - mu) * rs * g[j] + bl[j];
        x[idx] = nv;
        __nv_bfloat16 h, l;
        split_bf16(nv, h, l);
        g_xh[idx] = h;
        g_xl[idx] = l;
    }
}

// -------------------- host driver --------------------
extern "C" void kernel_launch(void* const* d_in, const int* in_sizes, int n_in,
                              void* d_out, int out_size) {
    const int*   tokens = (const int*)d_in[0];
    const float* emb    = (const float*)d_in[1];
    const float* Wq     = (const float*)d_in[2];
    const float* bq     = (const float*)d_in[3];
    const float* Wk     = (const float*)d_in[4];
    const float* bk     = (const float*)d_in[5];
    const float* Wv     = (const float*)d_in[6];
    const float* bvp    = (const float*)d_in[7];
    const float* rfs    = (const float*)d_in[8];
    const float* ln1g   = (const float*)d_in[9];
    const float* ln1b   = (const float*)d_in[10];
    const float* ln2g   = (const float*)d_in[11];
    const float* ln2b   = (const float*)d_in[12];
    const float* WU     = (const float*)d_in[13];
    const float* bU     = (const float*)d_in[14];
    const float* WV     = (const float*)d_in[15];
    const float* bV     = (const float*)d_in[16];
    const float* Wout   = (const float*)d_in[17];
    const float* bout   = (const float*)d_in[18];
    float* out = (float*)d_out;

    static float *px = nullptr, *pa, *pqkv, *pbqkv, *ppart;
    static __nv_bfloat16 *pxh, *pxl, *phh, *phl, *pwh, *pwl;
    if (!px) {
        cudaGetSymbolAddress((void**)&px, g_x);
        cudaGetSymbolAddress((void**)&pa, g_a);
        cudaGetSymbolAddress((void**)&pqkv, g_qkv);
        cudaGetSymbolAddress((void**)&pbqkv, g_bqkv);
        cudaGetSymbolAddress((void**)&ppart, g_part);
        cudaGetSymbolAddress((void**)&pxh, g_xh);
        cudaGetSymbolAddress((void**)&pxl, g_xl);
        cudaGetSymbolAddress((void**)&phh, g_hh);
        cudaGetSymbolAddress((void**)&phl, g_hl);
        cudaGetSymbolAddress((void**)&pwh, g_wh);
        cudaGetSymbolAddress((void**)&pwl, g_wl);
        cudaFuncSetAttribute(gemm_tc, cudaFuncAttributeMaxDynamicSharedMemorySize, SM_TOTAL);
    }

    // weights -> bf16 hi/lo ([K,N] row-major)
    int nq4 = Lv * Dv * Dv / 4;
    convw_qkv<<<(nq4 + 255) / 256, 256>>>(Wq, pwh + OFF_QKV, pwl + OFF_QKV, 0);
    convw_qkv<<<(nq4 + 255) / 256, 256>>>(Wk, pwh + OFF_QKV, pwl + OFF_QKV, 512);
    convw_qkv<<<(nq4 + 255) / 256, 256>>>(Wv, pwh + OFF_QKV, pwl + OFF_QKV, 1024);
    int nu4 = Lv * Dv * FFNv / 4;
    convw4<<<(nu4 + 255) / 256, 256>>>(WU, pwh + OFF_WU, pwl + OFF_WU, nu4);
    convw4<<<(nu4 + 255) / 256, 256>>>(WV, pwh + OFF_WD, pwl + OFF_WD, nu4);
    int no4 = Dv * VOCABv / 4;
    convw4<<<(no4 + 255) / 256, 256>>>(Wout, pwh + OFF_WO, pwl + OFF_WO, no4);
    bias_qkv<<<(Lv * QKVN + 255) / 256, 256>>>(bq, bk, bvp);

    embed_kernel<<<(NTOK * Dv + 255) / 256, 256>>>(tokens, emb);

    for (int l = 0; l < Lv; l++) {
        gemm_tc<<<dim3(QKVN / 128, NTOK / 128), 256, SM_TOTAL>>>(
            pxh, pxl, pwh + OFF_QKV + (size_t)l * Dv * QKVN,
            pwl + OFF_QKV + (size_t)l * Dv * QKVN, pbqkv + l * QKVN,
            pqkv, nullptr, nullptr, NTOK, QKVN, Dv, QKVN, Dv, 0);

        favor_feat<<<dim3(NTOK / 32, Hv), 128>>>(rfs + (size_t)l * Hv * HDv * HDv);
        attn_chunk<<<dim3(NCHUNK, Bv * Hv), 64>>>();
        attn_scan_S<<<Bv * Hv * HDv, 64>>>();
        attn_scan_z<<<Bv * Hv, 64>>>();
        attn_apply<<<dim3(NCHUNK, Bv * Hv), 64>>>();

        ln_add<<<NTOK, 128>>>(pa, ln1g + l * Dv, ln1b + l * Dv, px);

        gemm_tc<<<dim3(FFNv / 128, NTOK / 128), 256, SM_TOTAL>>>(
            pxh, pxl, pwh + OFF_WU + (size_t)l * Dv * FFNv,
            pwl + OFF_WU + (size_t)l * Dv * FFNv, bU + l * FFNv,
            nullptr, phh, phl, NTOK, FFNv, Dv, FFNv, Dv, 1);
        gemm_tc<<<dim3(Dv / 128, NTOK / 128), 256, SM_TOTAL>>>(
            phh, phl, pwh + OFF_WD + (size_t)l * FFNv * Dv,
            pwl + OFF_WD + (size_t)l * FFNv * Dv, bV + l * Dv,
            pa, nullptr, nullptr, NTOK, Dv, FFNv, Dv, FFNv, 0);

        ln_add<<<NTOK, 128>>>(pa, ln2g + l * Dv, ln2b + l * Dv, px);
    }

    // output GEMM split-K=2: partials, then reduce + bias
    for (int sp = 0; sp < 2; sp++) {
        int koff = sp * 256;
        gemm_tc<<<dim3(VOCABv / 128, NTOK / 128), 256, SM_TOTAL>>>(
            pxh + koff, pxl + koff,
            pwh + OFF_WO + (size_t)koff * VOCABv, pwl + OFF_WO + (size_t)koff * VOCABv,
            nullptr, ppart + (size_t)sp * NTOK * VOCABv, nullptr, nullptr,
            NTOK, VOCABv, Dv, VOCABv, 256, 2);
    }
    wout_reduce<<<NTOK * VOCABv / 4 / 256, 256>>>(bout, out);
}

// round 7
// speedup vs baseline: 1.3059x; 1.3059x over previous
#include <cuda_runtime.h>
#include <cuda_fp16.h>
#include <math.h>
#include <stdint.h>

// Problem constants
#define Bv      2
#define Tv      2048
#define NTOK    (Bv * Tv)      // 4096
#define Dv      512
#define Hv      8
#define HDv     64
#define FFNv    2048
#define VOCABv  256
#define Lv      2
#define CHUNK   32
#define NCHUNK  (Tv / CHUNK)   // 64
#define QKVN    1536

// weight region offsets (elements) in the fp16 weight pool ([K,N] row-major)
#define OFF_QKV 0
#define OFF_WU  (OFF_QKV + Lv * Dv * QKVN)
#define OFF_WD  (OFF_WU + Lv * Dv * FFNv)
#define OFF_WO  (OFF_WD + Lv * FFNv * Dv)
#define W_TOTAL (OFF_WO + Dv * VOCABv)

// -------------------- scratch (device globals; no allocs) --------------------
__device__ float g_x[NTOK * Dv];
__device__ float g_a[NTOK * Dv];
__device__ float g_qkv[NTOK * QKVN];
__device__ float g_qf[NTOK * Dv];
__device__ float g_kf[NTOK * Dv];
__device__ float g_S[Bv * Hv * NCHUNK * HDv * HDv];
__device__ float g_z[Bv * Hv * NCHUNK * HDv];
__device__ float g_bqkv[Lv * QKVN];
__device__ float g_part[2 * NTOK * VOCABv];
__device__ __half g_xh[NTOK * Dv];
__device__ __half g_xl[NTOK * Dv];
__device__ __half g_hh[NTOK * FFNv];
__device__ __half g_hl[NTOK * FFNv];
__device__ __half g_wh[W_TOTAL];

__device__ __forceinline__ void split_fp16(float v, __half& h, __half& l) {
    h = __float2half_rn(v);
    l = __float2half_rn(v - __half2float(h));
}

// -------------------- weight fp32 -> fp16 (vectorized) --------------------
__global__ void convw4(const float* __restrict__ src, __half* __restrict__ dh, int n4) {
    int i = blockIdx.x * blockDim.x + threadIdx.x;
    if (i >= n4) return;
    float4 v = *(const float4*)(src + 4 * i);
    __half2 a = __half2(__float2half_rn(v.x), __float2half_rn(v.y));
    __half2 b = __half2(__float2half_rn(v.z), __float2half_rn(v.w));
    ((__half2*)(dh + 4 * i))[0] = a;
    ((__half2*)(dh + 4 * i))[1] = b;
}

// QKV weight: src [L*512, 512] row-major -> dst rows stride 1536 at column colofs
__global__ void convw_qkv(const float* __restrict__ src, __half* __restrict__ dh, int colofs) {
    int i = blockIdx.x * blockDim.x + threadIdx.x;
    if (i >= Lv * Dv * Dv / 4) return;
    int e = 4 * i;
    int k = e >> 9, col = e & 511;
    float4 v = *(const float4*)(src + e);
    size_t dst = (size_t)k * QKVN + colofs + col;
    ((__half2*)(dh + dst))[0] = __half2(__float2half_rn(v.x), __float2half_rn(v.y));
    ((__half2*)(dh + dst))[1] = __half2(__float2half_rn(v.z), __float2half_rn(v.w));
}

__global__ void bias_qkv(const float* __restrict__ bq, const float* __restrict__ bk,
                         const float* __restrict__ bvp) {
    int idx = blockIdx.x * blockDim.x + threadIdx.x;
    if (idx >= Lv * QKVN) return;
    int l = idx / QKVN, c = idx % QKVN;
    float v;
    if (c < 512) v = bq[l * Dv + c];
    else if (c < 1024) v = bk[l * Dv + c - 512];
    else v = bvp[l * Dv + c - 1024];
    g_bqkv[idx] = v;
}

// -------------------- embedding + sinusoidal positions --------------------
__global__ void embed_kernel(const int* __restrict__ tokens,
                             const float* __restrict__ emb) {
    int idx = blockIdx.x * blockDim.x + threadIdx.x;
    if (idx >= NTOK * Dv) return;
    int n = idx >> 9;
    int j = idx & 511;
    int t = n & (Tv - 1);
    float val;
    const float c = 9.210340371976184f / 256.f;
    if (j < 256) {
        int tok = tokens[n];
        val = emb[tok * 256 + j];
    } else if (j < 384) {
        int i = j - 256;
        val = sinf((float)t * expf(-(2.f * (float)i) * c));
    } else {
        int i = j - 384;
        val = cosf((float)t * expf(-(2.f * (float)i) * c));
    }
    g_x[idx] = val;
    __half h, l;
    split_fp16(val, h, l);
    g_xh[idx] = h;
    g_xl[idx] = l;
}

// -------------------- tensor-core GEMM, fp16 2-term, BK=64, 2-stage cp.async ----
// C = A@B + bias; A[M,K] fp16 hi/lo (stride lda), B[K,N] fp16 (stride ldb).
// A*B ~= AhB + AlB (weights 1-term fp16; activation residual covered by Al).
// BM=BN=128, 256 threads (8 warps, 32x64 warp tiles), 2 CTAs/SM target.
// mode 0: fp32 out + bias. mode 1: gelu -> fp16 hi/lo. mode 2: raw fp32 (no bias).

__device__ __forceinline__ void ldsm_x4(uint32_t* r, const void* p) {
    uint32_t a = (uint32_t)__cvta_generic_to_shared(p);
    asm volatile("ldmatrix.sync.aligned.m8n8.x4.shared.b16 {%0,%1,%2,%3},[%4];"
        : "=r"(r[0]), "=r"(r[1]), "=r"(r[2]), "=r"(r[3]) : "r"(a));
}
__device__ __forceinline__ void ldsm_x4_t(uint32_t* r, const void* p) {
    uint32_t a = (uint32_t)__cvta_generic_to_shared(p);
    asm volatile("ldmatrix.sync.aligned.m8n8.x4.trans.shared.b16 {%0,%1,%2,%3},[%4];"
        : "=r"(r[0]), "=r"(r[1]), "=r"(r[2]), "=r"(r[3]) : "r"(a));
}
__device__ __forceinline__ void mma16816(float* c, const uint32_t* a, const uint32_t* b) {
    asm volatile("mma.sync.aligned.m16n8k16.row.col.f32.f16.f16.f32 "
        "{%0,%1,%2,%3},{%4,%5,%6,%7},{%8,%9},{%0,%1,%2,%3};"
        : "+f"(c[0]), "+f"(c[1]), "+f"(c[2]), "+f"(c[3])
        : "r"(a[0]), "r"(a[1]), "r"(a[2]), "r"(a[3]), "r"(b[0]), "r"(b[1]));
}
__device__ __forceinline__ void cp16(void* smem, const void* gmem) {
    uint32_t s = (uint32_t)__cvta_generic_to_shared(smem);
    asm volatile("cp.async.cg.shared.global [%0], [%1], 16;" :: "r"(s), "l"(gmem));
}
#define CP_COMMIT() asm volatile("cp.async.commit_group;")
#define CP_WAIT(n)  asm volatile("cp.async.wait_group %0;" :: "n"(n))

#define PADA 72    // As row stride (fp16): 144B
#define PADB 136   // Bs row stride (fp16): 272B
// 2 stages: AsH 2*128*72*2=36864 ; AsL same ; BsH 2*64*136*2=34816
#define SM_ASH 0
#define SM_ASL 36864
#define SM_BSH 73728
#define SM_TOTAL 108544

__global__ void __launch_bounds__(256, 2)
gemm_tc(const __half* __restrict__ Ahg, const __half* __restrict__ Alg,
        const __half* __restrict__ Bhg,
        const float* __restrict__ bias, float* __restrict__ C,
        __half* __restrict__ Ch, __half* __restrict__ Cl,
        int M, int N, int lda, int ldb, int Kext, int mode) {
    extern __shared__ char smraw[];
    __half* AsH = (__half*)(smraw + SM_ASH);
    __half* AsL = (__half*)(smraw + SM_ASL);
    __half* BsH = (__half*)(smraw + SM_BSH);

    int tid = threadIdx.x;
    int wid = tid >> 5, lane = tid & 31;
    int m_w = (wid >> 1) * 32, n_w = (wid & 1) * 64;
    int row0 = blockIdx.y * 128, col0 = blockIdx.x * 128;

    float acc[2][8][4];
#pragma unroll
    for (int i = 0; i < 2; i++)
#pragma unroll
        for (int j = 0; j < 8; j++)
#pragma unroll
            for (int q = 0; q < 4; q++) acc[i][j][q] = 0.f;

    int a_row = tid >> 1, a_colb = (tid & 1) * 32;   // A: 128 rows, 2 thr/row
    int b_row = tid >> 2, b_colb = (tid & 3) * 32;   // B: 64 rows, 4 thr/row

    auto loadStage = [&](int stage, int buf) {
        int k0 = stage * 64;
        const __half* aH = Ahg + (size_t)(row0 + a_row) * lda + k0 + a_colb;
        const __half* aL = Alg + (size_t)(row0 + a_row) * lda + k0 + a_colb;
        int sa = (buf * 128 + a_row) * PADA + a_colb;
        const __half* bH = Bhg + (size_t)(k0 + b_row) * ldb + col0 + b_colb;
        int sb = (buf * 64 + b_row) * PADB + b_colb;
#pragma unroll
        for (int i = 0; i < 4; i++) {
            cp16(AsH + sa + i * 8, aH + i * 8);
            cp16(AsL + sa + i * 8, aL + i * 8);
            cp16(BsH + sb + i * 8, bH + i * 8);
        }
        CP_COMMIT();
    };

    auto compute = [&](int buf) {
#pragma unroll
        for (int kk = 0; kk < 64; kk += 16) {
            uint32_t Ahf[2][4], Alf[2][4], Bhf[8][2];
#pragma unroll
            for (int i = 0; i < 2; i++) {
                int idx = (buf * 128 + m_w + i * 16 + (lane & 15)) * PADA + kk + (lane >> 4) * 8;
                ldsm_x4(Ahf[i], AsH + idx);
                ldsm_x4(Alf[i], AsL + idx);
            }
#pragma unroll
            for (int p = 0; p < 4; p++) {
                int idx = (buf * 64 + kk + (lane & 15)) * PADB + n_w + p * 16 + (lane >> 4) * 8;
                uint32_t r[4];
                ldsm_x4_t(r, BsH + idx);
                Bhf[2 * p][0] = r[0]; Bhf[2 * p][1] = r[1];
                Bhf[2 * p + 1][0] = r[2]; Bhf[2 * p + 1][1] = r[3];
            }
#pragma unroll
            for (int i = 0; i < 2; i++)
#pragma unroll
                for (int j = 0; j < 8; j++) {
                    mma16816(acc[i][j], Ahf[i], Bhf[j]);
                    mma16816(acc[i][j], Alf[i], Bhf[j]);
                }
        }
    };

    int nsteps = Kext >> 6;
    loadStage(0, 0);
    for (int s = 0; s < nsteps; s++) {
        CP_WAIT(0);
        __syncthreads();
        if (s + 1 < nsteps) loadStage(s + 1, (s + 1) & 1);
        compute(s & 1);
    }

    // epilogue
    int g = lane >> 2, tg = lane & 3;
#pragma unroll
    for (int i = 0; i < 2; i++) {
#pragma unroll
        for (int j = 0; j < 8; j++) {
            int cc = col0 + n_w + j * 8 + tg * 2;
            float b0 = 0.f, b1 = 0.f;
            if (mode != 2) { b0 = bias[cc]; b1 = bias[cc + 1]; }
#pragma unroll
            for (int half = 0; half < 2; half++) {
                int r = row0 + m_w + i * 16 + g + half * 8;
                float v0 = acc[i][j][half * 2 + 0] + b0;
                float v1 = acc[i][j][half * 2 + 1] + b1;
                if (mode == 1) {
                    v0 = 0.5f * v0 * (1.f + erff(v0 * 0.7071067811865475f));
                    v1 = 0.5f * v1 * (1.f + erff(v1 * 0.7071067811865475f));
                    __half h0, l0, h1, l1;
                    split_fp16(v0, h0, l0);
                    split_fp16(v1, h1, l1);
                    *(__half2*)(Ch + (size_t)r * N + cc) = __half2(h0, h1);
                    *(__half2*)(Cl + (size_t)r * N + cc) = __half2(l0, l1);
                } else {
                    *(float2*)(C + (size_t)r * N + cc) = make_float2(v0, v1);
                }
            }
        }
    }
}

// -------------------- reduce split-K partials for output GEMM --------------------
__global__ void wout_reduce(const float* __restrict__ bias, float* __restrict__ out) {
    int i = blockIdx.x * blockDim.x + threadIdx.x;   // float4 index
    float4 a = ((const float4*)g_part)[i];
    float4 b = ((const float4*)(g_part + (size_t)NTOK * VOCABv))[i];
    int col = (i * 4) & (VOCABv - 1);
    float4 o;
    o.x = a.x + b.x + bias[col + 0];
    o.y = a.y + b.y + bias[col + 1];
    o.z = a.z + b.z + bias[col + 2];
    o.w = a.w + b.w + bias[col + 3];
    ((float4*)out)[i] = o;
}

// -------------------- FAVOR+ feature map (smem-tiled; reads g_qkv) --------------------
__global__ void __launch_bounds__(128)
favor_feat(const float* __restrict__ rfs) {
    int tile = blockIdx.x, h = blockIdx.y;
    __shared__ float rf[64][64];
    __shared__ float sq[32][68], sk[32][68];
    int tid = threadIdx.x;
    const float* rfh = rfs + h * 4096;
    for (int i = tid; i < 4096; i += 128) rf[i >> 6][i & 63] = rfh[i];
    const float sc = 0.3535533905932738f;
    for (int i = tid; i < 2048; i += 128) {
        int tl = i >> 6, d = i & 63;
        size_t gq = (size_t)(tile * 32 + tl) * QKVN + h * HDv + d;
        sq[tl][d] = g_qkv[gq] * sc;
        sk[tl][d] = g_qkv[gq + 512] * sc;
    }
    __syncthreads();
    int tl = tid >> 2, ms = (tid & 3) << 4;
    float s2q = 0.f, s2k = 0.f;
#pragma unroll 8
    for (int d = 0; d < 64; d++) {
        float a = sq[tl][d], b = sk[tl][d];
        s2q += a * a;
        s2k += b * b;
    }
    float dq[16], dk[16];
#pragma unroll
    for (int mi = 0; mi < 16; mi++) { dq[mi] = 0.f; dk[mi] = 0.f; }
#pragma unroll 4
    for (int d = 0; d < 64; d++) {
        float a = sq[tl][d], b = sk[tl][d];
#pragma unroll
        for (int m4 = 0; m4 < 4; m4++) {
            float4 rv = *(const float4*)&rf[d][ms + m4 * 4];
            float rr[4] = {rv.x, rv.y, rv.z, rv.w};
#pragma unroll
            for (int q = 0; q < 4; q++) {
                dq[m4 * 4 + q] += a * rr[q];
                dk[m4 * 4 + q] += b * rr[q];
            }
        }
    }
    int base = (tile * 32 + tl) * Dv + h * HDv + ms;
#pragma unroll
    for (int mi = 0; mi < 16; mi++) {
        g_qf[base + mi] = expf(dq[mi] - 0.5f * s2q);
        g_kf[base + mi] = expf(dk[mi] - 0.5f * s2k);
    }
}

// -------------------- phase 1: per-chunk sums (double-buffered, 1 sync/iter) ------
__global__ void __launch_bounds__(64)
attn_chunk() {
    int c = blockIdx.x, bh = blockIdx.y;
    int b = bh / Hv, h = bh % Hv;
    int d = threadIdx.x;
    float S[64];
#pragma unroll
    for (int m = 0; m < 64; m++) S[m] = 0.f;
    float z = 0.f;
    __shared__ float skb[2][64];
    int t0 = c * CHUNK;
    skb[0][d] = g_kf[(b * Tv + t0) * Dv + h * HDv + d];
    __syncthreads();
    int p = 0;
    for (int t = t0; t < t0 + CHUNK; t++) {
        size_t vbase = (size_t)(b * Tv + t) * QKVN + 1024 + h * HDv;
        float vd = g_qkv[vbase + d];
        z += skb[p][d];
#pragma unroll
        for (int m = 0; m < 64; m++) S[m] += skb[p][m] * vd;
        if (t + 1 < t0 + CHUNK)
            skb[p ^ 1][d] = g_kf[(b * Tv + t + 1) * Dv + h * HDv + d];
        __syncthreads();
        p ^= 1;
    }
    int sb = (bh * NCHUNK + c) * 4096;
#pragma unroll
    for (int m = 0; m < 64; m++) g_S[sb + m * 64 + d] = S[m];
    g_z[(bh * NCHUNK + c) * 64 + d] = z;
}

// -------------------- phase 2: exclusive scans over chunks --------------------
__global__ void __launch_bounds__(64)
attn_scan_S() {
    int bh = blockIdx.x >> 6, m = blockIdx.x & 63, d = threadIdx.x;
    float v[NCHUNK];
#pragma unroll
    for (int c = 0; c < NCHUNK; c++)
        v[c] = g_S[((bh * NCHUNK + c) << 12) + m * 64 + d];
    float acc = 0.f;
#pragma unroll
    for (int c = 0; c < NCHUNK; c++) {
        g_S[((bh * NCHUNK + c) << 12) + m * 64 + d] = acc;
        acc += v[c];
    }
}
__global__ void __launch_bounds__(64)
attn_scan_z() {
    int bh = blockIdx.x, d = threadIdx.x;
    float v[NCHUNK];
#pragma unroll
    for (int c = 0; c < NCHUNK; c++) v[c] = g_z[(bh * NCHUNK + c) * 64 + d];
    float acc = 0.f;
#pragma unroll
    for (int c = 0; c < NCHUNK; c++) {
        g_z[(bh * NCHUNK + c) * 64 + d] = acc;
        acc += v[c];
    }
}

// -------------------- phase 3: replay + output (1 sync/iter) --------------------
__global__ void __launch_bounds__(64)
attn_apply() {
    int c = blockIdx.x, bh = blockIdx.y;
    int b = bh / Hv, h = bh % Hv;
    int d = threadIdx.x;
    int lane = d & 31, w = d >> 5;
    float S[64];
    int sb = (bh * NCHUNK + c) * 4096;
#pragma unroll
    for (int m = 0; m < 64; m++) S[m] = g_S[sb + m * 64 + d];
    float z = g_z[(bh * NCHUNK + c) * 64 + d];
    __shared__ float skb[2][64], sqb[2][64], sred[2][2];
    int t0 = c * CHUNK;
    {
        int base = (b * Tv + t0) * Dv + h * HDv;
        skb[0][d] = g_kf[base + d];
        sqb[0][d] = g_qf[base + d];
    }
    __syncthreads();
    int p = 0;
    for (int t = t0; t < t0 + CHUNK; t++) {
        z += skb[p][d];
        float pd = sqb[p][d] * z;
#pragma unroll
        for (int off = 16; off; off >>= 1) pd += __shfl_down_sync(0xffffffffu, pd, off);
        if (lane == 0) sred[p][w] = pd;
        size_t vbase = (size_t)(b * Tv + t) * QKVN + 1024 + h * HDv;
        float vd = g_qkv[vbase + d];
        float num = 0.f;
#pragma unroll
        for (int m = 0; m < 64; m++) {
            S[m] += skb[p][m] * vd;
            num += sqb[p][m] * S[m];
        }
        if (t + 1 < t0 + CHUNK) {
            int nbase = (b * Tv + t + 1) * Dv + h * HDv;
            skb[p ^ 1][d] = g_kf[nbase + d];
            sqb[p ^ 1][d] = g_qf[nbase + d];
        }
        __syncthreads();
        float den = sred[p][0] + sred[p][1];
        g_a[(b * Tv + t) * Dv + h * HDv + d] = num / (den + 1e-16f);
        p ^= 1;
    }
}

// -------------------- LayerNorm + residual add (+ fp16 hi/lo of new x) ----------
__global__ void __launch_bounds__(128)
ln_add(const float* __restrict__ a, const float* __restrict__ g,
       const float* __restrict__ bl, float* __restrict__ x) {
    int n = blockIdx.x, tid = threadIdx.x;
    int lane = tid & 31, w = tid >> 5;
    const float* ar = a + (size_t)n * Dv;
    float v[4];
    float s = 0.f, s2 = 0.f;
#pragma unroll
    for (int i = 0; i < 4; i++) {
        float t = ar[tid + i * 128];
        v[i] = t;
        s += t;
        s2 += t * t;
    }
    __shared__ float sh[8];
#pragma unroll
    for (int off = 16; off; off >>= 1) {
        s += __shfl_down_sync(0xffffffffu, s, off);
        s2 += __shfl_down_sync(0xffffffffu, s2, off);
    }
    if (lane == 0) { sh[w] = s; sh[4 + w] = s2; }
    __syncthreads();
    float S = sh[0] + sh[1] + sh[2] + sh[3];
    float S2 = sh[4] + sh[5] + sh[6] + sh[7];
    float mu = S * (1.f / Dv);
    float var = S2 * (1.f / Dv) - mu * mu;
    float rs = rsqrtf(var + 1e-5f);
#pragma unroll
    for (int i = 0; i < 4; i++) {
        int j = tid + i * 128;
        size_t idx = (size_t)n * Dv + j;
        float nv = x[idx] + (v[i] - mu) * rs * g[j] + bl[j];
        x[idx] = nv;
        __half h, l;
        split_fp16(nv, h, l);
        g_xh[idx] = h;
        g_xl[idx] = l;
    }
}

// -------------------- host driver --------------------
extern "C" void kernel_launch(void* const* d_in, const int* in_sizes, int n_in,
                              void* d_out, int out_size) {
    const int*   tokens = (const int*)d_in[0];
    const float* emb    = (const float*)d_in[1];
    const float* Wq     = (const float*)d_in[2];
    const float* bq     = (const float*)d_in[3];
    const float* Wk     = (const float*)d_in[4];
    const float* bk     = (const float*)d_in[5];
    const float* Wv     = (const float*)d_in[6];
    const float* bvp    = (const float*)d_in[7];
    const float* rfs    = (const float*)d_in[8];
    const float* ln1g   = (const float*)d_in[9];
    const float* ln1b   = (const float*)d_in[10];
    const float* ln2g   = (const float*)d_in[11];
    const float* ln2b   = (const float*)d_in[12];
    const float* WU     = (const float*)d_in[13];
    const float* bU     = (const float*)d_in[14];
    const float* WV     = (const float*)d_in[15];
    const float* bV     = (const float*)d_in[16];
    const float* Wout   = (const float*)d_in[17];
    const float* bout   = (const float*)d_in[18];
    float* out = (float*)d_out;

    static float *px = nullptr, *pa, *pqkv, *pbqkv, *ppart;
    static __half *pxh, *pxl, *phh, *phl, *pwh;
    if (!px) {
        cudaGetSymbolAddress((void**)&px, g_x);
        cudaGetSymbolAddress((void**)&pa, g_a);
        cudaGetSymbolAddress((void**)&pqkv, g_qkv);
        cudaGetSymbolAddress((void**)&pbqkv, g_bqkv);
        cudaGetSymbolAddress((void**)&ppart, g_part);
        cudaGetSymbolAddress((void**)&pxh, g_xh);
        cudaGetSymbolAddress((void**)&pxl, g_xl);
        cudaGetSymbolAddress((void**)&phh, g_hh);
        cudaGetSymbolAddress((void**)&phl, g_hl);
        cudaGetSymbolAddress((void**)&pwh, g_wh);
        cudaFuncSetAttribute(gemm_tc, cudaFuncAttributeMaxDynamicSharedMemorySize, SM_TOTAL);
    }

    // weights -> fp16 ([K,N] row-major)
    int nq4 = Lv * Dv * Dv / 4;
    convw_qkv<<<(nq4 + 255) / 256, 256>>>(Wq, pwh + OFF_QKV, 0);
    convw_qkv<<<(nq4 + 255) / 256, 256>>>(Wk, pwh + OFF_QKV, 512);
    convw_qkv<<<(nq4 + 255) / 256, 256>>>(Wv, pwh + OFF_QKV, 1024);
    int nu4 = Lv * Dv * FFNv / 4;
    convw4<<<(nu4 + 255) / 256, 256>>>(WU, pwh + OFF_WU, nu4);
    convw4<<<(nu4 + 255) / 256, 256>>>(WV, pwh + OFF_WD, nu4);
    int no4 = Dv * VOCABv / 4;
    convw4<<<(no4 + 255) / 256, 256>>>(Wout, pwh + OFF_WO, no4);
    bias_qkv<<<(Lv * QKVN + 255) / 256, 256>>>(bq, bk, bvp);

    embed_kernel<<<(NTOK * Dv + 255) / 256, 256>>>(tokens, emb);

    for (int l = 0; l < Lv; l++) {
        gemm_tc<<<dim3(QKVN / 128, NTOK / 128), 256, SM_TOTAL>>>(
            pxh, pxl, pwh + OFF_QKV + (size_t)l * Dv * QKVN, pbqkv + l * QKVN,
            pqkv, nullptr, nullptr, NTOK, QKVN, Dv, QKVN, Dv, 0);

        favor_feat<<<dim3(NTOK / 32, Hv), 128>>>(rfs + (size_t)l * Hv * HDv * HDv);
        attn_chunk<<<dim3(NCHUNK, Bv * Hv), 64>>>();
        attn_scan_S<<<Bv * Hv * HDv, 64>>>();
        attn_scan_z<<<Bv * Hv, 64>>>();
        attn_apply<<<dim3(NCHUNK, Bv * Hv), 64>>>();

        ln_add<<<NTOK, 128>>>(pa, ln1g + l * Dv, ln1b + l * Dv, px);

        gemm_tc<<<dim3(FFNv / 128, NTOK / 128), 256, SM_TOTAL>>>(
            pxh, pxl, pwh + OFF_WU + (size_t)l * Dv * FFNv, bU + l * FFNv,
            nullptr, phh, phl, NTOK, FFNv, Dv, FFNv, Dv, 1);
        gemm_tc<<<dim3(Dv / 128, NTOK / 128), 256, SM_TOTAL>>>(
            phh, phl, pwh + OFF_WD + (size_t)l * FFNv * Dv, bV + l * Dv,
            pa, nullptr, nullptr, NTOK, Dv, FFNv, Dv, FFNv, 0);

        ln_add<<<NTOK, 128>>>(pa, ln2g + l * Dv, ln2b + l * Dv, px);
    }

    // output GEMM split-K=2: partials, then reduce + bias
    for (int sp = 0; sp < 2; sp++) {
        int koff = sp * 256;
        gemm_tc<<<dim3(VOCABv / 128, NTOK / 128), 256, SM_TOTAL>>>(
            pxh + koff, pxl + koff,
            pwh + OFF_WO + (size_t)koff * VOCABv,
            nullptr, ppart + (size_t)sp * NTOK * VOCABv, nullptr, nullptr,
            NTOK, VOCABv, Dv, VOCABv, 256, 2);
    }
    wout_reduce<<<NTOK * VOCABv / 4 / 256, 256>>>(bout, out);
}

// round 8
// speedup vs baseline: 1.6624x; 1.2730x over previous
#include <cuda_runtime.h>
#include <cuda_fp16.h>
#include <math.h>
#include <stdint.h>

// Problem constants
#define Bv      2
#define Tv      2048
#define NTOK    (Bv * Tv)      // 4096
#define Dv      512
#define Hv      8
#define HDv     64
#define FFNv    2048
#define VOCABv  256
#define Lv      2
#define CHUNK   32
#define NCHUNK  (Tv / CHUNK)   // 64
#define QKVN    1536

// weight region offsets (elements) in the fp16 weight pool ([K,N] row-major)
#define OFF_QKV 0
#define OFF_WU  (OFF_QKV + Lv * Dv * QKVN)
#define OFF_WD  (OFF_WU + Lv * Dv * FFNv)
#define OFF_WO  (OFF_WD + Lv * FFNv * Dv)
#define W_TOTAL (OFF_WO + Dv * VOCABv)

// -------------------- scratch (device globals; no allocs) --------------------
__device__ float g_x[NTOK * Dv];
__device__ float g_a[NTOK * Dv];
__device__ float g_qkv[NTOK * QKVN];
__device__ float g_qf[NTOK * Dv];
__device__ float g_kf[NTOK * Dv];
__device__ float g_S[Bv * Hv * NCHUNK * HDv * HDv];
__device__ float g_z[Bv * Hv * NCHUNK * HDv];
__device__ float g_bqkv[Lv * QKVN];
__device__ float g_part[2 * NTOK * VOCABv];
__device__ __half g_xh[NTOK * Dv];
__device__ __half g_xl[NTOK * Dv];
__device__ __half g_hh[NTOK * FFNv];
__device__ __half g_wh[W_TOTAL];

__device__ __forceinline__ void split_fp16(float v, __half& h, __half& l) {
    h = __float2half_rn(v);
    l = __float2half_rn(v - __half2float(h));
}

// -------------------- weight fp32 -> fp16 (vectorized) --------------------
__global__ void convw4(const float* __restrict__ src, __half* __restrict__ dh, int n4) {
    int i = blockIdx.x * blockDim.x + threadIdx.x;
    if (i >= n4) return;
    float4 v = *(const float4*)(src + 4 * i);
    ((__half2*)(dh + 4 * i))[0] = __half2(__float2half_rn(v.x), __float2half_rn(v.y));
    ((__half2*)(dh + 4 * i))[1] = __half2(__float2half_rn(v.z), __float2half_rn(v.w));
}

// QKV weight: src [L*512, 512] row-major -> dst rows stride 1536 at column colofs
__global__ void convw_qkv(const float* __restrict__ src, __half* __restrict__ dh, int colofs) {
    int i = blockIdx.x * blockDim.x + threadIdx.x;
    if (i >= Lv * Dv * Dv / 4) return;
    int e = 4 * i;
    int k = e >> 9, col = e & 511;
    float4 v = *(const float4*)(src + e);
    size_t dst = (size_t)k * QKVN + colofs + col;
    ((__half2*)(dh + dst))[0] = __half2(__float2half_rn(v.x), __float2half_rn(v.y));
    ((__half2*)(dh + dst))[1] = __half2(__float2half_rn(v.z), __float2half_rn(v.w));
}

__global__ void bias_qkv(const float* __restrict__ bq, const float* __restrict__ bk,
                         const float* __restrict__ bvp) {
    int idx = blockIdx.x * blockDim.x + threadIdx.x;
    if (idx >= Lv * QKVN) return;
    int l = idx / QKVN, c = idx % QKVN;
    float v;
    if (c < 512) v = bq[l * Dv + c];
    else if (c < 1024) v = bk[l * Dv + c - 512];
    else v = bvp[l * Dv + c - 1024];
    g_bqkv[idx] = v;
}

// -------------------- embedding + sinusoidal positions --------------------
__global__ void embed_kernel(const int* __restrict__ tokens,
                             const float* __restrict__ emb) {
    int idx = blockIdx.x * blockDim.x + threadIdx.x;
    if (idx >= NTOK * Dv) return;
    int n = idx >> 9;
    int j = idx & 511;
    int t = n & (Tv - 1);
    float val;
    const float c = 9.210340371976184f / 256.f;
    if (j < 256) {
        int tok = tokens[n];
        val = emb[tok * 256 + j];
    } else if (j < 384) {
        int i = j - 256;
        val = sinf((float)t * expf(-(2.f * (float)i) * c));
    } else {
        int i = j - 384;
        val = cosf((float)t * expf(-(2.f * (float)i) * c));
    }
    g_x[idx] = val;
    __half h, l;
    split_fp16(val, h, l);
    g_xh[idx] = h;
    g_xl[idx] = l;
}

// -------------------- tensor-core GEMM, fp16, BK=64, 2-stage cp.async ----------
// C = A@B + bias; A[M,K] fp16 (hi, + lo if TERMS==2), B[K,N] fp16.
// BM=BN=128, 256 threads (8 warps, 32x64 warp tiles), 2 CTAs/SM.
// mode 0: fp32 out + bias. mode 1: gelu -> fp16 (Ch). mode 2: raw fp32 (no bias).

__device__ __forceinline__ void ldsm_x4(uint32_t* r, const void* p) {
    uint32_t a = (uint32_t)__cvta_generic_to_shared(p);
    asm volatile("ldmatrix.sync.aligned.m8n8.x4.shared.b16 {%0,%1,%2,%3},[%4];"
        : "=r"(r[0]), "=r"(r[1]), "=r"(r[2]), "=r"(r[3]) : "r"(a));
}
__device__ __forceinline__ void ldsm_x4_t(uint32_t* r, const void* p) {
    uint32_t a = (uint32_t)__cvta_generic_to_shared(p);
    asm volatile("ldmatrix.sync.aligned.m8n8.x4.trans.shared.b16 {%0,%1,%2,%3},[%4];"
        : "=r"(r[0]), "=r"(r[1]), "=r"(r[2]), "=r"(r[3]) : "r"(a));
}
__device__ __forceinline__ void mma16816(float* c, const uint32_t* a, const uint32_t* b) {
    asm volatile("mma.sync.aligned.m16n8k16.row.col.f32.f16.f16.f32 "
        "{%0,%1,%2,%3},{%4,%5,%6,%7},{%8,%9},{%0,%1,%2,%3};"
        : "+f"(c[0]), "+f"(c[1]), "+f"(c[2]), "+f"(c[3])
        : "r"(a[0]), "r"(a[1]), "r"(a[2]), "r"(a[3]), "r"(b[0]), "r"(b[1]));
}
__device__ __forceinline__ void cp16(void* smem, const void* gmem) {
    uint32_t s = (uint32_t)__cvta_generic_to_shared(smem);
    asm volatile("cp.async.cg.shared.global [%0], [%1], 16;" :: "r"(s), "l"(gmem));
}
#define CP_COMMIT() asm volatile("cp.async.commit_group;")
#define CP_WAIT(n)  asm volatile("cp.async.wait_group %0;" :: "n"(n))

#define PADA 72    // As row stride (fp16): 144B
#define PADB 136   // Bs row stride (fp16): 272B
#define A_TILE 36864   // 2 stages * 128 rows * 72 * 2B
#define B_TILE 34816   // 2 stages * 64 rows * 136 * 2B
// TERMS==2: [AsH | AsL | BsH] = 108544 ; TERMS==1: [AsH | BsH] = 71680

template <int TERMS>
__global__ void __launch_bounds__(256, 2)
gemm_tc(const __half* __restrict__ Ahg, const __half* __restrict__ Alg,
        const __half* __restrict__ Bhg,
        const float* __restrict__ bias, float* __restrict__ C,
        __half* __restrict__ Ch,
        int M, int N, int lda, int ldb, int Kext, int mode) {
    extern __shared__ char smraw[];
    __half* AsH = (__half*)(smraw);
    __half* AsL = (__half*)(smraw + A_TILE);                       // TERMS==2 only
    __half* BsH = (__half*)(smraw + (TERMS == 2 ? 2 * A_TILE : A_TILE));

    int tid = threadIdx.x;
    int wid = tid >> 5, lane = tid & 31;
    int m_w = (wid >> 1) * 32, n_w = (wid & 1) * 64;
    int row0 = blockIdx.y * 128, col0 = blockIdx.x * 128;

    float acc[2][8][4];
#pragma unroll
    for (int i = 0; i < 2; i++)
#pragma unroll
        for (int j = 0; j < 8; j++)
#pragma unroll
            for (int q = 0; q < 4; q++) acc[i][j][q] = 0.f;

    int a_row = tid >> 1, a_colb = (tid & 1) * 32;   // A: 128 rows, 2 thr/row
    int b_row = tid >> 2, b_colb = (tid & 3) * 32;   // B: 64 rows, 4 thr/row

    auto loadStage = [&](int stage, int buf) {
        int k0 = stage * 64;
        const __half* aH = Ahg + (size_t)(row0 + a_row) * lda + k0 + a_colb;
        int sa = (buf * 128 + a_row) * PADA + a_colb;
        const __half* bH = Bhg + (size_t)(k0 + b_row) * ldb + col0 + b_colb;
        int sb = (buf * 64 + b_row) * PADB + b_colb;
#pragma unroll
        for (int i = 0; i < 4; i++) {
            cp16(AsH + sa + i * 8, aH + i * 8);
            cp16(BsH + sb + i * 8, bH + i * 8);
        }
        if (TERMS == 2) {
            const __half* aL = Alg + (size_t)(row0 + a_row) * lda + k0 + a_colb;
#pragma unroll
            for (int i = 0; i < 4; i++) cp16(AsL + sa + i * 8, aL + i * 8);
        }
        CP_COMMIT();
    };

    auto compute = [&](int buf) {
#pragma unroll
        for (int kk = 0; kk < 64; kk += 16) {
            uint32_t Ahf[2][4], Alf[2][4], Bhf[8][2];
#pragma unroll
            for (int i = 0; i < 2; i++) {
                int idx = (buf * 128 + m_w + i * 16 + (lane & 15)) * PADA + kk + (lane >> 4) * 8;
                ldsm_x4(Ahf[i], AsH + idx);
                if (TERMS == 2) ldsm_x4(Alf[i], AsL + idx);
            }
#pragma unroll
            for (int p = 0; p < 4; p++) {
                int idx = (buf * 64 + kk + (lane & 15)) * PADB + n_w + p * 16 + (lane >> 4) * 8;
                uint32_t r[4];
                ldsm_x4_t(r, BsH + idx);
                Bhf[2 * p][0] = r[0]; Bhf[2 * p][1] = r[1];
                Bhf[2 * p + 1][0] = r[2]; Bhf[2 * p + 1][1] = r[3];
            }
#pragma unroll
            for (int i = 0; i < 2; i++)
#pragma unroll
                for (int j = 0; j < 8; j++) {
                    mma16816(acc[i][j], Ahf[i], Bhf[j]);
                    if (TERMS == 2) mma16816(acc[i][j], Alf[i], Bhf[j]);
                }
        }
    };

    int nsteps = Kext >> 6;
    loadStage(0, 0);
    for (int s = 0; s < nsteps; s++) {
        CP_WAIT(0);
        __syncthreads();
        if (s + 1 < nsteps) loadStage(s + 1, (s + 1) & 1);
        compute(s & 1);
    }

    // epilogue
    int g = lane >> 2, tg = lane & 3;
#pragma unroll
    for (int i = 0; i < 2; i++) {
#pragma unroll
        for (int j = 0; j < 8; j++) {
            int cc = col0 + n_w + j * 8 + tg * 2;
            float b0 = 0.f, b1 = 0.f;
            if (mode != 2) { b0 = bias[cc]; b1 = bias[cc + 1]; }
#pragma unroll
            for (int half = 0; half < 2; half++) {
                int r = row0 + m_w + i * 16 + g + half * 8;
                float v0 = acc[i][j][half * 2 + 0] + b0;
                float v1 = acc[i][j][half * 2 + 1] + b1;
                if (mode == 1) {
                    v0 = 0.5f * v0 * (1.f + erff(v0 * 0.7071067811865475f));
                    v1 = 0.5f * v1 * (1.f + erff(v1 * 0.7071067811865475f));
                    *(__half2*)(Ch + (size_t)r * N + cc) =
                        __half2(__float2half_rn(v0), __float2half_rn(v1));
                } else {
                    *(float2*)(C + (size_t)r * N + cc) = make_float2(v0, v1);
                }
            }
        }
    }
}

// -------------------- reduce split-K partials for output GEMM --------------------
__global__ void wout_reduce(const float* __restrict__ bias, float* __restrict__ out) {
    int i = blockIdx.x * blockDim.x + threadIdx.x;   // float4 index
    float4 a = ((const float4*)g_part)[i];
    float4 b = ((const float4*)(g_part + (size_t)NTOK * VOCABv))[i];
    int col = (i * 4) & (VOCABv - 1);
    float4 o;
    o.x = a.x + b.x + bias[col + 0];
    o.y = a.y + b.y + bias[col + 1];
    o.z = a.z + b.z + bias[col + 2];
    o.w = a.w + b.w + bias[col + 3];
    ((float4*)out)[i] = o;
}

// -------------------- FAVOR+ feature map (smem-tiled; reads g_qkv) --------------------
__global__ void __launch_bounds__(128)
favor_feat(const float* __restrict__ rfs) {
    int tile = blockIdx.x, h = blockIdx.y;
    __shared__ float rf[64][64];
    __shared__ float sq[32][68], sk[32][68];
    int tid = threadIdx.x;
    const float* rfh = rfs + h * 4096;
    for (int i = tid; i < 4096; i += 128) rf[i >> 6][i & 63] = rfh[i];
    const float sc = 0.3535533905932738f;
    for (int i = tid; i < 2048; i += 128) {
        int tl = i >> 6, d = i & 63;
        size_t gq = (size_t)(tile * 32 + tl) * QKVN + h * HDv + d;
        sq[tl][d] = g_qkv[gq] * sc;
        sk[tl][d] = g_qkv[gq + 512] * sc;
    }
    __syncthreads();
    int tl = tid >> 2, ms = (tid & 3) << 4;
    float s2q = 0.f, s2k = 0.f;
#pragma unroll 8
    for (int d = 0; d < 64; d++) {
        float a = sq[tl][d], b = sk[tl][d];
        s2q += a * a;
        s2k += b * b;
    }
    float dq[16], dk[16];
#pragma unroll
    for (int mi = 0; mi < 16; mi++) { dq[mi] = 0.f; dk[mi] = 0.f; }
#pragma unroll 4
    for (int d = 0; d < 64; d++) {
        float a = sq[tl][d], b = sk[tl][d];
#pragma unroll
        for (int m4 = 0; m4 < 4; m4++) {
            float4 rv = *(const float4*)&rf[d][ms + m4 * 4];
            float rr[4] = {rv.x, rv.y, rv.z, rv.w};
#pragma unroll
            for (int q = 0; q < 4; q++) {
                dq[m4 * 4 + q] += a * rr[q];
                dk[m4 * 4 + q] += b * rr[q];
            }
        }
    }
    int base = (tile * 32 + tl) * Dv + h * HDv + ms;
#pragma unroll
    for (int mi = 0; mi < 16; mi++) {
        g_qf[base + mi] = expf(dq[mi] - 0.5f * s2q);
        g_kf[base + mi] = expf(dk[mi] - 0.5f * s2k);
    }
}

// -------------------- phase 1: per-chunk sums (double-buffered, 1 sync/iter) ------
__global__ void __launch_bounds__(64)
attn_chunk() {
    int c = blockIdx.x, bh = blockIdx.y;
    int b = bh / Hv, h = bh % Hv;
    int d = threadIdx.x;
    float S[64];
#pragma unroll
    for (int m = 0; m < 64; m++) S[m] = 0.f;
    float z = 0.f;
    __shared__ float skb[2][64];
    int t0 = c * CHUNK;
    skb[0][d] = g_kf[(b * Tv + t0) * Dv + h * HDv + d];
    __syncthreads();
    int p = 0;
    for (int t = t0; t < t0 + CHUNK; t++) {
        size_t vbase = (size_t)(b * Tv + t) * QKVN + 1024 + h * HDv;
        float vd = g_qkv[vbase + d];
        z += skb[p][d];
#pragma unroll
        for (int m = 0; m < 64; m++) S[m] += skb[p][m] * vd;
        if (t + 1 < t0 + CHUNK)
            skb[p ^ 1][d] = g_kf[(b * Tv + t + 1) * Dv + h * HDv + d];
        __syncthreads();
        p ^= 1;
    }
    int sb = (bh * NCHUNK + c) * 4096;
#pragma unroll
    for (int m = 0; m < 64; m++) g_S[sb + m * 64 + d] = S[m];
    g_z[(bh * NCHUNK + c) * 64 + d] = z;
}

// -------------------- phase 2: exclusive scans over chunks --------------------
__global__ void __launch_bounds__(64)
attn_scan_S() {
    int bh = blockIdx.x >> 6, m = blockIdx.x & 63, d = threadIdx.x;
    float v[NCHUNK];
#pragma unroll
    for (int c = 0; c < NCHUNK; c++)
        v[c] = g_S[((bh * NCHUNK + c) << 12) + m * 64 + d];
    float acc = 0.f;
#pragma unroll
    for (int c = 0; c < NCHUNK; c++) {
        g_S[((bh * NCHUNK + c) << 12) + m * 64 + d] = acc;
        acc += v[c];
    }
}
__global__ void __launch_bounds__(64)
attn_scan_z() {
    int bh = blockIdx.x, d = threadIdx.x;
    float v[NCHUNK];
#pragma unroll
    for (int c = 0; c < NCHUNK; c++) v[c] = g_z[(bh * NCHUNK + c) * 64 + d];
    float acc = 0.f;
#pragma unroll
    for (int c = 0; c < NCHUNK; c++) {
        g_z[(bh * NCHUNK + c) * 64 + d] = acc;
        acc += v[c];
    }
}

// -------------------- phase 3: replay + output (1 sync/iter) --------------------
__global__ void __launch_bounds__(64)
attn_apply() {
    int c = blockIdx.x, bh = blockIdx.y;
    int b = bh / Hv, h = bh % Hv;
    int d = threadIdx.x;
    int lane = d & 31, w = d >> 5;
    float S[64];
    int sb = (bh * NCHUNK + c) * 4096;
#pragma unroll
    for (int m = 0; m < 64; m++) S[m] = g_S[sb + m * 64 + d];
    float z = g_z[(bh * NCHUNK + c) * 64 + d];
    __shared__ float skb[2][64], sqb[2][64], sred[2][2];
    int t0 = c * CHUNK;
    {
        int base = (b * Tv + t0) * Dv + h * HDv;
        skb[0][d] = g_kf[base + d];
        sqb[0][d] = g_qf[base + d];
    }
    __syncthreads();
    int p = 0;
    for (int t = t0; t < t0 + CHUNK; t++) {
        z += skb[p][d];
        float pd = sqb[p][d] * z;
#pragma unroll
        for (int off = 16; off; off >>= 1) pd += __shfl_down_sync(0xffffffffu, pd, off);
        if (lane == 0) sred[p][w] = pd;
        size_t vbase = (size_t)(b * Tv + t) * QKVN + 1024 + h * HDv;
        float vd = g_qkv[vbase + d];
        float num = 0.f;
#pragma unroll
        for (int m = 0; m < 64; m++) {
            S[m] += skb[p][m] * vd;
            num += sqb[p][m] * S[m];
        }
        if (t + 1 < t0 + CHUNK) {
            int nbase = (b * Tv + t + 1) * Dv + h * HDv;
            skb[p ^ 1][d] = g_kf[nbase + d];
            sqb[p ^ 1][d] = g_qf[nbase + d];
        }
        __syncthreads();
        float den = sred[p][0] + sred[p][1];
        g_a[(b * Tv + t) * Dv + h * HDv + d] = num / (den + 1e-16f);
        p ^= 1;
    }
}

// -------------------- LayerNorm + residual add (+ fp16 hi/lo of new x) ----------
__global__ void __launch_bounds__(128)
ln_add(const float* __restrict__ a, const float* __restrict__ g,
       const float* __restrict__ bl, float* __restrict__ x) {
    int n = blockIdx.x, tid = threadIdx.x;
    int lane = tid & 31, w = tid >> 5;
    const float* ar = a + (size_t)n * Dv;
    float v[4];
    float s = 0.f, s2 = 0.f;
#pragma unroll
    for (int i = 0; i < 4; i++) {
        float t = ar[tid + i * 128];
        v[i] = t;
        s += t;
        s2 += t * t;
    }
    __shared__ float sh[8];
#pragma unroll
    for (int off = 16; off; off >>= 1) {
        s += __shfl_down_sync(0xffffffffu, s, off);
        s2 += __shfl_down_sync(0xffffffffu, s2, off);
    }
    if (lane == 0) { sh[w] = s; sh[4 + w] = s2; }
    __syncthreads();
    float S = sh[0] + sh[1] + sh[2] + sh[3];
    float S2 = sh[4] + sh[5] + sh[6] + sh[7];
    float mu = S * (1.f / Dv);
    float var = S2 * (1.f / Dv) - mu * mu;
    float rs = rsqrtf(var + 1e-5f);
#pragma unroll
    for (int i = 0; i < 4; i++) {
        int j = tid + i * 128;
        size_t idx = (size_t)n * Dv + j;
        float nv = x[idx] + (v[i] - mu) * rs * g[j] + bl[j];
        x[idx] = nv;
        __half h, l;
        split_fp16(nv, h, l);
        g_xh[idx] = h;
        g_xl[idx] = l;
    }
}

// -------------------- host driver --------------------
extern "C" void kernel_launch(void* const* d_in, const int* in_sizes, int n_in,
                              void* d_out, int out_size) {
    const int*   tokens = (const int*)d_in[0];
    const float* emb    = (const float*)d_in[1];
    const float* Wq     = (const float*)d_in[2];
    const float* bq     = (const float*)d_in[3];
    const float* Wk     = (const float*)d_in[4];
    const float* bk     = (const float*)d_in[5];
    const float* Wv     = (const float*)d_in[6];
    const float* bvp    = (const float*)d_in[7];
    const float* rfs    = (const float*)d_in[8];
    const float* ln1g   = (const float*)d_in[9];
    const float* ln1b   = (const float*)d_in[10];
    const float* ln2g   = (const float*)d_in[11];
    const float* ln2b   = (const float*)d_in[12];
    const float* WU     = (const float*)d_in[13];
    const float* bU     = (const float*)d_in[14];
    const float* WV     = (const float*)d_in[15];
    const float* bV     = (const float*)d_in[16];
    const float* Wout   = (const float*)d_in[17];
    const float* bout   = (const float*)d_in[18];
    float* out = (float*)d_out;

    static float *px = nullptr, *pa, *pqkv, *pbqkv, *ppart;
    static __half *pxh, *pxl, *phh, *pwh;
    if (!px) {
        cudaGetSymbolAddress((void**)&px, g_x);
        cudaGetSymbolAddress((void**)&pa, g_a);
        cudaGetSymbolAddress((void**)&pqkv, g_qkv);
        cudaGetSymbolAddress((void**)&pbqkv, g_bqkv);
        cudaGetSymbolAddress((void**)&ppart, g_part);
        cudaGetSymbolAddress((void**)&pxh, g_xh);
        cudaGetSymbolAddress((void**)&pxl, g_xl);
        cudaGetSymbolAddress((void**)&phh, g_hh);
        cudaGetSymbolAddress((void**)&pwh, g_wh);
        cudaFuncSetAttribute(gemm_tc<1>, cudaFuncAttributeMaxDynamicSharedMemorySize,
                             A_TILE + B_TILE);
        cudaFuncSetAttribute(gemm_tc<2>, cudaFuncAttributeMaxDynamicSharedMemorySize,
                             2 * A_TILE + B_TILE);
    }

    // weights -> fp16 ([K,N] row-major)
    int nq4 = Lv * Dv * Dv / 4;
    convw_qkv<<<(nq4 + 255) / 256, 256>>>(Wq, pwh + OFF_QKV, 0);
    convw_qkv<<<(nq4 + 255) / 256, 256>>>(Wk, pwh + OFF_QKV, 512);
    convw_qkv<<<(nq4 + 255) / 256, 256>>>(Wv, pwh + OFF_QKV, 1024);
    int nu4 = Lv * Dv * FFNv / 4;
    convw4<<<(nu4 + 255) / 256, 256>>>(WU, pwh + OFF_WU, nu4);
    convw4<<<(nu4 + 255) / 256, 256>>>(WV, pwh + OFF_WD, nu4);
    int no4 = Dv * VOCABv / 4;
    convw4<<<(no4 + 255) / 256, 256>>>(Wout, pwh + OFF_WO, no4);
    bias_qkv<<<(Lv * QKVN + 255) / 256, 256>>>(bq, bk, bvp);

    embed_kernel<<<(NTOK * Dv + 255) / 256, 256>>>(tokens, emb);

    for (int l = 0; l < Lv; l++) {
        gemm_tc<1><<<dim3(QKVN / 128, NTOK / 128), 256, A_TILE + B_TILE>>>(
            pxh, nullptr, pwh + OFF_QKV + (size_t)l * Dv * QKVN, pbqkv + l * QKVN,
            pqkv, nullptr, NTOK, QKVN, Dv, QKVN, Dv, 0);

        favor_feat<<<dim3(NTOK / 32, Hv), 128>>>(rfs + (size_t)l * Hv * HDv * HDv);
        attn_chunk<<<dim3(NCHUNK, Bv * Hv), 64>>>();
        attn_scan_S<<<Bv * Hv * HDv, 64>>>();
        attn_scan_z<<<Bv * Hv, 64>>>();
        attn_apply<<<dim3(NCHUNK, Bv * Hv), 64>>>();

        ln_add<<<NTOK, 128>>>(pa, ln1g + l * Dv, ln1b + l * Dv, px);

        gemm_tc<1><<<dim3(FFNv / 128, NTOK / 128), 256, A_TILE + B_TILE>>>(
            pxh, nullptr, pwh + OFF_WU + (size_t)l * Dv * FFNv, bU + l * FFNv,
            nullptr, phh, NTOK, FFNv, Dv, FFNv, Dv, 1);
        gemm_tc<1><<<dim3(Dv / 128, NTOK / 128), 256, A_TILE + B_TILE>>>(
            phh, nullptr, pwh + OFF_WD + (size_t)l * FFNv * Dv, bV + l * Dv,
            pa, nullptr, NTOK, Dv, FFNv, Dv, FFNv, 0);

        ln_add<<<NTOK, 128>>>(pa, ln2g + l * Dv, ln2b + l * Dv, px);
    }

    // output GEMM split-K=2 (2-term fp16 for accuracy): partials, then reduce + bias
    for (int sp = 0; sp < 2; sp++) {
        int koff = sp * 256;
        gemm_tc<2><<<dim3(VOCABv / 128, NTOK / 128), 256, 2 * A_TILE + B_TILE>>>(
            pxh + koff, pxl + koff,
            pwh + OFF_WO + (size_t)koff * VOCABv,
            nullptr, ppart + (size_t)sp * NTOK * VOCABv, nullptr,
            NTOK, VOCABv, Dv, VOCABv, 256, 2);
    }
    wout_reduce<<<NTOK * VOCABv / 4 / 256, 256>>>(bout, out);
}

// round 9
// speedup vs baseline: 1.6829x; 1.0123x over previous
#include <cuda_runtime.h>
#include <cuda_fp16.h>
#include <math.h>
#include <stdint.h>

// Problem constants
#define Bv      2
#define Tv      2048
#define NTOK    (Bv * Tv)      // 4096
#define Dv      512
#define Hv      8
#define HDv     64
#define FFNv    2048
#define VOCABv  256
#define Lv      2
#define CHUNK   32
#define NCHUNK  (Tv / CHUNK)   // 64
#define QKVN    1536

// weight region offsets (elements) in the fp16 weight pool ([K,N] row-major)
#define OFF_QKV 0
#define OFF_WU  (OFF_QKV + Lv * Dv * QKVN)
#define OFF_WD  (OFF_WU + Lv * Dv * FFNv)
#define OFF_WO  (OFF_WD + Lv * FFNv * Dv)
#define W_TOTAL (OFF_WO + Dv * VOCABv)

// -------------------- scratch (device globals; no allocs) --------------------
__device__ float g_x[NTOK * Dv];
__device__ float g_a[NTOK * Dv];
__device__ float g_qkv[NTOK * QKVN];
__device__ float g_qf[NTOK * Dv];
__device__ float g_kf[NTOK * Dv];
__device__ float g_S[Bv * Hv * NCHUNK * HDv * HDv];
__device__ float g_z[Bv * Hv * NCHUNK * HDv];
__device__ float g_bqkv[Lv * QKVN];
__device__ float g_part[2 * NTOK * VOCABv];
__device__ __half g_xh[NTOK * Dv];
__device__ __half g_xl[NTOK * Dv];
__device__ __half g_hh[NTOK * FFNv];
__device__ __half g_wh[W_TOTAL];

__device__ __forceinline__ void split_fp16(float v, __half& h, __half& l) {
    h = __float2half_rn(v);
    l = __float2half_rn(v - __half2float(h));
}

// -------------------- weight fp32 -> fp16 (vectorized) --------------------
__global__ void convw4(const float* __restrict__ src, __half* __restrict__ dh, int n4) {
    int i = blockIdx.x * blockDim.x + threadIdx.x;
    if (i >= n4) return;
    float4 v = *(const float4*)(src + 4 * i);
    ((__half2*)(dh + 4 * i))[0] = __half2(__float2half_rn(v.x), __float2half_rn(v.y));
    ((__half2*)(dh + 4 * i))[1] = __half2(__float2half_rn(v.z), __float2half_rn(v.w));
}

// QKV weight: src [L*512, 512] row-major -> dst rows stride 1536 at column colofs
__global__ void convw_qkv(const float* __restrict__ src, __half* __restrict__ dh, int colofs) {
    int i = blockIdx.x * blockDim.x + threadIdx.x;
    if (i >= Lv * Dv * Dv / 4) return;
    int e = 4 * i;
    int k = e >> 9, col = e & 511;
    float4 v = *(const float4*)(src + e);
    size_t dst = (size_t)k * QKVN + colofs + col;
    ((__half2*)(dh + dst))[0] = __half2(__float2half_rn(v.x), __float2half_rn(v.y));
    ((__half2*)(dh + dst))[1] = __half2(__float2half_rn(v.z), __float2half_rn(v.w));
}

__global__ void bias_qkv(const float* __restrict__ bq, const float* __restrict__ bk,
                         const float* __restrict__ bvp) {
    int idx = blockIdx.x * blockDim.x + threadIdx.x;
    if (idx >= Lv * QKVN) return;
    int l = idx / QKVN, c = idx % QKVN;
    float v;
    if (c < 512) v = bq[l * Dv + c];
    else if (c < 1024) v = bk[l * Dv + c - 512];
    else v = bvp[l * Dv + c - 1024];
    g_bqkv[idx] = v;
}

// -------------------- embedding + sinusoidal positions --------------------
__global__ void embed_kernel(const int* __restrict__ tokens,
                             const float* __restrict__ emb) {
    int idx = blockIdx.x * blockDim.x + threadIdx.x;
    if (idx >= NTOK * Dv) return;
    int n = idx >> 9;
    int j = idx & 511;
    int t = n & (Tv - 1);
    float val;
    const float c = 9.210340371976184f / 256.f;
    if (j < 256) {
        int tok = tokens[n];
        val = emb[tok * 256 + j];
    } else if (j < 384) {
        int i = j - 256;
        val = sinf((float)t * expf(-(2.f * (float)i) * c));
    } else {
        int i = j - 384;
        val = cosf((float)t * expf(-(2.f * (float)i) * c));
    }
    g_x[idx] = val;
    __half h, l;
    split_fp16(val, h, l);
    g_xh[idx] = h;
    g_xl[idx] = l;
}

// -------------------- tensor-core GEMM, fp16, BK=64, 2-stage cp.async ----------
__device__ __forceinline__ void ldsm_x4(uint32_t* r, const void* p) {
    uint32_t a = (uint32_t)__cvta_generic_to_shared(p);
    asm volatile("ldmatrix.sync.aligned.m8n8.x4.shared.b16 {%0,%1,%2,%3},[%4];"
        : "=r"(r[0]), "=r"(r[1]), "=r"(r[2]), "=r"(r[3]) : "r"(a));
}
__device__ __forceinline__ void ldsm_x4_t(uint32_t* r, const void* p) {
    uint32_t a = (uint32_t)__cvta_generic_to_shared(p);
    asm volatile("ldmatrix.sync.aligned.m8n8.x4.trans.shared.b16 {%0,%1,%2,%3},[%4];"
        : "=r"(r[0]), "=r"(r[1]), "=r"(r[2]), "=r"(r[3]) : "r"(a));
}
__device__ __forceinline__ void mma16816(float* c, const uint32_t* a, const uint32_t* b) {
    asm volatile("mma.sync.aligned.m16n8k16.row.col.f32.f16.f16.f32 "
        "{%0,%1,%2,%3},{%4,%5,%6,%7},{%8,%9},{%0,%1,%2,%3};"
        : "+f"(c[0]), "+f"(c[1]), "+f"(c[2]), "+f"(c[3])
        : "r"(a[0]), "r"(a[1]), "r"(a[2]), "r"(a[3]), "r"(b[0]), "r"(b[1]));
}
__device__ __forceinline__ void cp16(void* smem, const void* gmem) {
    uint32_t s = (uint32_t)__cvta_generic_to_shared(smem);
    asm volatile("cp.async.cg.shared.global [%0], [%1], 16;" :: "r"(s), "l"(gmem));
}
#define CP_COMMIT() asm volatile("cp.async.commit_group;")
#define CP_WAIT(n)  asm volatile("cp.async.wait_group %0;" :: "n"(n))

#define PADA 72
#define PADB 136
#define A_TILE 36864
#define B_TILE 34816

// mode 0: fp32 out + bias. mode 1: gelu -> fp16 (Ch). mode 2: split-K partials (no bias).
template <int TERMS>
__global__ void __launch_bounds__(256, 2)
gemm_tc(const __half* __restrict__ Ahg, const __half* __restrict__ Alg,
        const __half* __restrict__ Bhg,
        const float* __restrict__ bias, float* __restrict__ C,
        __half* __restrict__ Ch,
        int M, int N, int lda, int ldb, int Kext, int mode) {
    extern __shared__ char smraw[];
    __half* AsH = (__half*)(smraw);
    __half* AsL = (__half*)(smraw + A_TILE);
    __half* BsH = (__half*)(smraw + (TERMS == 2 ? 2 * A_TILE : A_TILE));

    if (mode == 2) {   // split-K over blockIdx.z
        size_t ko = (size_t)blockIdx.z * Kext;
        Ahg += ko;
        if (TERMS == 2) Alg += ko;
        Bhg += ko * ldb;
        C += (size_t)blockIdx.z * M * N;
    }

    int tid = threadIdx.x;
    int wid = tid >> 5, lane = tid & 31;
    int m_w = (wid >> 1) * 32, n_w = (wid & 1) * 64;
    int row0 = blockIdx.y * 128, col0 = blockIdx.x * 128;

    float acc[2][8][4];
#pragma unroll
    for (int i = 0; i < 2; i++)
#pragma unroll
        for (int j = 0; j < 8; j++)
#pragma unroll
            for (int q = 0; q < 4; q++) acc[i][j][q] = 0.f;

    int a_row = tid >> 1, a_colb = (tid & 1) * 32;
    int b_row = tid >> 2, b_colb = (tid & 3) * 32;

    auto loadStage = [&](int stage, int buf) {
        int k0 = stage * 64;
        const __half* aH = Ahg + (size_t)(row0 + a_row) * lda + k0 + a_colb;
        int sa = (buf * 128 + a_row) * PADA + a_colb;
        const __half* bH = Bhg + (size_t)(k0 + b_row) * ldb + col0 + b_colb;
        int sb = (buf * 64 + b_row) * PADB + b_colb;
#pragma unroll
        for (int i = 0; i < 4; i++) {
            cp16(AsH + sa + i * 8, aH + i * 8);
            cp16(BsH + sb + i * 8, bH + i * 8);
        }
        if (TERMS == 2) {
            const __half* aL = Alg + (size_t)(row0 + a_row) * lda + k0 + a_colb;
#pragma unroll
            for (int i = 0; i < 4; i++) cp16(AsL + sa + i * 8, aL + i * 8);
        }
        CP_COMMIT();
    };

    auto compute = [&](int buf) {
#pragma unroll
        for (int kk = 0; kk < 64; kk += 16) {
            uint32_t Ahf[2][4], Alf[2][4], Bhf[8][2];
#pragma unroll
            for (int i = 0; i < 2; i++) {
                int idx = (buf * 128 + m_w + i * 16 + (lane & 15)) * PADA + kk + (lane >> 4) * 8;
                ldsm_x4(Ahf[i], AsH + idx);
                if (TERMS == 2) ldsm_x4(Alf[i], AsL + idx);
            }
#pragma unroll
            for (int p = 0; p < 4; p++) {
                int idx = (buf * 64 + kk + (lane & 15)) * PADB + n_w + p * 16 + (lane >> 4) * 8;
                uint32_t r[4];
                ldsm_x4_t(r, BsH + idx);
                Bhf[2 * p][0] = r[0]; Bhf[2 * p][1] = r[1];
                Bhf[2 * p + 1][0] = r[2]; Bhf[2 * p + 1][1] = r[3];
            }
#pragma unroll
            for (int i = 0; i < 2; i++)
#pragma unroll
                for (int j = 0; j < 8; j++) {
                    mma16816(acc[i][j], Ahf[i], Bhf[j]);
                    if (TERMS == 2) mma16816(acc[i][j], Alf[i], Bhf[j]);
                }
        }
    };

    int nsteps = Kext >> 6;
    loadStage(0, 0);
    for (int s = 0; s < nsteps; s++) {
        CP_WAIT(0);
        __syncthreads();
        if (s + 1 < nsteps) loadStage(s + 1, (s + 1) & 1);
        compute(s & 1);
    }

    int g = lane >> 2, tg = lane & 3;
#pragma unroll
    for (int i = 0; i < 2; i++) {
#pragma unroll
        for (int j = 0; j < 8; j++) {
            int cc = col0 + n_w + j * 8 + tg * 2;
            float b0 = 0.f, b1 = 0.f;
            if (mode != 2) { b0 = bias[cc]; b1 = bias[cc + 1]; }
#pragma unroll
            for (int half = 0; half < 2; half++) {
                int r = row0 + m_w + i * 16 + g + half * 8;
                float v0 = acc[i][j][half * 2 + 0] + b0;
                float v1 = acc[i][j][half * 2 + 1] + b1;
                if (mode == 1) {
                    v0 = 0.5f * v0 * (1.f + erff(v0 * 0.7071067811865475f));
                    v1 = 0.5f * v1 * (1.f + erff(v1 * 0.7071067811865475f));
                    *(__half2*)(Ch + (size_t)r * N + cc) =
                        __half2(__float2half_rn(v0), __float2half_rn(v1));
                } else {
                    *(float2*)(C + (size_t)r * N + cc) = make_float2(v0, v1);
                }
            }
        }
    }
}

// -------------------- reduce split-K partials for output GEMM --------------------
__global__ void wout_reduce(const float* __restrict__ bias, float* __restrict__ out) {
    int i = blockIdx.x * blockDim.x + threadIdx.x;
    float4 a = ((const float4*)g_part)[i];
    float4 b = ((const float4*)(g_part + (size_t)NTOK * VOCABv))[i];
    int col = (i * 4) & (VOCABv - 1);
    float4 o;
    o.x = a.x + b.x + bias[col + 0];
    o.y = a.y + b.y + bias[col + 1];
    o.z = a.z + b.z + bias[col + 2];
    o.w = a.w + b.w + bias[col + 3];
    ((float4*)out)[i] = o;
}

// -------------------- FAVOR+ feature map (smem-tiled; reads g_qkv) --------------------
__global__ void __launch_bounds__(128)
favor_feat(const float* __restrict__ rfs) {
    int tile = blockIdx.x, h = blockIdx.y;
    __shared__ float rf[64][64];
    __shared__ float sq[32][68], sk[32][68];
    int tid = threadIdx.x;
    const float* rfh = rfs + h * 4096;
    for (int i = tid; i < 4096; i += 128) rf[i >> 6][i & 63] = rfh[i];
    const float sc = 0.3535533905932738f;
    for (int i = tid; i < 2048; i += 128) {
        int tl = i >> 6, d = i & 63;
        size_t gq = (size_t)(tile * 32 + tl) * QKVN + h * HDv + d;
        sq[tl][d] = g_qkv[gq] * sc;
        sk[tl][d] = g_qkv[gq + 512] * sc;
    }
    __syncthreads();
    int tl = tid >> 2, ms = (tid & 3) << 4;
    float s2q = 0.f, s2k = 0.f;
#pragma unroll 8
    for (int d = 0; d < 64; d++) {
        float a = sq[tl][d], b = sk[tl][d];
        s2q += a * a;
        s2k += b * b;
    }
    float dq[16], dk[16];
#pragma unroll
    for (int mi = 0; mi < 16; mi++) { dq[mi] = 0.f; dk[mi] = 0.f; }
#pragma unroll 4
    for (int d = 0; d < 64; d++) {
        float a = sq[tl][d], b = sk[tl][d];
#pragma unroll
        for (int m4 = 0; m4 < 4; m4++) {
            float4 rv = *(const float4*)&rf[d][ms + m4 * 4];
            float rr[4] = {rv.x, rv.y, rv.z, rv.w};
#pragma unroll
            for (int q = 0; q < 4; q++) {
                dq[m4 * 4 + q] += a * rr[q];
                dk[m4 * 4 + q] += b * rr[q];
            }
        }
    }
    int base = (tile * 32 + tl) * Dv + h * HDv + ms;
#pragma unroll
    for (int mi = 0; mi < 16; mi++) {
        g_qf[base + mi] = expf(dq[mi] - 0.5f * s2q);
        g_kf[base + mi] = expf(dk[mi] - 0.5f * s2k);
    }
}

// -------------------- phase 1: per-chunk sums via parallel outer-product GEMM ----
// S_c[m][d] = sum_t Kf[t][m]*V[t][d]; z_c[m] = sum_t Kf[t][m]. 128 threads/block.
__global__ void __launch_bounds__(128)
attn_chunk() {
    int c = blockIdx.x, bh = blockIdx.y;
    int b = bh / Hv, h = bh % Hv;
    int tid = threadIdx.x;
    __shared__ float Kf[32][68], V[32][68];
    int t0 = c * CHUNK;
    for (int i = tid; i < 512; i += 128) {
        int row = i >> 4, c4 = (i & 15) * 4;
        size_t kb = (size_t)(b * Tv + t0 + row) * Dv + h * HDv + c4;
        size_t vb = (size_t)(b * Tv + t0 + row) * QKVN + 1024 + h * HDv + c4;
        *(float4*)&Kf[row][c4] = *(const float4*)(g_kf + kb);
        *(float4*)&V[row][c4] = *(const float4*)(g_qkv + vb);
    }
    __syncthreads();
    int m0 = (tid >> 3) * 4, d0 = (tid & 7) * 8;
    float acc[4][8];
#pragma unroll
    for (int r = 0; r < 4; r++)
#pragma unroll
        for (int q = 0; q < 8; q++) acc[r][q] = 0.f;
#pragma unroll 8
    for (int t = 0; t < 32; t++) {
        float4 km = *(const float4*)&Kf[t][m0];
        float4 v0 = *(const float4*)&V[t][d0];
        float4 v1 = *(const float4*)&V[t][d0 + 4];
        float kr[4] = {km.x, km.y, km.z, km.w};
        float vr[8] = {v0.x, v0.y, v0.z, v0.w, v1.x, v1.y, v1.z, v1.w};
#pragma unroll
        for (int r = 0; r < 4; r++)
#pragma unroll
            for (int q = 0; q < 8; q++) acc[r][q] += kr[r] * vr[q];
    }
    int sb = (bh * NCHUNK + c) * 4096;
#pragma unroll
    for (int r = 0; r < 4; r++) {
        *(float4*)(g_S + sb + (m0 + r) * 64 + d0) =
            make_float4(acc[r][0], acc[r][1], acc[r][2], acc[r][3]);
        *(float4*)(g_S + sb + (m0 + r) * 64 + d0 + 4) =
            make_float4(acc[r][4], acc[r][5], acc[r][6], acc[r][7]);
    }
    if (tid < 64) {
        float z = 0.f;
#pragma unroll
        for (int t = 0; t < 32; t++) z += Kf[t][tid];
        g_z[(bh * NCHUNK + c) * 64 + tid] = z;
    }
}

// -------------------- phase 2: exclusive scans over chunks --------------------
__global__ void __launch_bounds__(64)
attn_scan_S() {
    int bh = blockIdx.x >> 6, m = blockIdx.x & 63, d = threadIdx.x;
    float v[NCHUNK];
#pragma unroll
    for (int c = 0; c < NCHUNK; c++)
        v[c] = g_S[((bh * NCHUNK + c) << 12) + m * 64 + d];
    float acc = 0.f;
#pragma unroll
    for (int c = 0; c < NCHUNK; c++) {
        g_S[((bh * NCHUNK + c) << 12) + m * 64 + d] = acc;
        acc += v[c];
    }
}
__global__ void __launch_bounds__(64)
attn_scan_z() {
    int bh = blockIdx.x, d = threadIdx.x;
    float v[NCHUNK];
#pragma unroll
    for (int c = 0; c < NCHUNK; c++) v[c] = g_z[(bh * NCHUNK + c) * 64 + d];
    float acc = 0.f;
#pragma unroll
    for (int c = 0; c < NCHUNK; c++) {
        g_z[(bh * NCHUNK + c) * 64 + d] = acc;
        acc += v[c];
    }
}

// -------------------- phase 3: chunked-GEMM apply (no serial scan) --------------
// num = Qf*S0 + tril(Qf*Kf^T)*V ; den = Qf*z0 + rowsum(tril(Qf*Kf^T)).
__global__ void __launch_bounds__(128)
attn_apply() {
    int c = blockIdx.x, bh = blockIdx.y;
    int b = bh / Hv, h = bh % Hv;
    int tid = threadIdx.x;
    __shared__ float Qf[32][68], Kf[32][68], V[32][68];
    __shared__ float S0[64][68];
    __shared__ float A[32][36];
    __shared__ float z0[64], sden[32];
    int t0 = c * CHUNK;
    int sb = (bh * NCHUNK + c) * 4096;

    for (int i = tid; i < 512; i += 128) {
        int row = i >> 4, c4 = (i & 15) * 4;
        size_t qb = (size_t)(b * Tv + t0 + row) * Dv + h * HDv + c4;
        size_t vb = (size_t)(b * Tv + t0 + row) * QKVN + 1024 + h * HDv + c4;
        *(float4*)&Qf[row][c4] = *(const float4*)(g_qf + qb);
        *(float4*)&Kf[row][c4] = *(const float4*)(g_kf + qb);
        *(float4*)&V[row][c4] = *(const float4*)(g_qkv + vb);
    }
    for (int i = tid; i < 1024; i += 128) {
        int m = i >> 4, c4 = (i & 15) * 4;
        *(float4*)&S0[m][c4] = *(const float4*)(g_S + sb + m * 64 + c4);
    }
    if (tid < 16)
        *(float4*)&z0[tid * 4] = *(const float4*)(g_z + (bh * NCHUNK + c) * 64 + tid * 4);
    __syncthreads();

    // phase 1: A = tril(Qf * Kf^T), each thread 4i x {j0, j0+16}
    int i0 = (tid >> 4) * 4;
    int j0 = tid & 15;
    {
        float a0[4] = {0.f, 0.f, 0.f, 0.f}, a1[4] = {0.f, 0.f, 0.f, 0.f};
#pragma unroll
        for (int k = 0; k < 64; k += 4) {
            float4 ka = *(const float4*)&Kf[j0][k];
            float4 kb = *(const float4*)&Kf[j0 + 16][k];
#pragma unroll
            for (int r = 0; r < 4; r++) {
                float4 q = *(const float4*)&Qf[i0 + r][k];
                a0[r] += q.x * ka.x + q.y * ka.y + q.z * ka.z + q.w * ka.w;
                a1[r] += q.x * kb.x + q.y * kb.y + q.z * kb.z + q.w * kb.w;
            }
        }
#pragma unroll
        for (int r = 0; r < 4; r++) {
            A[i0 + r][j0] = (j0 <= i0 + r) ? a0[r] : 0.f;
            A[i0 + r][j0 + 16] = (j0 + 16 <= i0 + r) ? a1[r] : 0.f;
        }
    }
    __syncthreads();

    // den by warp 0 (A already masked, so plain row sums)
    if (tid < 32) {
        float dn = 1e-16f;
#pragma unroll 8
        for (int m = 0; m < 64; m++) dn += Qf[tid][m] * z0[m];
#pragma unroll
        for (int j = 0; j < 32; j++) dn += A[tid][j];
        sden[tid] = dn;
    }

    // phase 2: num = Qf*S0 + A*V, each thread 4i x 4d
    int dg = tid & 15, d0 = dg * 4;
    float acc[4][4];
#pragma unroll
    for (int r = 0; r < 4; r++)
#pragma unroll
        for (int q = 0; q < 4; q++) acc[r][q] = 0.f;
#pragma unroll 4
    for (int m = 0; m < 64; m += 4) {
        float4 qv[4], sv[4];
#pragma unroll
        for (int r = 0; r < 4; r++) qv[r] = *(const float4*)&Qf[i0 + r][m];
#pragma unroll
        for (int kk = 0; kk < 4; kk++) sv[kk] = *(const float4*)&S0[m + kk][d0];
#pragma unroll
        for (int r = 0; r < 4; r++) {
            float qr[4] = {qv[r].x, qv[r].y, qv[r].z, qv[r].w};
#pragma unroll
            for (int kk = 0; kk < 4; kk++) {
                acc[r][0] += qr[kk] * sv[kk].x;
                acc[r][1] += qr[kk] * sv[kk].y;
                acc[r][2] += qr[kk] * sv[kk].z;
                acc[r][3] += qr[kk] * sv[kk].w;
            }
        }
    }
#pragma unroll 2
    for (int j = 0; j < 32; j += 4) {
        float4 av[4], vv[4];
#pragma unroll
        for (int r = 0; r < 4; r++) av[r] = *(const float4*)&A[i0 + r][j];
#pragma unroll
        for (int kk = 0; kk < 4; kk++) vv[kk] = *(const float4*)&V[j + kk][d0];
#pragma unroll
        for (int r = 0; r < 4; r++) {
            float ar[4] = {av[r].x, av[r].y, av[r].z, av[r].w};
#pragma unroll
            for (int kk = 0; kk < 4; kk++) {
                acc[r][0] += ar[kk] * vv[kk].x;
                acc[r][1] += ar[kk] * vv[kk].y;
                acc[r][2] += ar[kk] * vv[kk].z;
                acc[r][3] += ar[kk] * vv[kk].w;
            }
        }
    }
    __syncthreads();   // sden ready
#pragma unroll
    for (int r = 0; r < 4; r++) {
        float inv = 1.f / sden[i0 + r];
        float4 o = make_float4(acc[r][0] * inv, acc[r][1] * inv,
                               acc[r][2] * inv, acc[r][3] * inv);
        *(float4*)(g_a + (size_t)(b * Tv + t0 + i0 + r) * Dv + h * HDv + d0) = o;
    }
}

// -------------------- LayerNorm + residual add (+ fp16 hi/lo of new x) ----------
__global__ void __launch_bounds__(128)
ln_add(const float* __restrict__ a, const float* __restrict__ g,
       const float* __restrict__ bl, float* __restrict__ x) {
    int n = blockIdx.x, tid = threadIdx.x;
    int lane = tid & 31, w = tid >> 5;
    const float* ar = a + (size_t)n * Dv;
    float v[4];
    float s = 0.f, s2 = 0.f;
#pragma unroll
    for (int i = 0; i < 4; i++) {
        float t = ar[tid + i * 128];
        v[i] = t;
        s += t;
        s2 += t * t;
    }
    __shared__ float sh[8];
#pragma unroll
    for (int off = 16; off; off >>= 1) {
        s += __shfl_down_sync(0xffffffffu, s, off);
        s2 += __shfl_down_sync(0xffffffffu, s2, off);
    }
    if (lane == 0) { sh[w] = s; sh[4 + w] = s2; }
    __syncthreads();
    float S = sh[0] + sh[1] + sh[2] + sh[3];
    float S2 = sh[4] + sh[5] + sh[6] + sh[7];
    float mu = S * (1.f / Dv);
    float var = S2 * (1.f / Dv) - mu * mu;
    float rs = rsqrtf(var + 1e-5f);
#pragma unroll
    for (int i = 0; i < 4; i++) {
        int j = tid + i * 128;
        size_t idx = (size_t)n * Dv + j;
        float nv = x[idx] + (v[i] - mu) * rs * g[j] + bl[j];
        x[idx] = nv;
        __half h, l;
        split_fp16(nv, h, l);
        g_xh[idx] = h;
        g_xl[idx] = l;
    }
}

// -------------------- host driver --------------------
extern "C" void kernel_launch(void* const* d_in, const int* in_sizes, int n_in,
                              void* d_out, int out_size) {
    const int*   tokens = (const int*)d_in[0];
    const float* emb    = (const float*)d_in[1];
    const float* Wq     = (const float*)d_in[2];
    const float* bq     = (const float*)d_in[3];
    const float* Wk     = (const float*)d_in[4];
    const float* bk     = (const float*)d_in[5];
    const float* Wv     = (const float*)d_in[6];
    const float* bvp    = (const float*)d_in[7];
    const float* rfs    = (const float*)d_in[8];
    const float* ln1g   = (const float*)d_in[9];
    const float* ln1b   = (const float*)d_in[10];
    const float* ln2g   = (const float*)d_in[11];
    const float* ln2b   = (const float*)d_in[12];
    const float* WU     = (const float*)d_in[13];
    const float* bU     = (const float*)d_in[14];
    const float* WV     = (const float*)d_in[15];
    const float* bV     = (const float*)d_in[16];
    const float* Wout   = (const float*)d_in[17];
    const float* bout   = (const float*)d_in[18];
    float* out = (float*)d_out;

    static float *px = nullptr, *pa, *pqkv, *pbqkv, *ppart;
    static __half *pxh, *pxl, *phh, *pwh;
    if (!px) {
        cudaGetSymbolAddress((void**)&px, g_x);
        cudaGetSymbolAddress((void**)&pa, g_a);
        cudaGetSymbolAddress((void**)&pqkv, g_qkv);
        cudaGetSymbolAddress((void**)&pbqkv, g_bqkv);
        cudaGetSymbolAddress((void**)&ppart, g_part);
        cudaGetSymbolAddress((void**)&pxh, g_xh);
        cudaGetSymbolAddress((void**)&pxl, g_xl);
        cudaGetSymbolAddress((void**)&phh, g_hh);
        cudaGetSymbolAddress((void**)&pwh, g_wh);
        cudaFuncSetAttribute(gemm_tc<1>, cudaFuncAttributeMaxDynamicSharedMemorySize,
                             A_TILE + B_TILE);
        cudaFuncSetAttribute(gemm_tc<2>, cudaFuncAttributeMaxDynamicSharedMemorySize,
                             2 * A_TILE + B_TILE);
    }

    // weights -> fp16 ([K,N] row-major)
    int nq4 = Lv * Dv * Dv / 4;
    convw_qkv<<<(nq4 + 255) / 256, 256>>>(Wq, pwh + OFF_QKV, 0);
    convw_qkv<<<(nq4 + 255) / 256, 256>>>(Wk, pwh + OFF_QKV, 512);
    convw_qkv<<<(nq4 + 255) / 256, 256>>>(Wv, pwh + OFF_QKV, 1024);
    int nu4 = Lv * Dv * FFNv / 4;
    convw4<<<(nu4 + 255) / 256, 256>>>(WU, pwh + OFF_WU, nu4);
    convw4<<<(nu4 + 255) / 256, 256>>>(WV, pwh + OFF_WD, nu4);
    int no4 = Dv * VOCABv / 4;
    convw4<<<(no4 + 255) / 256, 256>>>(Wout, pwh + OFF_WO, no4);
    bias_qkv<<<(Lv * QKVN + 255) / 256, 256>>>(bq, bk, bvp);

    embed_kernel<<<(NTOK * Dv + 255) / 256, 256>>>(tokens, emb);

    for (int l = 0; l < Lv; l++) {
        gemm_tc<1><<<dim3(QKVN / 128, NTOK / 128), 256, A_TILE + B_TILE>>>(
            pxh, nullptr, pwh + OFF_QKV + (size_t)l * Dv * QKVN, pbqkv + l * QKVN,
            pqkv, nullptr, NTOK, QKVN, Dv, QKVN, Dv, 0);

        favor_feat<<<dim3(NTOK / 32, Hv), 128>>>(rfs + (size_t)l * Hv * HDv * HDv);
        attn_chunk<<<dim3(NCHUNK, Bv * Hv), 128>>>();
        attn_scan_S<<<Bv * Hv * HDv, 64>>>();
        attn_scan_z<<<Bv * Hv, 64>>>();
        attn_apply<<<dim3(NCHUNK, Bv * Hv), 128>>>();

        ln_add<<<NTOK, 128>>>(pa, ln1g + l * Dv, ln1b + l * Dv, px);

        gemm_tc<1><<<dim3(FFNv / 128, NTOK / 128), 256, A_TILE + B_TILE>>>(
            pxh, nullptr, pwh + OFF_WU + (size_t)l * Dv * FFNv, bU + l * FFNv,
            nullptr, phh, NTOK, FFNv, Dv, FFNv, Dv, 1);
        gemm_tc<1><<<dim3(Dv / 128, NTOK / 128), 256, A_TILE + B_TILE>>>(
            phh, nullptr, pwh + OFF_WD + (size_t)l * FFNv * Dv, bV + l * Dv,
            pa, nullptr, NTOK, Dv, FFNv, Dv, FFNv, 0);

        ln_add<<<NTOK, 128>>>(pa, ln2g + l * Dv, ln2b + l * Dv, px);
    }

    // output GEMM split-K=2 in one launch (blockIdx.z), then reduce + bias
    gemm_tc<2><<<dim3(VOCABv / 128, NTOK / 128, 2), 256, 2 * A_TILE + B_TILE>>>(
        pxh, pxl, pwh + OFF_WO,
        nullptr, ppart, nullptr,
        NTOK, VOCABv, Dv, VOCABv, 256, 2);
    wout_reduce<<<NTOK * VOCABv / 4 / 256, 256>>>(bout, out);
}

// round 10
// speedup vs baseline: 1.8510x; 1.0999x over previous
#include <cuda_runtime.h>
#include <cuda_fp16.h>
#include <math.h>
#include <stdint.h>

// Problem constants
#define Bv      2
#define Tv      2048
#define NTOK    (Bv * Tv)      // 4096
#define Dv      512
#define Hv      8
#define HDv     64
#define FFNv    2048
#define VOCABv  256
#define Lv      2
#define CHUNK   32
#define NCHUNK  (Tv / CHUNK)   // 64
#define QKVN    1536

// weight region offsets (elements) in the fp16 weight pool ([K,N] row-major)
#define OFF_QKV 0
#define OFF_WU  (OFF_QKV + Lv * Dv * QKVN)
#define OFF_WD  (OFF_WU + Lv * Dv * FFNv)
#define OFF_WO  (OFF_WD + Lv * FFNv * Dv)
#define W_TOTAL (OFF_WO + Dv * VOCABv)

#define QKV4 (Lv * Dv * QKVN / 4)
#define WU4  (Lv * Dv * FFNv / 4)
#define WD4  (Lv * FFNv * Dv / 4)
#define WO4  (Dv * VOCABv / 4)
#define TOT4 (QKV4 + WU4 + WD4 + WO4)
#define BIA4 (Lv * QKVN / 4)

// -------------------- scratch (device globals; no allocs) --------------------
__device__ float g_x[NTOK * Dv];
__device__ float g_a[NTOK * Dv];
__device__ float g_qkv[NTOK * QKVN];
__device__ float g_qf[NTOK * Dv];
__device__ float g_kf[NTOK * Dv];
__device__ float g_S[Bv * Hv * NCHUNK * HDv * HDv];
__device__ float g_z[Bv * Hv * NCHUNK * HDv];
__device__ float g_bqkv[Lv * QKVN];
__device__ float g_part[2 * NTOK * Dv];
__device__ __half g_xh[NTOK * Dv];
__device__ __half g_xl[NTOK * Dv];
__device__ __half g_hh[NTOK * FFNv];
__device__ __half g_wh[W_TOTAL];

__device__ __forceinline__ void split_fp16(float v, __half& h, __half& l) {
    h = __float2half_rn(v);
    l = __float2half_rn(v - __half2float(h));
}

// -------------------- ONE fused weight conversion + bias pack --------------------
__global__ void convw_all(const float* __restrict__ Wq, const float* __restrict__ Wk,
                          const float* __restrict__ Wv, const float* __restrict__ WU,
                          const float* __restrict__ WV, const float* __restrict__ Wout,
                          const float* __restrict__ bq, const float* __restrict__ bk,
                          const float* __restrict__ bvp) {
    int idx = blockIdx.x * blockDim.x + threadIdx.x;
    if (idx < TOT4) {
        const float* src;
        int e;
        if (idx < QKV4) {
            e = idx * 4;                       // dst element in QKV region
            int l = e / (Dv * QKVN);
            int r = e % (Dv * QKVN);
            int k = r / QKVN, col = r % QKVN;
            if (col < 512)       src = Wq + (size_t)l * Dv * Dv + k * 512 + col;
            else if (col < 1024) src = Wk + (size_t)l * Dv * Dv + k * 512 + col - 512;
            else                 src = Wv + (size_t)l * Dv * Dv + k * 512 + col - 1024;
            e += OFF_QKV;
        } else if (idx < QKV4 + WU4) {
            int e2 = (idx - QKV4) * 4;
            src = WU + e2;
            e = OFF_WU + e2;
        } else if (idx < QKV4 + WU4 + WD4) {
            int e2 = (idx - QKV4 - WU4) * 4;
            src = WV + e2;
            e = OFF_WD + e2;
        } else {
            int e2 = (idx - QKV4 - WU4 - WD4) * 4;
            src = Wout + e2;
            e = OFF_WO + e2;
        }
        float4 v = *(const float4*)src;
        ((__half2*)(g_wh + e))[0] = __half2(__float2half_rn(v.x), __float2half_rn(v.y));
        ((__half2*)(g_wh + e))[1] = __half2(__float2half_rn(v.z), __float2half_rn(v.w));
    } else if (idx < TOT4 + BIA4) {
        int j = (idx - TOT4) * 4;
#pragma unroll
        for (int q = 0; q < 4; q++) {
            int jj = j + q;
            int l = jj / QKVN, c = jj % QKVN;
            float v;
            if (c < 512) v = bq[l * Dv + c];
            else if (c < 1024) v = bk[l * Dv + c - 512];
            else v = bvp[l * Dv + c - 1024];
            g_bqkv[jj] = v;
        }
    }
}

// -------------------- embedding + sinusoidal positions --------------------
__global__ void embed_kernel(const int* __restrict__ tokens,
                             const float* __restrict__ emb) {
    int idx = blockIdx.x * blockDim.x + threadIdx.x;
    if (idx >= NTOK * Dv) return;
    int n = idx >> 9;
    int j = idx & 511;
    int t = n & (Tv - 1);
    float val;
    const float c = 9.210340371976184f / 256.f;
    if (j < 256) {
        int tok = tokens[n];
        val = emb[tok * 256 + j];
    } else if (j < 384) {
        int i = j - 256;
        val = sinf((float)t * expf(-(2.f * (float)i) * c));
    } else {
        int i = j - 384;
        val = cosf((float)t * expf(-(2.f * (float)i) * c));
    }
    g_x[idx] = val;
    __half h, l;
    split_fp16(val, h, l);
    g_xh[idx] = h;
    g_xl[idx] = l;
}

// -------------------- tensor-core GEMM, fp16, BK=64, 2-stage cp.async ----------
__device__ __forceinline__ void ldsm_x4(uint32_t* r, const void* p) {
    uint32_t a = (uint32_t)__cvta_generic_to_shared(p);
    asm volatile("ldmatrix.sync.aligned.m8n8.x4.shared.b16 {%0,%1,%2,%3},[%4];"
        : "=r"(r[0]), "=r"(r[1]), "=r"(r[2]), "=r"(r[3]) : "r"(a));
}
__device__ __forceinline__ void ldsm_x4_t(uint32_t* r, const void* p) {
    uint32_t a = (uint32_t)__cvta_generic_to_shared(p);
    asm volatile("ldmatrix.sync.aligned.m8n8.x4.trans.shared.b16 {%0,%1,%2,%3},[%4];"
        : "=r"(r[0]), "=r"(r[1]), "=r"(r[2]), "=r"(r[3]) : "r"(a));
}
__device__ __forceinline__ void mma16816(float* c, const uint32_t* a, const uint32_t* b) {
    asm volatile("mma.sync.aligned.m16n8k16.row.col.f32.f16.f16.f32 "
        "{%0,%1,%2,%3},{%4,%5,%6,%7},{%8,%9},{%0,%1,%2,%3};"
        : "+f"(c[0]), "+f"(c[1]), "+f"(c[2]), "+f"(c[3])
        : "r"(a[0]), "r"(a[1]), "r"(a[2]), "r"(a[3]), "r"(b[0]), "r"(b[1]));
}
__device__ __forceinline__ void cp16(void* smem, const void* gmem) {
    uint32_t s = (uint32_t)__cvta_generic_to_shared(smem);
    asm volatile("cp.async.cg.shared.global [%0], [%1], 16;" :: "r"(s), "l"(gmem));
}
#define CP_COMMIT() asm volatile("cp.async.commit_group;")
#define CP_WAIT(n)  asm volatile("cp.async.wait_group %0;" :: "n"(n))

#define PADA 72
#define PADB 136
#define A_TILE 36864
#define B_TILE 34816

// mode 0: fp32 out + bias. mode 1: gelu -> fp16 (Ch). mode 2: split-K partials (no bias).
template <int TERMS>
__global__ void __launch_bounds__(256, 2)
gemm_tc(const __half* __restrict__ Ahg, const __half* __restrict__ Alg,
        const __half* __restrict__ Bhg,
        const float* __restrict__ bias, float* __restrict__ C,
        __half* __restrict__ Ch,
        int M, int N, int lda, int ldb, int Kext, int mode) {
    extern __shared__ char smraw[];
    __half* AsH = (__half*)(smraw);
    __half* AsL = (__half*)(smraw + A_TILE);
    __half* BsH = (__half*)(smraw + (TERMS == 2 ? 2 * A_TILE : A_TILE));

    if (mode == 2) {   // split-K over blockIdx.z
        size_t ko = (size_t)blockIdx.z * Kext;
        Ahg += ko;
        if (TERMS == 2) Alg += ko;
        Bhg += ko * ldb;
        C += (size_t)blockIdx.z * M * N;
    }

    int tid = threadIdx.x;
    int wid = tid >> 5, lane = tid & 31;
    int m_w = (wid >> 1) * 32, n_w = (wid & 1) * 64;
    int row0 = blockIdx.y * 128, col0 = blockIdx.x * 128;

    float acc[2][8][4];
#pragma unroll
    for (int i = 0; i < 2; i++)
#pragma unroll
        for (int j = 0; j < 8; j++)
#pragma unroll
            for (int q = 0; q < 4; q++) acc[i][j][q] = 0.f;

    int a_row = tid >> 1, a_colb = (tid & 1) * 32;
    int b_row = tid >> 2, b_colb = (tid & 3) * 32;

    auto loadStage = [&](int stage, int buf) {
        int k0 = stage * 64;
        const __half* aH = Ahg + (size_t)(row0 + a_row) * lda + k0 + a_colb;
        int sa = (buf * 128 + a_row) * PADA + a_colb;
        const __half* bH = Bhg + (size_t)(k0 + b_row) * ldb + col0 + b_colb;
        int sb = (buf * 64 + b_row) * PADB + b_colb;
#pragma unroll
        for (int i = 0; i < 4; i++) {
            cp16(AsH + sa + i * 8, aH + i * 8);
            cp16(BsH + sb + i * 8, bH + i * 8);
        }
        if (TERMS == 2) {
            const __half* aL = Alg + (size_t)(row0 + a_row) * lda + k0 + a_colb;
#pragma unroll
            for (int i = 0; i < 4; i++) cp16(AsL + sa + i * 8, aL + i * 8);
        }
        CP_COMMIT();
    };

    auto compute = [&](int buf) {
#pragma unroll
        for (int kk = 0; kk < 64; kk += 16) {
            uint32_t Ahf[2][4], Alf[2][4], Bhf[8][2];
#pragma unroll
            for (int i = 0; i < 2; i++) {
                int idx = (buf * 128 + m_w + i * 16 + (lane & 15)) * PADA + kk + (lane >> 4) * 8;
                ldsm_x4(Ahf[i], AsH + idx);
                if (TERMS == 2) ldsm_x4(Alf[i], AsL + idx);
            }
#pragma unroll
            for (int p = 0; p < 4; p++) {
                int idx = (buf * 64 + kk + (lane & 15)) * PADB + n_w + p * 16 + (lane >> 4) * 8;
                uint32_t r[4];
                ldsm_x4_t(r, BsH + idx);
                Bhf[2 * p][0] = r[0]; Bhf[2 * p][1] = r[1];
                Bhf[2 * p + 1][0] = r[2]; Bhf[2 * p + 1][1] = r[3];
            }
#pragma unroll
            for (int i = 0; i < 2; i++)
#pragma unroll
                for (int j = 0; j < 8; j++) {
                    mma16816(acc[i][j], Ahf[i], Bhf[j]);
                    if (TERMS == 2) mma16816(acc[i][j], Alf[i], Bhf[j]);
                }
        }
    };

    int nsteps = Kext >> 6;
    loadStage(0, 0);
    for (int s = 0; s < nsteps; s++) {
        CP_WAIT(0);
        __syncthreads();
        if (s + 1 < nsteps) loadStage(s + 1, (s + 1) & 1);
        compute(s & 1);
    }

    int g = lane >> 2, tg = lane & 3;
#pragma unroll
    for (int i = 0; i < 2; i++) {
#pragma unroll
        for (int j = 0; j < 8; j++) {
            int cc = col0 + n_w + j * 8 + tg * 2;
            float b0 = 0.f, b1 = 0.f;
            if (mode != 2) { b0 = bias[cc]; b1 = bias[cc + 1]; }
#pragma unroll
            for (int half = 0; half < 2; half++) {
                int r = row0 + m_w + i * 16 + g + half * 8;
                float v0 = acc[i][j][half * 2 + 0] + b0;
                float v1 = acc[i][j][half * 2 + 1] + b1;
                if (mode == 1) {
                    v0 = 0.5f * v0 * (1.f + erff(v0 * 0.7071067811865475f));
                    v1 = 0.5f * v1 * (1.f + erff(v1 * 0.7071067811865475f));
                    *(__half2*)(Ch + (size_t)r * N + cc) =
                        __half2(__float2half_rn(v0), __float2half_rn(v1));
                } else {
                    *(float2*)(C + (size_t)r * N + cc) = make_float2(v0, v1);
                }
            }
        }
    }
}

// -------------------- generic split-K=2 reduce + bias (N = power of 2) ----------
__global__ void reduce2(const float* __restrict__ part, const float* __restrict__ bias,
                        float* __restrict__ out, int total4, int nmask) {
    int i = blockIdx.x * blockDim.x + threadIdx.x;
    if (i >= total4) return;
    float4 a = ((const float4*)part)[i];
    float4 b = ((const float4*)part)[i + total4];
    int col = (i * 4) & nmask;
    float4 o;
    o.x = a.x + b.x + bias[col + 0];
    o.y = a.y + b.y + bias[col + 1];
    o.z = a.z + b.z + bias[col + 2];
    o.w = a.w + b.w + bias[col + 3];
    ((float4*)out)[i] = o;
}

// -------------------- fused FAVOR+ features + per-chunk sums --------------------
// grid (NTOK/32, Hv), 128 threads. Computes qf/kf (written to gmem) AND the
// chunk outer-product sums S_c, z_c in one kernel.
__global__ void __launch_bounds__(128)
favor_chunk(const float* __restrict__ rfs) {
    int tile = blockIdx.x, h = blockIdx.y;
    int b = tile >> 6, c = tile & 63;
    int bh = b * Hv + h;
    __shared__ float rf[64][64];
    __shared__ float sq[32][68], sk[32][68];
    int tid = threadIdx.x;
    const float* rfh = rfs + h * 4096;
    for (int i = tid; i < 4096; i += 128) rf[i >> 6][i & 63] = rfh[i];
    const float sc = 0.3535533905932738f;
    int t0 = c * CHUNK;
    for (int i = tid; i < 2048; i += 128) {
        int tl = i >> 6, d = i & 63;
        size_t gq = (size_t)(b * Tv + t0 + tl) * QKVN + h * HDv + d;
        sq[tl][d] = g_qkv[gq] * sc;
        sk[tl][d] = g_qkv[gq + 512] * sc;
    }
    __syncthreads();

    int tl = tid >> 2, ms = (tid & 3) << 4;
    float s2q = 0.f, s2k = 0.f;
#pragma unroll 8
    for (int d = 0; d < 64; d++) {
        float a = sq[tl][d], bb = sk[tl][d];
        s2q += a * a;
        s2k += bb * bb;
    }
    float dq[16], dk[16];
#pragma unroll
    for (int mi = 0; mi < 16; mi++) { dq[mi] = 0.f; dk[mi] = 0.f; }
#pragma unroll 4
    for (int d = 0; d < 64; d++) {
        float a = sq[tl][d], bb = sk[tl][d];
#pragma unroll
        for (int m4 = 0; m4 < 4; m4++) {
            float4 rv = *(const float4*)&rf[d][ms + m4 * 4];
            float rr[4] = {rv.x, rv.y, rv.z, rv.w};
#pragma unroll
            for (int q = 0; q < 4; q++) {
                dq[m4 * 4 + q] += a * rr[q];
                dk[m4 * 4 + q] += bb * rr[q];
            }
        }
    }
    float qfv[16], kfv[16];
#pragma unroll
    for (int mi = 0; mi < 16; mi++) {
        qfv[mi] = expf(dq[mi] - 0.5f * s2q);
        kfv[mi] = expf(dk[mi] - 0.5f * s2k);
    }
    int base = (b * Tv + t0 + tl) * Dv + h * HDv + ms;
#pragma unroll
    for (int mi = 0; mi < 16; mi += 4) {
        *(float4*)(g_qf + base + mi) = make_float4(qfv[mi], qfv[mi + 1], qfv[mi + 2], qfv[mi + 3]);
        *(float4*)(g_kf + base + mi) = make_float4(kfv[mi], kfv[mi + 1], kfv[mi + 2], kfv[mi + 3]);
    }
    __syncthreads();   // done reading sq/sk

    // reuse: sk <- kf values ; sq <- V
#pragma unroll
    for (int mi = 0; mi < 16; mi++) sk[tl][ms + mi] = kfv[mi];
    for (int i = tid; i < 512; i += 128) {
        int row = i >> 4, c4 = (i & 15) * 4;
        size_t vb = (size_t)(b * Tv + t0 + row) * QKVN + 1024 + h * HDv + c4;
        *(float4*)&sq[row][c4] = *(const float4*)(g_qkv + vb);
    }
    __syncthreads();

    // chunk outer-product sums: S_c[m][d] = sum_t kf[t][m] V[t][d]
    int m0 = (tid >> 3) * 4, d0 = (tid & 7) * 8;
    float acc[4][8];
#pragma unroll
    for (int r = 0; r < 4; r++)
#pragma unroll
        for (int q = 0; q < 8; q++) acc[r][q] = 0.f;
#pragma unroll 8
    for (int t = 0; t < 32; t++) {
        float4 km = *(const float4*)&sk[t][m0];
        float4 v0 = *(const float4*)&sq[t][d0];
        float4 v1 = *(const float4*)&sq[t][d0 + 4];
        float kr[4] = {km.x, km.y, km.z, km.w};
        float vr[8] = {v0.x, v0.y, v0.z, v0.w, v1.x, v1.y, v1.z, v1.w};
#pragma unroll
        for (int r = 0; r < 4; r++)
#pragma unroll
            for (int q = 0; q < 8; q++) acc[r][q] += kr[r] * vr[q];
    }
    int sb = (bh * NCHUNK + c) * 4096;
#pragma unroll
    for (int r = 0; r < 4; r++) {
        *(float4*)(g_S + sb + (m0 + r) * 64 + d0) =
            make_float4(acc[r][0], acc[r][1], acc[r][2], acc[r][3]);
        *(float4*)(g_S + sb + (m0 + r) * 64 + d0 + 4) =
            make_float4(acc[r][4], acc[r][5], acc[r][6], acc[r][7]);
    }
    if (tid < 64) {
        float z = 0.f;
#pragma unroll
        for (int t = 0; t < 32; t++) z += sk[t][tid];
        g_z[(bh * NCHUNK + c) * 64 + tid] = z;
    }
}

// -------------------- exclusive scans over chunks (S and z fused) ---------------
__global__ void __launch_bounds__(64)
attn_scan() {
    int bh = blockIdx.x >> 6, m = blockIdx.x & 63, d = threadIdx.x;
    float v[NCHUNK];
#pragma unroll
    for (int c = 0; c < NCHUNK; c++)
        v[c] = g_S[((bh * NCHUNK + c) << 12) + m * 64 + d];
    float acc = 0.f;
#pragma unroll
    for (int c = 0; c < NCHUNK; c++) {
        g_S[((bh * NCHUNK + c) << 12) + m * 64 + d] = acc;
        acc += v[c];
    }
    if (m == 0) {
        float zv[NCHUNK];
#pragma unroll
        for (int c = 0; c < NCHUNK; c++) zv[c] = g_z[(bh * NCHUNK + c) * 64 + d];
        float za = 0.f;
#pragma unroll
        for (int c = 0; c < NCHUNK; c++) {
            g_z[(bh * NCHUNK + c) * 64 + d] = za;
            za += zv[c];
        }
    }
}

// -------------------- chunked-GEMM apply --------------------
__global__ void __launch_bounds__(128)
attn_apply() {
    int c = blockIdx.x, bh = blockIdx.y;
    int b = bh / Hv, h = bh % Hv;
    int tid = threadIdx.x;
    __shared__ float Qf[32][68], Kf[32][68], V[32][68];
    __shared__ float S0[64][68];
    __shared__ float A[32][36];
    __shared__ float z0[64], sden[32];
    int t0 = c * CHUNK;
    int sb = (bh * NCHUNK + c) * 4096;

    for (int i = tid; i < 512; i += 128) {
        int row = i >> 4, c4 = (i & 15) * 4;
        size_t qb = (size_t)(b * Tv + t0 + row) * Dv + h * HDv + c4;
        size_t vb = (size_t)(b * Tv + t0 + row) * QKVN + 1024 + h * HDv + c4;
        *(float4*)&Qf[row][c4] = *(const float4*)(g_qf + qb);
        *(float4*)&Kf[row][c4] = *(const float4*)(g_kf + qb);
        *(float4*)&V[row][c4] = *(const float4*)(g_qkv + vb);
    }
    for (int i = tid; i < 1024; i += 128) {
        int m = i >> 4, c4 = (i & 15) * 4;
        *(float4*)&S0[m][c4] = *(const float4*)(g_S + sb + m * 64 + c4);
    }
    if (tid < 16)
        *(float4*)&z0[tid * 4] = *(const float4*)(g_z + (bh * NCHUNK + c) * 64 + tid * 4);
    __syncthreads();

    int i0 = (tid >> 4) * 4;
    int j0 = tid & 15;
    {
        float a0[4] = {0.f, 0.f, 0.f, 0.f}, a1[4] = {0.f, 0.f, 0.f, 0.f};
#pragma unroll
        for (int k = 0; k < 64; k += 4) {
            float4 ka = *(const float4*)&Kf[j0][k];
            float4 kb = *(const float4*)&Kf[j0 + 16][k];
#pragma unroll
            for (int r = 0; r < 4; r++) {
                float4 q = *(const float4*)&Qf[i0 + r][k];
                a0[r] += q.x * ka.x + q.y * ka.y + q.z * ka.z + q.w * ka.w;
                a1[r] += q.x * kb.x + q.y * kb.y + q.z * kb.z + q.w * kb.w;
            }
        }
#pragma unroll
        for (int r = 0; r < 4; r++) {
            A[i0 + r][j0] = (j0 <= i0 + r) ? a0[r] : 0.f;
            A[i0 + r][j0 + 16] = (j0 + 16 <= i0 + r) ? a1[r] : 0.f;
        }
    }
    __syncthreads();

    if (tid < 32) {
        float dn = 1e-16f;
#pragma unroll 8
        for (int m = 0; m < 64; m++) dn += Qf[tid][m] * z0[m];
#pragma unroll
        for (int j = 0; j < 32; j++) dn += A[tid][j];
        sden[tid] = dn;
    }

    int d0 = (tid & 15) * 4;
    float acc[4][4];
#pragma unroll
    for (int r = 0; r < 4; r++)
#pragma unroll
        for (int q = 0; q < 4; q++) acc[r][q] = 0.f;
#pragma unroll 4
    for (int m = 0; m < 64; m += 4) {
        float4 qv[4], sv[4];
#pragma unroll
        for (int r = 0; r < 4; r++) qv[r] = *(const float4*)&Qf[i0 + r][m];
#pragma unroll
        for (int kk = 0; kk < 4; kk++) sv[kk] = *(const float4*)&S0[m + kk][d0];
#pragma unroll
        for (int r = 0; r < 4; r++) {
            float qr[4] = {qv[r].x, qv[r].y, qv[r].z, qv[r].w};
#pragma unroll
            for (int kk = 0; kk < 4; kk++) {
                acc[r][0] += qr[kk] * sv[kk].x;
                acc[r][1] += qr[kk] * sv[kk].y;
                acc[r][2] += qr[kk] * sv[kk].z;
                acc[r][3] += qr[kk] * sv[kk].w;
            }
        }
    }
#pragma unroll 2
    for (int j = 0; j < 32; j += 4) {
        float4 av[4], vv[4];
#pragma unroll
        for (int r = 0; r < 4; r++) av[r] = *(const float4*)&A[i0 + r][j];
#pragma unroll
        for (int kk = 0; kk < 4; kk++) vv[kk] = *(const float4*)&V[j + kk][d0];
#pragma unroll
        for (int r = 0; r < 4; r++) {
            float ar[4] = {av[r].x, av[r].y, av[r].z, av[r].w};
#pragma unroll
            for (int kk = 0; kk < 4; kk++) {
                acc[r][0] += ar[kk] * vv[kk].x;
                acc[r][1] += ar[kk] * vv[kk].y;
                acc[r][2] += ar[kk] * vv[kk].z;
                acc[r][3] += ar[kk] * vv[kk].w;
            }
        }
    }
    __syncthreads();
#pragma unroll
    for (int r = 0; r < 4; r++) {
        float inv = 1.f / sden[i0 + r];
        float4 o = make_float4(acc[r][0] * inv, acc[r][1] * inv,
                               acc[r][2] * inv, acc[r][3] * inv);
        *(float4*)(g_a + (size_t)(b * Tv + t0 + i0 + r) * Dv + h * HDv + d0) = o;
    }
}

// -------------------- LayerNorm + residual add (+ fp16 hi/lo of new x) ----------
__global__ void __launch_bounds__(128)
ln_add(const float* __restrict__ a, const float* __restrict__ g,
       const float* __restrict__ bl, float* __restrict__ x) {
    int n = blockIdx.x, tid = threadIdx.x;
    int lane = tid & 31, w = tid >> 5;
    const float* ar = a + (size_t)n * Dv;
    float v[4];
    float s = 0.f, s2 = 0.f;
#pragma unroll
    for (int i = 0; i < 4; i++) {
        float t = ar[tid + i * 128];
        v[i] = t;
        s += t;
        s2 += t * t;
    }
    __shared__ float sh[8];
#pragma unroll
    for (int off = 16; off; off >>= 1) {
        s += __shfl_down_sync(0xffffffffu, s, off);
        s2 += __shfl_down_sync(0xffffffffu, s2, off);
    }
    if (lane == 0) { sh[w] = s; sh[4 + w] = s2; }
    __syncthreads();
    float S = sh[0] + sh[1] + sh[2] + sh[3];
    float S2 = sh[4] + sh[5] + sh[6] + sh[7];
    float mu = S * (1.f / Dv);
    float var = S2 * (1.f / Dv) - mu * mu;
    float rs = rsqrtf(var + 1e-5f);
#pragma unroll
    for (int i = 0; i < 4; i++) {
        int j = tid + i * 128;
        size_t idx = (size_t)n * Dv + j;
        float nv = x[idx] + (v[i] - mu) * rs * g[j] + bl[j];
        x[idx] = nv;
        __half h, l;
        split_fp16(nv, h, l);
        g_xh[idx] = h;
        g_xl[idx] = l;
    }
}

// -------------------- host driver --------------------
extern "C" void kernel_launch(void* const* d_in, const int* in_sizes, int n_in,
                              void* d_out, int out_size) {
    const int*   tokens = (const int*)d_in[0];
    const float* emb    = (const float*)d_in[1];
    const float* Wq     = (const float*)d_in[2];
    const float* bq     = (const float*)d_in[3];
    const float* Wk     = (const float*)d_in[4];
    const float* bk     = (const float*)d_in[5];
    const float* Wv     = (const float*)d_in[6];
    const float* bvp    = (const float*)d_in[7];
    const float* rfs    = (const float*)d_in[8];
    const float* ln1g   = (const float*)d_in[9];
    const float* ln1b   = (const float*)d_in[10];
    const float* ln2g   = (const float*)d_in[11];
    const float* ln2b   = (const float*)d_in[12];
    const float* WU     = (const float*)d_in[13];
    const float* bU     = (const float*)d_in[14];
    const float* WV     = (const float*)d_in[15];
    const float* bV     = (const float*)d_in[16];
    const float* Wout   = (const float*)d_in[17];
    const float* bout   = (const float*)d_in[18];
    float* out = (float*)d_out;

    static float *px = nullptr, *pa, *pqkv, *pbqkv, *ppart;
    static __half *pxh, *pxl, *phh, *pwh;
    if (!px) {
        cudaGetSymbolAddress((void**)&px, g_x);
        cudaGetSymbolAddress((void**)&pa, g_a);
        cudaGetSymbolAddress((void**)&pqkv, g_qkv);
        cudaGetSymbolAddress((void**)&pbqkv, g_bqkv);
        cudaGetSymbolAddress((void**)&ppart, g_part);
        cudaGetSymbolAddress((void**)&pxh, g_xh);
        cudaGetSymbolAddress((void**)&pxl, g_xl);
        cudaGetSymbolAddress((void**)&phh, g_hh);
        cudaGetSymbolAddress((void**)&pwh, g_wh);
        cudaFuncSetAttribute(gemm_tc<1>, cudaFuncAttributeMaxDynamicSharedMemorySize,
                             A_TILE + B_TILE);
        cudaFuncSetAttribute(gemm_tc<2>, cudaFuncAttributeMaxDynamicSharedMemorySize,
                             2 * A_TILE + B_TILE);
    }

    convw_all<<<(TOT4 + BIA4 + 255) / 256, 256>>>(Wq, Wk, Wv, WU, WV, Wout, bq, bk, bvp);
    embed_kernel<<<(NTOK * Dv + 255) / 256, 256>>>(tokens, emb);

    for (int l = 0; l < Lv; l++) {
        gemm_tc<1><<<dim3(QKVN / 128, NTOK / 128), 256, A_TILE + B_TILE>>>(
            pxh, nullptr, pwh + OFF_QKV + (size_t)l * Dv * QKVN, pbqkv + l * QKVN,
            pqkv, nullptr, NTOK, QKVN, Dv, QKVN, Dv, 0);

        favor_chunk<<<dim3(NTOK / 32, Hv), 128>>>(rfs + (size_t)l * Hv * HDv * HDv);
        attn_scan<<<Bv * Hv * HDv, 64>>>();
        attn_apply<<<dim3(NCHUNK, Bv * Hv), 128>>>();

        ln_add<<<NTOK, 128>>>(pa, ln1g + l * Dv, ln1b + l * Dv, px);

        gemm_tc<1><<<dim3(FFNv / 128, NTOK / 128), 256, A_TILE + B_TILE>>>(
            pxh, nullptr, pwh + OFF_WU + (size_t)l * Dv * FFNv, bU + l * FFNv,
            nullptr, phh, NTOK, FFNv, Dv, FFNv, Dv, 1);

        // FFN down: split-K=2 (K=2048 -> 2x1024), 256 CTAs, then reduce+bias
        gemm_tc<1><<<dim3(Dv / 128, NTOK / 128, 2), 256, A_TILE + B_TILE>>>(
            phh, nullptr, pwh + OFF_WD + (size_t)l * FFNv * Dv, nullptr,
            ppart, nullptr, NTOK, Dv, FFNv, Dv, 1024, 2);
        reduce2<<<(NTOK * Dv / 4 + 255) / 256, 256>>>(ppart, bV + l * Dv, pa,
                                                      NTOK * Dv / 4, Dv - 1);

        ln_add<<<NTOK, 128>>>(pa, ln2g + l * Dv, ln2b + l * Dv, px);
    }

    // output GEMM split-K=2 (2-term fp16), then reduce + bias
    gemm_tc<2><<<dim3(VOCABv / 128, NTOK / 128, 2), 256, 2 * A_TILE + B_TILE>>>(
        pxh, pxl, pwh + OFF_WO, nullptr, ppart, nullptr,
        NTOK, VOCABv, Dv, VOCABv, 256, 2);
    reduce2<<<(NTOK * VOCABv / 4 + 255) / 256, 256>>>(ppart, bout, out,
                                                      NTOK * VOCABv / 4, VOCABv - 1);
}

// round 11
// speedup vs baseline: 1.9708x; 1.0647x over previous
#include <cuda_runtime.h>
#include <cuda_fp16.h>
#include <math.h>
#include <stdint.h>

// Problem constants
#define Bv      2
#define Tv      2048
#define NTOK    (Bv * Tv)      // 4096
#define Dv      512
#define Hv      8
#define HDv     64
#define FFNv    2048
#define VOCABv  256
#define Lv      2
#define CHUNK   32
#define NCHUNK  (Tv / CHUNK)   // 64
#define QKVN    1536

// weight region offsets (elements) in the fp16 weight pool ([K,N] row-major)
#define OFF_QKV 0
#define OFF_WU  (OFF_QKV + Lv * Dv * QKVN)
#define OFF_WD  (OFF_WU + Lv * Dv * FFNv)
#define OFF_WO  (OFF_WD + Lv * FFNv * Dv)
#define W_TOTAL (OFF_WO + Dv * VOCABv)

#define QKV4 (Lv * Dv * QKVN / 4)
#define WU4  (Lv * Dv * FFNv / 4)
#define WD4  (Lv * FFNv * Dv / 4)
#define WO4  (Dv * VOCABv / 4)
#define TOT4 (QKV4 + WU4 + WD4 + WO4)
#define BIA4 (Lv * QKVN / 4)

// -------------------- scratch (device globals; no allocs) --------------------
__device__ float g_x[NTOK * Dv];
__device__ float g_a[NTOK * Dv];
__device__ float g_qkv[NTOK * QKVN];
__device__ float g_qf[NTOK * Dv];
__device__ float g_kf[NTOK * Dv];
__device__ float g_S[Bv * Hv * NCHUNK * HDv * HDv];
__device__ float g_z[Bv * Hv * NCHUNK * HDv];
__device__ float g_bqkv[Lv * QKVN];
__device__ float g_part[2 * NTOK * Dv];
__device__ __half g_xh[NTOK * Dv];
__device__ __half g_xl[NTOK * Dv];
__device__ __half g_hh[NTOK * FFNv];
__device__ __half g_wh[W_TOTAL];

__device__ __forceinline__ void split_fp16(float v, __half& h, __half& l) {
    h = __float2half_rn(v);
    l = __float2half_rn(v - __half2float(h));
}

// -------------------- ONE fused weight conversion + bias pack --------------------
__global__ void convw_all(const float* __restrict__ Wq, const float* __restrict__ Wk,
                          const float* __restrict__ Wv, const float* __restrict__ WU,
                          const float* __restrict__ WV, const float* __restrict__ Wout,
                          const float* __restrict__ bq, const float* __restrict__ bk,
                          const float* __restrict__ bvp) {
    int idx = blockIdx.x * blockDim.x + threadIdx.x;
    if (idx < TOT4) {
        const float* src;
        int e;
        if (idx < QKV4) {
            e = idx * 4;
            int l = e / (Dv * QKVN);
            int r = e % (Dv * QKVN);
            int k = r / QKVN, col = r % QKVN;
            if (col < 512)       src = Wq + (size_t)l * Dv * Dv + k * 512 + col;
            else if (col < 1024) src = Wk + (size_t)l * Dv * Dv + k * 512 + col - 512;
            else                 src = Wv + (size_t)l * Dv * Dv + k * 512 + col - 1024;
            e += OFF_QKV;
        } else if (idx < QKV4 + WU4) {
            int e2 = (idx - QKV4) * 4;
            src = WU + e2;
            e = OFF_WU + e2;
        } else if (idx < QKV4 + WU4 + WD4) {
            int e2 = (idx - QKV4 - WU4) * 4;
            src = WV + e2;
            e = OFF_WD + e2;
        } else {
            int e2 = (idx - QKV4 - WU4 - WD4) * 4;
            src = Wout + e2;
            e = OFF_WO + e2;
        }
        float4 v = *(const float4*)src;
        ((__half2*)(g_wh + e))[0] = __half2(__float2half_rn(v.x), __float2half_rn(v.y));
        ((__half2*)(g_wh + e))[1] = __half2(__float2half_rn(v.z), __float2half_rn(v.w));
    } else if (idx < TOT4 + BIA4) {
        int j = (idx - TOT4) * 4;
#pragma unroll
        for (int q = 0; q < 4; q++) {
            int jj = j + q;
            int l = jj / QKVN, c = jj % QKVN;
            float v;
            if (c < 512) v = bq[l * Dv + c];
            else if (c < 1024) v = bk[l * Dv + c - 512];
            else v = bvp[l * Dv + c - 1024];
            g_bqkv[jj] = v;
        }
    }
}

// -------------------- embedding + sinusoidal positions --------------------
__global__ void embed_kernel(const int* __restrict__ tokens,
                             const float* __restrict__ emb) {
    int idx = blockIdx.x * blockDim.x + threadIdx.x;
    if (idx >= NTOK * Dv) return;
    int n = idx >> 9;
    int j = idx & 511;
    int t = n & (Tv - 1);
    float val;
    const float c = 9.210340371976184f / 256.f;
    if (j < 256) {
        int tok = tokens[n];
        val = emb[tok * 256 + j];
    } else if (j < 384) {
        int i = j - 256;
        val = sinf((float)t * expf(-(2.f * (float)i) * c));
    } else {
        int i = j - 384;
        val = cosf((float)t * expf(-(2.f * (float)i) * c));
    }
    g_x[idx] = val;
    __half h, l;
    split_fp16(val, h, l);
    g_xh[idx] = h;
    g_xl[idx] = l;
}

// -------------------- tensor-core GEMM, fp16, BK=64, 2-stage cp.async ----------
__device__ __forceinline__ void ldsm_x4(uint32_t* r, const void* p) {
    uint32_t a = (uint32_t)__cvta_generic_to_shared(p);
    asm volatile("ldmatrix.sync.aligned.m8n8.x4.shared.b16 {%0,%1,%2,%3},[%4];"
        : "=r"(r[0]), "=r"(r[1]), "=r"(r[2]), "=r"(r[3]) : "r"(a));
}
__device__ __forceinline__ void ldsm_x4_t(uint32_t* r, const void* p) {
    uint32_t a = (uint32_t)__cvta_generic_to_shared(p);
    asm volatile("ldmatrix.sync.aligned.m8n8.x4.trans.shared.b16 {%0,%1,%2,%3},[%4];"
        : "=r"(r[0]), "=r"(r[1]), "=r"(r[2]), "=r"(r[3]) : "r"(a));
}
__device__ __forceinline__ void mma16816(float* c, const uint32_t* a, const uint32_t* b) {
    asm volatile("mma.sync.aligned.m16n8k16.row.col.f32.f16.f16.f32 "
        "{%0,%1,%2,%3},{%4,%5,%6,%7},{%8,%9},{%0,%1,%2,%3};"
        : "+f"(c[0]), "+f"(c[1]), "+f"(c[2]), "+f"(c[3])
        : "r"(a[0]), "r"(a[1]), "r"(a[2]), "r"(a[3]), "r"(b[0]), "r"(b[1]));
}
__device__ __forceinline__ void cp16(void* smem, const void* gmem) {
    uint32_t s = (uint32_t)__cvta_generic_to_shared(smem);
    asm volatile("cp.async.cg.shared.global [%0], [%1], 16;" :: "r"(s), "l"(gmem));
}
#define CP_COMMIT() asm volatile("cp.async.commit_group;")
#define CP_WAIT(n)  asm volatile("cp.async.wait_group %0;" :: "n"(n))

#define PADA 72
#define PADB 136
#define A_TILE 36864
#define B_TILE 34816

// mode 0: fp32 out + bias. mode 1: gelu -> fp16 (Ch). mode 2: split-K partials (no bias).
template <int TERMS>
__global__ void __launch_bounds__(256, 2)
gemm_tc(const __half* __restrict__ Ahg, const __half* __restrict__ Alg,
        const __half* __restrict__ Bhg,
        const float* __restrict__ bias, float* __restrict__ C,
        __half* __restrict__ Ch,
        int M, int N, int lda, int ldb, int Kext, int mode) {
    extern __shared__ char smraw[];
    __half* AsH = (__half*)(smraw);
    __half* AsL = (__half*)(smraw + A_TILE);
    __half* BsH = (__half*)(smraw + (TERMS == 2 ? 2 * A_TILE : A_TILE));

    if (mode == 2) {
        size_t ko = (size_t)blockIdx.z * Kext;
        Ahg += ko;
        if (TERMS == 2) Alg += ko;
        Bhg += ko * ldb;
        C += (size_t)blockIdx.z * M * N;
    }

    int tid = threadIdx.x;
    int wid = tid >> 5, lane = tid & 31;
    int m_w = (wid >> 1) * 32, n_w = (wid & 1) * 64;
    int row0 = blockIdx.y * 128, col0 = blockIdx.x * 128;

    float acc[2][8][4];
#pragma unroll
    for (int i = 0; i < 2; i++)
#pragma unroll
        for (int j = 0; j < 8; j++)
#pragma unroll
            for (int q = 0; q < 4; q++) acc[i][j][q] = 0.f;

    int a_row = tid >> 1, a_colb = (tid & 1) * 32;
    int b_row = tid >> 2, b_colb = (tid & 3) * 32;

    auto loadStage = [&](int stage, int buf) {
        int k0 = stage * 64;
        const __half* aH = Ahg + (size_t)(row0 + a_row) * lda + k0 + a_colb;
        int sa = (buf * 128 + a_row) * PADA + a_colb;
        const __half* bH = Bhg + (size_t)(k0 + b_row) * ldb + col0 + b_colb;
        int sb = (buf * 64 + b_row) * PADB + b_colb;
#pragma unroll
        for (int i = 0; i < 4; i++) {
            cp16(AsH + sa + i * 8, aH + i * 8);
            cp16(BsH + sb + i * 8, bH + i * 8);
        }
        if (TERMS == 2) {
            const __half* aL = Alg + (size_t)(row0 + a_row) * lda + k0 + a_colb;
#pragma unroll
            for (int i = 0; i < 4; i++) cp16(AsL + sa + i * 8, aL + i * 8);
        }
        CP_COMMIT();
    };

    auto compute = [&](int buf) {
#pragma unroll
        for (int kk = 0; kk < 64; kk += 16) {
            uint32_t Ahf[2][4], Alf[2][4], Bhf[8][2];
#pragma unroll
            for (int i = 0; i < 2; i++) {
                int idx = (buf * 128 + m_w + i * 16 + (lane & 15)) * PADA + kk + (lane >> 4) * 8;
                ldsm_x4(Ahf[i], AsH + idx);
                if (TERMS == 2) ldsm_x4(Alf[i], AsL + idx);
            }
#pragma unroll
            for (int p = 0; p < 4; p++) {
                int idx = (buf * 64 + kk + (lane & 15)) * PADB + n_w + p * 16 + (lane >> 4) * 8;
                uint32_t r[4];
                ldsm_x4_t(r, BsH + idx);
                Bhf[2 * p][0] = r[0]; Bhf[2 * p][1] = r[1];
                Bhf[2 * p + 1][0] = r[2]; Bhf[2 * p + 1][1] = r[3];
            }
#pragma unroll
            for (int i = 0; i < 2; i++)
#pragma unroll
                for (int j = 0; j < 8; j++) {
                    mma16816(acc[i][j], Ahf[i], Bhf[j]);
                    if (TERMS == 2) mma16816(acc[i][j], Alf[i], Bhf[j]);
                }
        }
    };

    int nsteps = Kext >> 6;
    loadStage(0, 0);
    for (int s = 0; s < nsteps; s++) {
        CP_WAIT(0);
        __syncthreads();
        if (s + 1 < nsteps) loadStage(s + 1, (s + 1) & 1);
        compute(s & 1);
    }

    int g = lane >> 2, tg = lane & 3;
#pragma unroll
    for (int i = 0; i < 2; i++) {
#pragma unroll
        for (int j = 0; j < 8; j++) {
            int cc = col0 + n_w + j * 8 + tg * 2;
            float b0 = 0.f, b1 = 0.f;
            if (mode != 2) { b0 = bias[cc]; b1 = bias[cc + 1]; }
#pragma unroll
            for (int half = 0; half < 2; half++) {
                int r = row0 + m_w + i * 16 + g + half * 8;
                float v0 = acc[i][j][half * 2 + 0] + b0;
                float v1 = acc[i][j][half * 2 + 1] + b1;
                if (mode == 1) {
                    v0 = 0.5f * v0 * (1.f + erff(v0 * 0.7071067811865475f));
                    v1 = 0.5f * v1 * (1.f + erff(v1 * 0.7071067811865475f));
                    *(__half2*)(Ch + (size_t)r * N + cc) =
                        __half2(__float2half_rn(v0), __float2half_rn(v1));
                } else {
                    *(float2*)(C + (size_t)r * N + cc) = make_float2(v0, v1);
                }
            }
        }
    }
}

// -------------------- generic split-K=2 reduce + bias (N = power of 2) ----------
__global__ void reduce2(const float* __restrict__ part, const float* __restrict__ bias,
                        float* __restrict__ out, int total4, int nmask) {
    int i = blockIdx.x * blockDim.x + threadIdx.x;
    if (i >= total4) return;
    float4 a = ((const float4*)part)[i];
    float4 b = ((const float4*)part)[i + total4];
    int col = (i * 4) & nmask;
    float4 o;
    o.x = a.x + b.x + bias[col + 0];
    o.y = a.y + b.y + bias[col + 1];
    o.z = a.z + b.z + bias[col + 2];
    o.w = a.w + b.w + bias[col + 3];
    ((float4*)out)[i] = o;
}

// -------------------- fused FAVOR+ features + per-chunk sums (LDS-amortized) -----
// grid (NTOK/128, Hv), 128 threads. Block handles 128 tokens = 4 chunks; rf staged
// once. Thread tile: 4 rows x 4 m (features), then the chunk outer-product.
__global__ void __launch_bounds__(128)
favor_chunk(const float* __restrict__ rfs) {
    int tile = blockIdx.x, h = blockIdx.y;
    int b = tile >> 4, blk = tile & 15;   // 16 tiles per batch (Tv/128)
    int bh = b * Hv + h;
    __shared__ float rf[64][64];
    __shared__ float sq[32][68], sk[32][68];
    int tid = threadIdx.x;
    const float* rfh = rfs + h * 4096;
    for (int i = tid; i < 4096; i += 128) rf[i >> 6][i & 63] = rfh[i];
    const float sc = 0.3535533905932738f;
    int rg = tid >> 4, mg = tid & 15;
    int r0 = rg * 4, m0 = mg * 4;
    int om0 = (tid >> 3) * 4, od0 = (tid & 7) * 8;

    for (int cc = 0; cc < 4; cc++) {
        int c = blk * 4 + cc;
        int t0 = c * CHUNK;
        __syncthreads();   // prev iter reads done (iter 0: pairs with rf staging)
        for (int i = tid; i < 512; i += 128) {
            int tl = i >> 4, c4 = (i & 15) * 4;
            size_t gq = (size_t)(b * Tv + t0 + tl) * QKVN + h * HDv + c4;
            float4 qv = *(const float4*)(g_qkv + gq);
            float4 kv = *(const float4*)(g_qkv + gq + 512);
            qv.x *= sc; qv.y *= sc; qv.z *= sc; qv.w *= sc;
            kv.x *= sc; kv.y *= sc; kv.z *= sc; kv.w *= sc;
            *(float4*)&sq[tl][c4] = qv;
            *(float4*)&sk[tl][c4] = kv;
        }
        __syncthreads();

        // features: 4 rows x 4 m per thread
        float dq[4][4], dk[4][4], s2q[4], s2k[4];
#pragma unroll
        for (int r = 0; r < 4; r++) {
            s2q[r] = 0.f; s2k[r] = 0.f;
#pragma unroll
            for (int q = 0; q < 4; q++) { dq[r][q] = 0.f; dk[r][q] = 0.f; }
        }
#pragma unroll 4
        for (int d4 = 0; d4 < 16; d4++) {
            float4 rfv[4];
#pragma unroll
            for (int j = 0; j < 4; j++) rfv[j] = *(const float4*)&rf[d4 * 4 + j][m0];
#pragma unroll
            for (int r = 0; r < 4; r++) {
                float4 qv = *(const float4*)&sq[r0 + r][d4 * 4];
                float4 kv = *(const float4*)&sk[r0 + r][d4 * 4];
                float qa[4] = {qv.x, qv.y, qv.z, qv.w};
                float ka[4] = {kv.x, kv.y, kv.z, kv.w};
#pragma unroll
                for (int j = 0; j < 4; j++) {
                    float rr[4] = {rfv[j].x, rfv[j].y, rfv[j].z, rfv[j].w};
#pragma unroll
                    for (int q = 0; q < 4; q++) {
                        dq[r][q] += qa[j] * rr[q];
                        dk[r][q] += ka[j] * rr[q];
                    }
                    s2q[r] += qa[j] * qa[j];
                    s2k[r] += ka[j] * ka[j];
                }
            }
        }
        float qfv[4][4], kfv[4][4];
#pragma unroll
        for (int r = 0; r < 4; r++) {
            float hq = 0.5f * s2q[r], hk = 0.5f * s2k[r];
#pragma unroll
            for (int q = 0; q < 4; q++) {
                qfv[r][q] = expf(dq[r][q] - hq);
                kfv[r][q] = expf(dk[r][q] - hk);
            }
        }
#pragma unroll
        for (int r = 0; r < 4; r++) {
            size_t base = (size_t)(b * Tv + t0 + r0 + r) * Dv + h * HDv + m0;
            *(float4*)(g_qf + base) = make_float4(qfv[r][0], qfv[r][1], qfv[r][2], qfv[r][3]);
            *(float4*)(g_kf + base) = make_float4(kfv[r][0], kfv[r][1], kfv[r][2], kfv[r][3]);
        }
        __syncthreads();   // done reading sq/sk

        // stash kf -> sk ; V -> sq
#pragma unroll
        for (int r = 0; r < 4; r++)
            *(float4*)&sk[r0 + r][m0] = make_float4(kfv[r][0], kfv[r][1], kfv[r][2], kfv[r][3]);
        for (int i = tid; i < 512; i += 128) {
            int tl = i >> 4, c4 = (i & 15) * 4;
            size_t vb = (size_t)(b * Tv + t0 + tl) * QKVN + 1024 + h * HDv + c4;
            *(float4*)&sq[tl][c4] = *(const float4*)(g_qkv + vb);
        }
        __syncthreads();

        // chunk outer-product sums: S_c[m][d] = sum_t kf[t][m] V[t][d]
        float acc[4][8];
#pragma unroll
        for (int r = 0; r < 4; r++)
#pragma unroll
            for (int q = 0; q < 8; q++) acc[r][q] = 0.f;
#pragma unroll 8
        for (int t = 0; t < 32; t++) {
            float4 km = *(const float4*)&sk[t][om0];
            float4 v0 = *(const float4*)&sq[t][od0];
            float4 v1 = *(const float4*)&sq[t][od0 + 4];
            float kr[4] = {km.x, km.y, km.z, km.w};
            float vr[8] = {v0.x, v0.y, v0.z, v0.w, v1.x, v1.y, v1.z, v1.w};
#pragma unroll
            for (int r = 0; r < 4; r++)
#pragma unroll
                for (int q = 0; q < 8; q++) acc[r][q] += kr[r] * vr[q];
        }
        int sb = (bh * NCHUNK + c) * 4096;
#pragma unroll
        for (int r = 0; r < 4; r++) {
            *(float4*)(g_S + sb + (om0 + r) * 64 + od0) =
                make_float4(acc[r][0], acc[r][1], acc[r][2], acc[r][3]);
            *(float4*)(g_S + sb + (om0 + r) * 64 + od0 + 4) =
                make_float4(acc[r][4], acc[r][5], acc[r][6], acc[r][7]);
        }
        if (tid < 64) {
            float z = 0.f;
#pragma unroll
            for (int t = 0; t < 32; t++) z += sk[t][tid];
            g_z[(bh * NCHUNK + c) * 64 + tid] = z;
        }
    }
}

// -------------------- exclusive scans over chunks (S and z fused) ---------------
__global__ void __launch_bounds__(64)
attn_scan() {
    int bh = blockIdx.x >> 6, m = blockIdx.x & 63, d = threadIdx.x;
    float v[NCHUNK];
#pragma unroll
    for (int c = 0; c < NCHUNK; c++)
        v[c] = g_S[((bh * NCHUNK + c) << 12) + m * 64 + d];
    float acc = 0.f;
#pragma unroll
    for (int c = 0; c < NCHUNK; c++) {
        g_S[((bh * NCHUNK + c) << 12) + m * 64 + d] = acc;
        acc += v[c];
    }
    if (m == 0) {
        float zv[NCHUNK];
#pragma unroll
        for (int c = 0; c < NCHUNK; c++) zv[c] = g_z[(bh * NCHUNK + c) * 64 + d];
        float za = 0.f;
#pragma unroll
        for (int c = 0; c < NCHUNK; c++) {
            g_z[(bh * NCHUNK + c) * 64 + d] = za;
            za += zv[c];
        }
    }
}

// -------------------- chunked-GEMM apply --------------------
__global__ void __launch_bounds__(128)
attn_apply() {
    int c = blockIdx.x, bh = blockIdx.y;
    int b = bh / Hv, h = bh % Hv;
    int tid = threadIdx.x;
    __shared__ float Qf[32][68], Kf[32][68], V[32][68];
    __shared__ float S0[64][68];
    __shared__ float A[32][36];
    __shared__ float z0[64], sden[32];
    int t0 = c * CHUNK;
    int sb = (bh * NCHUNK + c) * 4096;

    for (int i = tid; i < 512; i += 128) {
        int row = i >> 4, c4 = (i & 15) * 4;
        size_t qb = (size_t)(b * Tv + t0 + row) * Dv + h * HDv + c4;
        size_t vb = (size_t)(b * Tv + t0 + row) * QKVN + 1024 + h * HDv + c4;
        *(float4*)&Qf[row][c4] = *(const float4*)(g_qf + qb);
        *(float4*)&Kf[row][c4] = *(const float4*)(g_kf + qb);
        *(float4*)&V[row][c4] = *(const float4*)(g_qkv + vb);
    }
    for (int i = tid; i < 1024; i += 128) {
        int m = i >> 4, c4 = (i & 15) * 4;
        *(float4*)&S0[m][c4] = *(const float4*)(g_S + sb + m * 64 + c4);
    }
    if (tid < 16)
        *(float4*)&z0[tid * 4] = *(const float4*)(g_z + (bh * NCHUNK + c) * 64 + tid * 4);
    __syncthreads();

    int i0 = (tid >> 4) * 4;
    int j0 = tid & 15;
    {
        float a0[4] = {0.f, 0.f, 0.f, 0.f}, a1[4] = {0.f, 0.f, 0.f, 0.f};
#pragma unroll
        for (int k = 0; k < 64; k += 4) {
            float4 ka = *(const float4*)&Kf[j0][k];
            float4 kb = *(const float4*)&Kf[j0 + 16][k];
#pragma unroll
            for (int r = 0; r < 4; r++) {
                float4 q = *(const float4*)&Qf[i0 + r][k];
                a0[r] += q.x * ka.x + q.y * ka.y + q.z * ka.z + q.w * ka.w;
                a1[r] += q.x * kb.x + q.y * kb.y + q.z * kb.z + q.w * kb.w;
            }
        }
#pragma unroll
        for (int r = 0; r < 4; r++) {
            A[i0 + r][j0] = (j0 <= i0 + r) ? a0[r] : 0.f;
            A[i0 + r][j0 + 16] = (j0 + 16 <= i0 + r) ? a1[r] : 0.f;
        }
    }
    __syncthreads();

    if (tid < 32) {
        float dn = 1e-16f;
#pragma unroll 8
        for (int m = 0; m < 64; m++) dn += Qf[tid][m] * z0[m];
#pragma unroll
        for (int j = 0; j < 32; j++) dn += A[tid][j];
        sden[tid] = dn;
    }

    int d0 = (tid & 15) * 4;
    float acc[4][4];
#pragma unroll
    for (int r = 0; r < 4; r++)
#pragma unroll
        for (int q = 0; q < 4; q++) acc[r][q] = 0.f;
#pragma unroll 4
    for (int m = 0; m < 64; m += 4) {
        float4 qv[4], sv[4];
#pragma unroll
        for (int r = 0; r < 4; r++) qv[r] = *(const float4*)&Qf[i0 + r][m];
#pragma unroll
        for (int kk = 0; kk < 4; kk++) sv[kk] = *(const float4*)&S0[m + kk][d0];
#pragma unroll
        for (int r = 0; r < 4; r++) {
            float qr[4] = {qv[r].x, qv[r].y, qv[r].z, qv[r].w};
#pragma unroll
            for (int kk = 0; kk < 4; kk++) {
                acc[r][0] += qr[kk] * sv[kk].x;
                acc[r][1] += qr[kk] * sv[kk].y;
                acc[r][2] += qr[kk] * sv[kk].z;
                acc[r][3] += qr[kk] * sv[kk].w;
            }
        }
    }
#pragma unroll 2
    for (int j = 0; j < 32; j += 4) {
        float4 av[4], vv[4];
#pragma unroll
        for (int r = 0; r < 4; r++) av[r] = *(const float4*)&A[i0 + r][j];
#pragma unroll
        for (int kk = 0; kk < 4; kk++) vv[kk] = *(const float4*)&V[j + kk][d0];
#pragma unroll
        for (int r = 0; r < 4; r++) {
            float ar[4] = {av[r].x, av[r].y, av[r].z, av[r].w};
#pragma unroll
            for (int kk = 0; kk < 4; kk++) {
                acc[r][0] += ar[kk] * vv[kk].x;
                acc[r][1] += ar[kk] * vv[kk].y;
                acc[r][2] += ar[kk] * vv[kk].z;
                acc[r][3] += ar[kk] * vv[kk].w;
            }
        }
    }
    __syncthreads();
#pragma unroll
    for (int r = 0; r < 4; r++) {
        float inv = 1.f / sden[i0 + r];
        float4 o = make_float4(acc[r][0] * inv, acc[r][1] * inv,
                               acc[r][2] * inv, acc[r][3] * inv);
        *(float4*)(g_a + (size_t)(b * Tv + t0 + i0 + r) * Dv + h * HDv + d0) = o;
    }
}

// -------------------- LayerNorm + residual add (+ fp16 hi/lo of new x) ----------
__global__ void __launch_bounds__(128)
ln_add(const float* __restrict__ a, const float* __restrict__ g,
       const float* __restrict__ bl, float* __restrict__ x) {
    int n = blockIdx.x, tid = threadIdx.x;
    int lane = tid & 31, w = tid >> 5;
    const float* ar = a + (size_t)n * Dv;
    float v[4];
    float s = 0.f, s2 = 0.f;
#pragma unroll
    for (int i = 0; i < 4; i++) {
        float t = ar[tid + i * 128];
        v[i] = t;
        s += t;
        s2 += t * t;
    }
    __shared__ float sh[8];
#pragma unroll
    for (int off = 16; off; off >>= 1) {
        s += __shfl_down_sync(0xffffffffu, s, off);
        s2 += __shfl_down_sync(0xffffffffu, s2, off);
    }
    if (lane == 0) { sh[w] = s; sh[4 + w] = s2; }
    __syncthreads();
    float S = sh[0] + sh[1] + sh[2] + sh[3];
    float S2 = sh[4] + sh[5] + sh[6] + sh[7];
    float mu = S * (1.f / Dv);
    float var = S2 * (1.f / Dv) - mu * mu;
    float rs = rsqrtf(var + 1e-5f);
#pragma unroll
    for (int i = 0; i < 4; i++) {
        int j = tid + i * 128;
        size_t idx = (size_t)n * Dv + j;
        float nv = x[idx] + (v[i] - mu) * rs * g[j] + bl[j];
        x[idx] = nv;
        __half h, l;
        split_fp16(nv, h, l);
        g_xh[idx] = h;
        g_xl[idx] = l;
    }
}

// -------------------- host driver --------------------
extern "C" void kernel_launch(void* const* d_in, const int* in_sizes, int n_in,
                              void* d_out, int out_size) {
    const int*   tokens = (const int*)d_in[0];
    const float* emb    = (const float*)d_in[1];
    const float* Wq     = (const float*)d_in[2];
    const float* bq     = (const float*)d_in[3];
    const float* Wk     = (const float*)d_in[4];
    const float* bk     = (const float*)d_in[5];
    const float* Wv     = (const float*)d_in[6];
    const float* bvp    = (const float*)d_in[7];
    const float* rfs    = (const float*)d_in[8];
    const float* ln1g   = (const float*)d_in[9];
    const float* ln1b   = (const float*)d_in[10];
    const float* ln2g   = (const float*)d_in[11];
    const float* ln2b   = (const float*)d_in[12];
    const float* WU     = (const float*)d_in[13];
    const float* bU     = (const float*)d_in[14];
    const float* WV     = (const float*)d_in[15];
    const float* bV     = (const float*)d_in[16];
    const float* Wout   = (const float*)d_in[17];
    const float* bout   = (const float*)d_in[18];
    float* out = (float*)d_out;

    static float *px = nullptr, *pa, *pqkv, *pbqkv, *ppart;
    static __half *pxh, *pxl, *phh, *pwh;
    if (!px) {
        cudaGetSymbolAddress((void**)&px, g_x);
        cudaGetSymbolAddress((void**)&pa, g_a);
        cudaGetSymbolAddress((void**)&pqkv, g_qkv);
        cudaGetSymbolAddress((void**)&pbqkv, g_bqkv);
        cudaGetSymbolAddress((void**)&ppart, g_part);
        cudaGetSymbolAddress((void**)&pxh, g_xh);
        cudaGetSymbolAddress((void**)&pxl, g_xl);
        cudaGetSymbolAddress((void**)&phh, g_hh);
        cudaGetSymbolAddress((void**)&pwh, g_wh);
        cudaFuncSetAttribute(gemm_tc<1>, cudaFuncAttributeMaxDynamicSharedMemorySize,
                             A_TILE + B_TILE);
        cudaFuncSetAttribute(gemm_tc<2>, cudaFuncAttributeMaxDynamicSharedMemorySize,
                             2 * A_TILE + B_TILE);
    }

    convw_all<<<(TOT4 + BIA4 + 255) / 256, 256>>>(Wq, Wk, Wv, WU, WV, Wout, bq, bk, bvp);
    embed_kernel<<<(NTOK * Dv + 255) / 256, 256>>>(tokens, emb);

    for (int l = 0; l < Lv; l++) {
        gemm_tc<1><<<dim3(QKVN / 128, NTOK / 128), 256, A_TILE + B_TILE>>>(
            pxh, nullptr, pwh + OFF_QKV + (size_t)l * Dv * QKVN, pbqkv + l * QKVN,
            pqkv, nullptr, NTOK, QKVN, Dv, QKVN, Dv, 0);

        favor_chunk<<<dim3(NTOK / 128, Hv), 128>>>(rfs + (size_t)l * Hv * HDv * HDv);
        attn_scan<<<Bv * Hv * HDv, 64>>>();
        attn_apply<<<dim3(NCHUNK, Bv * Hv), 128>>>();

        ln_add<<<NTOK, 128>>>(pa, ln1g + l * Dv, ln1b + l * Dv, px);

        gemm_tc<1><<<dim3(FFNv / 128, NTOK / 128), 256, A_TILE + B_TILE>>>(
            pxh, nullptr, pwh + OFF_WU + (size_t)l * Dv * FFNv, bU + l * FFNv,
            nullptr, phh, NTOK, FFNv, Dv, FFNv, Dv, 1);

        gemm_tc<1><<<dim3(Dv / 128, NTOK / 128, 2), 256, A_TILE + B_TILE>>>(
            phh, nullptr, pwh + OFF_WD + (size_t)l * FFNv * Dv, nullptr,
            ppart, nullptr, NTOK, Dv, FFNv, Dv, 1024, 2);
        reduce2<<<(NTOK * Dv / 4 + 255) / 256, 256>>>(ppart, bV + l * Dv, pa,
                                                      NTOK * Dv / 4, Dv - 1);

        ln_add<<<NTOK, 128>>>(pa, ln2g + l * Dv, ln2b + l * Dv, px);
    }

    gemm_tc<2><<<dim3(VOCABv / 128, NTOK / 128, 2), 256, 2 * A_TILE + B_TILE>>>(
        pxh, pxl, pwh + OFF_WO, nullptr, ppart, nullptr,
        NTOK, VOCABv, Dv, VOCABv, 256, 2);
    reduce2<<<(NTOK * VOCABv / 4 + 255) / 256, 256>>>(ppart, bout, out,
                                                      NTOK * VOCABv / 4, VOCABv - 1);
}

// round 12
// speedup vs baseline: 2.0974x; 1.0642x over previous
#include <cuda_runtime.h>
#include <cuda_fp16.h>
#include <math.h>
#include <stdint.h>

// Problem constants
#define Bv      2
#define Tv      2048
#define NTOK    (Bv * Tv)      // 4096
#define Dv      512
#define Hv      8
#define HDv     64
#define FFNv    2048
#define VOCABv  256
#define Lv      2
#define CHUNK   32
#define NCHUNK  (Tv / CHUNK)   // 64
#define QKVN    1536

// weight region offsets (elements) in the fp16 weight pool ([K,N] row-major)
#define OFF_QKV 0
#define OFF_WU  (OFF_QKV + Lv * Dv * QKVN)
#define OFF_WD  (OFF_WU + Lv * Dv * FFNv)
#define OFF_WO  (OFF_WD + Lv * FFNv * Dv)
#define W_TOTAL (OFF_WO + Dv * VOCABv)

#define QKV4 (Lv * Dv * QKVN / 4)
#define WU4  (Lv * Dv * FFNv / 4)
#define WD4  (Lv * FFNv * Dv / 4)
#define WO4  (Dv * VOCABv / 4)
#define TOT4 (QKV4 + WU4 + WD4 + WO4)
#define BIA4 (Lv * QKVN / 4)

// -------------------- scratch (device globals; no allocs) --------------------
__device__ float g_x[NTOK * Dv];
__device__ float g_a[NTOK * Dv];
__device__ float g_qkv[NTOK * QKVN];
__device__ float g_qf[NTOK * Dv];
__device__ float g_kf[NTOK * Dv];
__device__ float g_S[Bv * Hv * NCHUNK * HDv * HDv];
__device__ float g_z[Bv * Hv * NCHUNK * HDv];
__device__ float g_bqkv[Lv * QKVN];
__device__ float g_part[2 * NTOK * Dv];
__device__ __half g_xh[NTOK * Dv];
__device__ __half g_xl[NTOK * Dv];
__device__ __half g_hh[NTOK * FFNv];
__device__ __half g_wh[W_TOTAL];

__device__ __forceinline__ void split_fp16(float v, __half& h, __half& l) {
    h = __float2half_rn(v);
    l = __float2half_rn(v - __half2float(h));
}

// -------------------- ONE fused weight conversion + bias pack --------------------
__global__ void convw_all(const float* __restrict__ Wq, const float* __restrict__ Wk,
                          const float* __restrict__ Wv, const float* __restrict__ WU,
                          const float* __restrict__ WV, const float* __restrict__ Wout,
                          const float* __restrict__ bq, const float* __restrict__ bk,
                          const float* __restrict__ bvp) {
    int idx = blockIdx.x * blockDim.x + threadIdx.x;
    if (idx < TOT4) {
        const float* src;
        int e;
        if (idx < QKV4) {
            e = idx * 4;
            int l = e / (Dv * QKVN);
            int r = e % (Dv * QKVN);
            int k = r / QKVN, col = r % QKVN;
            if (col < 512)       src = Wq + (size_t)l * Dv * Dv + k * 512 + col;
            else if (col < 1024) src = Wk + (size_t)l * Dv * Dv + k * 512 + col - 512;
            else                 src = Wv + (size_t)l * Dv * Dv + k * 512 + col - 1024;
            e += OFF_QKV;
        } else if (idx < QKV4 + WU4) {
            int e2 = (idx - QKV4) * 4;
            src = WU + e2;
            e = OFF_WU + e2;
        } else if (idx < QKV4 + WU4 + WD4) {
            int e2 = (idx - QKV4 - WU4) * 4;
            src = WV + e2;
            e = OFF_WD + e2;
        } else {
            int e2 = (idx - QKV4 - WU4 - WD4) * 4;
            src = Wout + e2;
            e = OFF_WO + e2;
        }
        float4 v = *(const float4*)src;
        ((__half2*)(g_wh + e))[0] = __half2(__float2half_rn(v.x), __float2half_rn(v.y));
        ((__half2*)(g_wh + e))[1] = __half2(__float2half_rn(v.z), __float2half_rn(v.w));
    } else if (idx < TOT4 + BIA4) {
        int j = (idx - TOT4) * 4;
#pragma unroll
        for (int q = 0; q < 4; q++) {
            int jj = j + q;
            int l = jj / QKVN, c = jj % QKVN;
            float v;
            if (c < 512) v = bq[l * Dv + c];
            else if (c < 1024) v = bk[l * Dv + c - 512];
            else v = bvp[l * Dv + c - 1024];
            g_bqkv[jj] = v;
        }
    }
}

// -------------------- embedding + sinusoidal positions --------------------
__global__ void embed_kernel(const int* __restrict__ tokens,
                             const float* __restrict__ emb) {
    int idx = blockIdx.x * blockDim.x + threadIdx.x;
    if (idx >= NTOK * Dv) return;
    int n = idx >> 9;
    int j = idx & 511;
    int t = n & (Tv - 1);
    float val;
    const float c = 9.210340371976184f / 256.f;
    if (j < 256) {
        int tok = tokens[n];
        val = emb[tok * 256 + j];
    } else if (j < 384) {
        int i = j - 256;
        val = sinf((float)t * expf(-(2.f * (float)i) * c));
    } else {
        int i = j - 384;
        val = cosf((float)t * expf(-(2.f * (float)i) * c));
    }
    g_x[idx] = val;
    __half h, l;
    split_fp16(val, h, l);
    g_xh[idx] = h;
    g_xl[idx] = l;
}

// -------------------- tensor-core GEMM, fp16, BK=64, 2-stage cp.async ----------
__device__ __forceinline__ void ldsm_x4(uint32_t* r, const void* p) {
    uint32_t a = (uint32_t)__cvta_generic_to_shared(p);
    asm volatile("ldmatrix.sync.aligned.m8n8.x4.shared.b16 {%0,%1,%2,%3},[%4];"
        : "=r"(r[0]), "=r"(r[1]), "=r"(r[2]), "=r"(r[3]) : "r"(a));
}
__device__ __forceinline__ void ldsm_x4_t(uint32_t* r, const void* p) {
    uint32_t a = (uint32_t)__cvta_generic_to_shared(p);
    asm volatile("ldmatrix.sync.aligned.m8n8.x4.trans.shared.b16 {%0,%1,%2,%3},[%4];"
        : "=r"(r[0]), "=r"(r[1]), "=r"(r[2]), "=r"(r[3]) : "r"(a));
}
__device__ __forceinline__ void mma16816(float* c, const uint32_t* a, const uint32_t* b) {
    asm volatile("mma.sync.aligned.m16n8k16.row.col.f32.f16.f16.f32 "
        "{%0,%1,%2,%3},{%4,%5,%6,%7},{%8,%9},{%0,%1,%2,%3};"
        : "+f"(c[0]), "+f"(c[1]), "+f"(c[2]), "+f"(c[3])
        : "r"(a[0]), "r"(a[1]), "r"(a[2]), "r"(a[3]), "r"(b[0]), "r"(b[1]));
}
__device__ __forceinline__ void cp16(void* smem, const void* gmem) {
    uint32_t s = (uint32_t)__cvta_generic_to_shared(smem);
    asm volatile("cp.async.cg.shared.global [%0], [%1], 16;" :: "r"(s), "l"(gmem));
}
#define CP_COMMIT() asm volatile("cp.async.commit_group;")
#define CP_WAIT(n)  asm volatile("cp.async.wait_group %0;" :: "n"(n))

#define PADA 72
#define PADB 136
#define A_TILE 36864
#define B_TILE 34816

// mode 0: fp32 out + bias. mode 1: gelu -> fp16 (Ch). mode 2: split-K partials (no bias).
template <int TERMS>
__global__ void __launch_bounds__(256, 2)
gemm_tc(const __half* __restrict__ Ahg, const __half* __restrict__ Alg,
        const __half* __restrict__ Bhg,
        const float* __restrict__ bias, float* __restrict__ C,
        __half* __restrict__ Ch,
        int M, int N, int lda, int ldb, int Kext, int mode) {
    extern __shared__ char smraw[];
    __half* AsH = (__half*)(smraw);
    __half* AsL = (__half*)(smraw + A_TILE);
    __half* BsH = (__half*)(smraw + (TERMS == 2 ? 2 * A_TILE : A_TILE));

    if (mode == 2) {
        size_t ko = (size_t)blockIdx.z * Kext;
        Ahg += ko;
        if (TERMS == 2) Alg += ko;
        Bhg += ko * ldb;
        C += (size_t)blockIdx.z * M * N;
    }

    int tid = threadIdx.x;
    int wid = tid >> 5, lane = tid & 31;
    int m_w = (wid >> 1) * 32, n_w = (wid & 1) * 64;
    int row0 = blockIdx.y * 128, col0 = blockIdx.x * 128;

    float acc[2][8][4];
#pragma unroll
    for (int i = 0; i < 2; i++)
#pragma unroll
        for (int j = 0; j < 8; j++)
#pragma unroll
            for (int q = 0; q < 4; q++) acc[i][j][q] = 0.f;

    int a_row = tid >> 1, a_colb = (tid & 1) * 32;
    int b_row = tid >> 2, b_colb = (tid & 3) * 32;

    auto loadStage = [&](int stage, int buf) {
        int k0 = stage * 64;
        const __half* aH = Ahg + (size_t)(row0 + a_row) * lda + k0 + a_colb;
        int sa = (buf * 128 + a_row) * PADA + a_colb;
        const __half* bH = Bhg + (size_t)(k0 + b_row) * ldb + col0 + b_colb;
        int sb = (buf * 64 + b_row) * PADB + b_colb;
#pragma unroll
        for (int i = 0; i < 4; i++) {
            cp16(AsH + sa + i * 8, aH + i * 8);
            cp16(BsH + sb + i * 8, bH + i * 8);
        }
        if (TERMS == 2) {
            const __half* aL = Alg + (size_t)(row0 + a_row) * lda + k0 + a_colb;
#pragma unroll
            for (int i = 0; i < 4; i++) cp16(AsL + sa + i * 8, aL + i * 8);
        }
        CP_COMMIT();
    };

    auto compute = [&](int buf) {
#pragma unroll
        for (int kk = 0; kk < 64; kk += 16) {
            uint32_t Ahf[2][4], Alf[2][4], Bhf[8][2];
#pragma unroll
            for (int i = 0; i < 2; i++) {
                int idx = (buf * 128 + m_w + i * 16 + (lane & 15)) * PADA + kk + (lane >> 4) * 8;
                ldsm_x4(Ahf[i], AsH + idx);
                if (TERMS == 2) ldsm_x4(Alf[i], AsL + idx);
            }
#pragma unroll
            for (int p = 0; p < 4; p++) {
                int idx = (buf * 64 + kk + (lane & 15)) * PADB + n_w + p * 16 + (lane >> 4) * 8;
                uint32_t r[4];
                ldsm_x4_t(r, BsH + idx);
                Bhf[2 * p][0] = r[0]; Bhf[2 * p][1] = r[1];
                Bhf[2 * p + 1][0] = r[2]; Bhf[2 * p + 1][1] = r[3];
            }
#pragma unroll
            for (int i = 0; i < 2; i++)
#pragma unroll
                for (int j = 0; j < 8; j++) {
                    mma16816(acc[i][j], Ahf[i], Bhf[j]);
                    if (TERMS == 2) mma16816(acc[i][j], Alf[i], Bhf[j]);
                }
        }
    };

    int nsteps = Kext >> 6;
    loadStage(0, 0);
    for (int s = 0; s < nsteps; s++) {
        CP_WAIT(0);
        __syncthreads();
        if (s + 1 < nsteps) loadStage(s + 1, (s + 1) & 1);
        compute(s & 1);
    }

    int g = lane >> 2, tg = lane & 3;
#pragma unroll
    for (int i = 0; i < 2; i++) {
#pragma unroll
        for (int j = 0; j < 8; j++) {
            int cc = col0 + n_w + j * 8 + tg * 2;
            float b0 = 0.f, b1 = 0.f;
            if (mode != 2) { b0 = bias[cc]; b1 = bias[cc + 1]; }
#pragma unroll
            for (int half = 0; half < 2; half++) {
                int r = row0 + m_w + i * 16 + g + half * 8;
                float v0 = acc[i][j][half * 2 + 0] + b0;
                float v1 = acc[i][j][half * 2 + 1] + b1;
                if (mode == 1) {
                    v0 = 0.5f * v0 * (1.f + erff(v0 * 0.7071067811865475f));
                    v1 = 0.5f * v1 * (1.f + erff(v1 * 0.7071067811865475f));
                    *(__half2*)(Ch + (size_t)r * N + cc) =
                        __half2(__float2half_rn(v0), __float2half_rn(v1));
                } else {
                    *(float2*)(C + (size_t)r * N + cc) = make_float2(v0, v1);
                }
            }
        }
    }
}

// -------------------- generic split-K=2 reduce + bias (N = power of 2) ----------
__global__ void reduce2(const float* __restrict__ part, const float* __restrict__ bias,
                        float* __restrict__ out, int total4, int nmask) {
    int i = blockIdx.x * blockDim.x + threadIdx.x;
    if (i >= total4) return;
    float4 a = ((const float4*)part)[i];
    float4 b = ((const float4*)part)[i + total4];
    int col = (i * 4) & nmask;
    float4 o;
    o.x = a.x + b.x + bias[col + 0];
    o.y = a.y + b.y + bias[col + 1];
    o.z = a.z + b.z + bias[col + 2];
    o.w = a.w + b.w + bias[col + 3];
    ((float4*)out)[i] = o;
}

// -------------------- fused FAVOR+ features + per-chunk sums (LDS-amortized) -----
// grid (NTOK/64, Hv), 128 threads. Block handles 64 tokens = 2 chunks; rf staged
// once per block. Thread tile: 4 rows x 4 m, then the chunk outer-product.
__global__ void __launch_bounds__(128)
favor_chunk(const float* __restrict__ rfs) {
    int tile = blockIdx.x, h = blockIdx.y;
    int b = tile >> 5, blk = tile & 31;   // 32 tiles per batch (Tv/64)
    int bh = b * Hv + h;
    __shared__ float rf[64][64];
    __shared__ float sq[32][68], sk[32][68];
    int tid = threadIdx.x;
    const float* rfh = rfs + h * 4096;
    for (int i = tid; i < 4096; i += 128) rf[i >> 6][i & 63] = rfh[i];
    const float sc = 0.3535533905932738f;
    int rg = tid >> 4, mg = tid & 15;
    int r0 = rg * 4, m0 = mg * 4;
    int om0 = (tid >> 3) * 4, od0 = (tid & 7) * 8;

    for (int cc = 0; cc < 2; cc++) {
        int c = blk * 2 + cc;
        int t0 = c * CHUNK;
        __syncthreads();
        for (int i = tid; i < 512; i += 128) {
            int tl = i >> 4, c4 = (i & 15) * 4;
            size_t gq = (size_t)(b * Tv + t0 + tl) * QKVN + h * HDv + c4;
            float4 qv = *(const float4*)(g_qkv + gq);
            float4 kv = *(const float4*)(g_qkv + gq + 512);
            qv.x *= sc; qv.y *= sc; qv.z *= sc; qv.w *= sc;
            kv.x *= sc; kv.y *= sc; kv.z *= sc; kv.w *= sc;
            *(float4*)&sq[tl][c4] = qv;
            *(float4*)&sk[tl][c4] = kv;
        }
        __syncthreads();

        float dq[4][4], dk[4][4], s2q[4], s2k[4];
#pragma unroll
        for (int r = 0; r < 4; r++) {
            s2q[r] = 0.f; s2k[r] = 0.f;
#pragma unroll
            for (int q = 0; q < 4; q++) { dq[r][q] = 0.f; dk[r][q] = 0.f; }
        }
#pragma unroll 4
        for (int d4 = 0; d4 < 16; d4++) {
            float4 rfv[4];
#pragma unroll
            for (int j = 0; j < 4; j++) rfv[j] = *(const float4*)&rf[d4 * 4 + j][m0];
#pragma unroll
            for (int r = 0; r < 4; r++) {
                float4 qv = *(const float4*)&sq[r0 + r][d4 * 4];
                float4 kv = *(const float4*)&sk[r0 + r][d4 * 4];
                float qa[4] = {qv.x, qv.y, qv.z, qv.w};
                float ka[4] = {kv.x, kv.y, kv.z, kv.w};
#pragma unroll
                for (int j = 0; j < 4; j++) {
                    float rr[4] = {rfv[j].x, rfv[j].y, rfv[j].z, rfv[j].w};
#pragma unroll
                    for (int q = 0; q < 4; q++) {
                        dq[r][q] += qa[j] * rr[q];
                        dk[r][q] += ka[j] * rr[q];
                    }
                    s2q[r] += qa[j] * qa[j];
                    s2k[r] += ka[j] * ka[j];
                }
            }
        }
        float qfv[4][4], kfv[4][4];
#pragma unroll
        for (int r = 0; r < 4; r++) {
            float hq = 0.5f * s2q[r], hk = 0.5f * s2k[r];
#pragma unroll
            for (int q = 0; q < 4; q++) {
                qfv[r][q] = expf(dq[r][q] - hq);
                kfv[r][q] = expf(dk[r][q] - hk);
            }
        }
#pragma unroll
        for (int r = 0; r < 4; r++) {
            size_t base = (size_t)(b * Tv + t0 + r0 + r) * Dv + h * HDv + m0;
            *(float4*)(g_qf + base) = make_float4(qfv[r][0], qfv[r][1], qfv[r][2], qfv[r][3]);
            *(float4*)(g_kf + base) = make_float4(kfv[r][0], kfv[r][1], kfv[r][2], kfv[r][3]);
        }
        __syncthreads();

        // stash kf -> sk ; V -> sq
#pragma unroll
        for (int r = 0; r < 4; r++)
            *(float4*)&sk[r0 + r][m0] = make_float4(kfv[r][0], kfv[r][1], kfv[r][2], kfv[r][3]);
        for (int i = tid; i < 512; i += 128) {
            int tl = i >> 4, c4 = (i & 15) * 4;
            size_t vb = (size_t)(b * Tv + t0 + tl) * QKVN + 1024 + h * HDv + c4;
            *(float4*)&sq[tl][c4] = *(const float4*)(g_qkv + vb);
        }
        __syncthreads();

        float acc[4][8];
#pragma unroll
        for (int r = 0; r < 4; r++)
#pragma unroll
            for (int q = 0; q < 8; q++) acc[r][q] = 0.f;
#pragma unroll 8
        for (int t = 0; t < 32; t++) {
            float4 km = *(const float4*)&sk[t][om0];
            float4 v0 = *(const float4*)&sq[t][od0];
            float4 v1 = *(const float4*)&sq[t][od0 + 4];
            float kr[4] = {km.x, km.y, km.z, km.w};
            float vr[8] = {v0.x, v0.y, v0.z, v0.w, v1.x, v1.y, v1.z, v1.w};
#pragma unroll
            for (int r = 0; r < 4; r++)
#pragma unroll
                for (int q = 0; q < 8; q++) acc[r][q] += kr[r] * vr[q];
        }
        int sb = (bh * NCHUNK + c) * 4096;
#pragma unroll
        for (int r = 0; r < 4; r++) {
            *(float4*)(g_S + sb + (om0 + r) * 64 + od0) =
                make_float4(acc[r][0], acc[r][1], acc[r][2], acc[r][3]);
            *(float4*)(g_S + sb + (om0 + r) * 64 + od0 + 4) =
                make_float4(acc[r][4], acc[r][5], acc[r][6], acc[r][7]);
        }
        if (tid < 64) {
            float z = 0.f;
#pragma unroll
            for (int t = 0; t < 32; t++) z += sk[t][tid];
            g_z[(bh * NCHUNK + c) * 64 + tid] = z;
        }
    }
}

// -------------------- exclusive scans over chunks (S and z fused) ---------------
__global__ void __launch_bounds__(64)
attn_scan() {
    int bh = blockIdx.x >> 6, m = blockIdx.x & 63, d = threadIdx.x;
    float v[NCHUNK];
#pragma unroll
    for (int c = 0; c < NCHUNK; c++)
        v[c] = g_S[((bh * NCHUNK + c) << 12) + m * 64 + d];
    float acc = 0.f;
#pragma unroll
    for (int c = 0; c < NCHUNK; c++) {
        g_S[((bh * NCHUNK + c) << 12) + m * 64 + d] = acc;
        acc += v[c];
    }
    if (m == 0) {
        float zv[NCHUNK];
#pragma unroll
        for (int c = 0; c < NCHUNK; c++) zv[c] = g_z[(bh * NCHUNK + c) * 64 + d];
        float za = 0.f;
#pragma unroll
        for (int c = 0; c < NCHUNK; c++) {
            g_z[(bh * NCHUNK + c) * 64 + d] = za;
            za += zv[c];
        }
    }
}

// -------------------- chunked-GEMM apply --------------------
__global__ void __launch_bounds__(128)
attn_apply() {
    int c = blockIdx.x, bh = blockIdx.y;
    int b = bh / Hv, h = bh % Hv;
    int tid = threadIdx.x;
    __shared__ float Qf[32][68], Kf[32][68], V[32][68];
    __shared__ float S0[64][68];
    __shared__ float A[32][36];
    __shared__ float z0[64], sden[32];
    int t0 = c * CHUNK;
    int sb = (bh * NCHUNK + c) * 4096;

    for (int i = tid; i < 512; i += 128) {
        int row = i >> 4, c4 = (i & 15) * 4;
        size_t qb = (size_t)(b * Tv + t0 + row) * Dv + h * HDv + c4;
        size_t vb = (size_t)(b * Tv + t0 + row) * QKVN + 1024 + h * HDv + c4;
        *(float4*)&Qf[row][c4] = *(const float4*)(g_qf + qb);
        *(float4*)&Kf[row][c4] = *(const float4*)(g_kf + qb);
        *(float4*)&V[row][c4] = *(const float4*)(g_qkv + vb);
    }
    for (int i = tid; i < 1024; i += 128) {
        int m = i >> 4, c4 = (i & 15) * 4;
        *(float4*)&S0[m][c4] = *(const float4*)(g_S + sb + m * 64 + c4);
    }
    if (tid < 16)
        *(float4*)&z0[tid * 4] = *(const float4*)(g_z + (bh * NCHUNK + c) * 64 + tid * 4);
    __syncthreads();

    int i0 = (tid >> 4) * 4;
    int j0 = tid & 15;
    {
        float a0[4] = {0.f, 0.f, 0.f, 0.f}, a1[4] = {0.f, 0.f, 0.f, 0.f};
#pragma unroll
        for (int k = 0; k < 64; k += 4) {
            float4 ka = *(const float4*)&Kf[j0][k];
            float4 kb = *(const float4*)&Kf[j0 + 16][k];
#pragma unroll
            for (int r = 0; r < 4; r++) {
                float4 q = *(const float4*)&Qf[i0 + r][k];
                a0[r] += q.x * ka.x + q.y * ka.y + q.z * ka.z + q.w * ka.w;
                a1[r] += q.x * kb.x + q.y * kb.y + q.z * kb.z + q.w * kb.w;
            }
        }
#pragma unroll
        for (int r = 0; r < 4; r++) {
            A[i0 + r][j0] = (j0 <= i0 + r) ? a0[r] : 0.f;
            A[i0 + r][j0 + 16] = (j0 + 16 <= i0 + r) ? a1[r] : 0.f;
        }
    }
    __syncthreads();

    if (tid < 32) {
        float dn = 1e-16f;
#pragma unroll 8
        for (int m = 0; m < 64; m++) dn += Qf[tid][m] * z0[m];
#pragma unroll
        for (int j = 0; j < 32; j++) dn += A[tid][j];
        sden[tid] = dn;
    }

    int d0 = (tid & 15) * 4;
    float acc[4][4];
#pragma unroll
    for (int r = 0; r < 4; r++)
#pragma unroll
        for (int q = 0; q < 4; q++) acc[r][q] = 0.f;
#pragma unroll 4
    for (int m = 0; m < 64; m += 4) {
        float4 qv[4], sv[4];
#pragma unroll
        for (int r = 0; r < 4; r++) qv[r] = *(const float4*)&Qf[i0 + r][m];
#pragma unroll
        for (int kk = 0; kk < 4; kk++) sv[kk] = *(const float4*)&S0[m + kk][d0];
#pragma unroll
        for (int r = 0; r < 4; r++) {
            float qr[4] = {qv[r].x, qv[r].y, qv[r].z, qv[r].w};
#pragma unroll
            for (int kk = 0; kk < 4; kk++) {
                acc[r][0] += qr[kk] * sv[kk].x;
                acc[r][1] += qr[kk] * sv[kk].y;
                acc[r][2] += qr[kk] * sv[kk].z;
                acc[r][3] += qr[kk] * sv[kk].w;
            }
        }
    }
#pragma unroll 2
    for (int j = 0; j < 32; j += 4) {
        float4 av[4], vv[4];
#pragma unroll
        for (int r = 0; r < 4; r++) av[r] = *(const float4*)&A[i0 + r][j];
#pragma unroll
        for (int kk = 0; kk < 4; kk++) vv[kk] = *(const float4*)&V[j + kk][d0];
#pragma unroll
        for (int r = 0; r < 4; r++) {
            float ar[4] = {av[r].x, av[r].y, av[r].z, av[r].w};
#pragma unroll
            for (int kk = 0; kk < 4; kk++) {
                acc[r][0] += ar[kk] * vv[kk].x;
                acc[r][1] += ar[kk] * vv[kk].y;
                acc[r][2] += ar[kk] * vv[kk].z;
                acc[r][3] += ar[kk] * vv[kk].w;
            }
        }
    }
    __syncthreads();
#pragma unroll
    for (int r = 0; r < 4; r++) {
        float inv = 1.f / sden[i0 + r];
        float4 o = make_float4(acc[r][0] * inv, acc[r][1] * inv,
                               acc[r][2] * inv, acc[r][3] * inv);
        *(float4*)(g_a + (size_t)(b * Tv + t0 + i0 + r) * Dv + h * HDv + d0) = o;
    }
}

// -------------------- LayerNorm + residual add (+ fp16 hi/lo of new x) ----------
// red=0: a = in0[row]. red=1: a = in0[row] + in1[row] + bias (split-K partials).
template <int RED>
__global__ void __launch_bounds__(128)
ln_add(const float* __restrict__ in0, const float* __restrict__ in1,
       const float* __restrict__ pbias,
       const float* __restrict__ g, const float* __restrict__ bl,
       float* __restrict__ x) {
    int n = blockIdx.x, tid = threadIdx.x;
    int lane = tid & 31, w = tid >> 5;
    float v[4];
    float s = 0.f, s2 = 0.f;
#pragma unroll
    for (int i = 0; i < 4; i++) {
        int j = tid + i * 128;
        float t = in0[(size_t)n * Dv + j];
        if (RED) t += in1[(size_t)n * Dv + j] + pbias[j];
        v[i] = t;
        s += t;
        s2 += t * t;
    }
    __shared__ float sh[8];
#pragma unroll
    for (int off = 16; off; off >>= 1) {
        s += __shfl_down_sync(0xffffffffu, s, off);
        s2 += __shfl_down_sync(0xffffffffu, s2, off);
    }
    if (lane == 0) { sh[w] = s; sh[4 + w] = s2; }
    __syncthreads();
    float S = sh[0] + sh[1] + sh[2] + sh[3];
    float S2 = sh[4] + sh[5] + sh[6] + sh[7];
    float mu = S * (1.f / Dv);
    float var = S2 * (1.f / Dv) - mu * mu;
    float rs = rsqrtf(var + 1e-5f);
#pragma unroll
    for (int i = 0; i < 4; i++) {
        int j = tid + i * 128;
        size_t idx = (size_t)n * Dv + j;
        float nv = x[idx] + (v[i] - mu) * rs * g[j] + bl[j];
        x[idx] = nv;
        __half h, l;
        split_fp16(nv, h, l);
        g_xh[idx] = h;
        g_xl[idx] = l;
    }
}

// -------------------- host driver --------------------
extern "C" void kernel_launch(void* const* d_in, const int* in_sizes, int n_in,
                              void* d_out, int out_size) {
    const int*   tokens = (const int*)d_in[0];
    const float* emb    = (const float*)d_in[1];
    const float* Wq     = (const float*)d_in[2];
    const float* bq     = (const float*)d_in[3];
    const float* Wk     = (const float*)d_in[4];
    const float* bk     = (const float*)d_in[5];
    const float* Wv     = (const float*)d_in[6];
    const float* bvp    = (const float*)d_in[7];
    const float* rfs    = (const float*)d_in[8];
    const float* ln1g   = (const float*)d_in[9];
    const float* ln1b   = (const float*)d_in[10];
    const float* ln2g   = (const float*)d_in[11];
    const float* ln2b   = (const float*)d_in[12];
    const float* WU     = (const float*)d_in[13];
    const float* bU     = (const float*)d_in[14];
    const float* WV     = (const float*)d_in[15];
    const float* bV     = (const float*)d_in[16];
    const float* Wout   = (const float*)d_in[17];
    const float* bout   = (const float*)d_in[18];
    float* out = (float*)d_out;

    static float *px = nullptr, *pa, *pqkv, *pbqkv, *ppart;
    static __half *pxh, *pxl, *phh, *pwh;
    if (!px) {
        cudaGetSymbolAddress((void**)&px, g_x);
        cudaGetSymbolAddress((void**)&pa, g_a);
        cudaGetSymbolAddress((void**)&pqkv, g_qkv);
        cudaGetSymbolAddress((void**)&pbqkv, g_bqkv);
        cudaGetSymbolAddress((void**)&ppart, g_part);
        cudaGetSymbolAddress((void**)&pxh, g_xh);
        cudaGetSymbolAddress((void**)&pxl, g_xl);
        cudaGetSymbolAddress((void**)&phh, g_hh);
        cudaGetSymbolAddress((void**)&pwh, g_wh);
        cudaFuncSetAttribute(gemm_tc<1>, cudaFuncAttributeMaxDynamicSharedMemorySize,
                             A_TILE + B_TILE);
        cudaFuncSetAttribute(gemm_tc<2>, cudaFuncAttributeMaxDynamicSharedMemorySize,
                             2 * A_TILE + B_TILE);
    }

    convw_all<<<(TOT4 + BIA4 + 255) / 256, 256>>>(Wq, Wk, Wv, WU, WV, Wout, bq, bk, bvp);
    embed_kernel<<<(NTOK * Dv + 255) / 256, 256>>>(tokens, emb);

    for (int l = 0; l < Lv; l++) {
        gemm_tc<1><<<dim3(QKVN / 128, NTOK / 128), 256, A_TILE + B_TILE>>>(
            pxh, nullptr, pwh + OFF_QKV + (size_t)l * Dv * QKVN, pbqkv + l * QKVN,
            pqkv, nullptr, NTOK, QKVN, Dv, QKVN, Dv, 0);

        favor_chunk<<<dim3(NTOK / 64, Hv), 128>>>(rfs + (size_t)l * Hv * HDv * HDv);
        attn_scan<<<Bv * Hv * HDv, 64>>>();
        attn_apply<<<dim3(NCHUNK, Bv * Hv), 128>>>();

        ln_add<0><<<NTOK, 128>>>(pa, nullptr, nullptr,
                                 ln1g + l * Dv, ln1b + l * Dv, px);

        gemm_tc<1><<<dim3(FFNv / 128, NTOK / 128), 256, A_TILE + B_TILE>>>(
            pxh, nullptr, pwh + OFF_WU + (size_t)l * Dv * FFNv, bU + l * FFNv,
            nullptr, phh, NTOK, FFNv, Dv, FFNv, Dv, 1);

        // FFN down: split-K=2 partials, then reduce fused into ln_add
        gemm_tc<1><<<dim3(Dv / 128, NTOK / 128, 2), 256, A_TILE + B_TILE>>>(
            phh, nullptr, pwh + OFF_WD + (size_t)l * FFNv * Dv, nullptr,
            ppart, nullptr, NTOK, Dv, FFNv, Dv, 1024, 2);

        ln_add<1><<<NTOK, 128>>>(ppart, ppart + (size_t)NTOK * Dv, bV + l * Dv,
                                 ln2g + l * Dv, ln2b + l * Dv, px);
    }

    gemm_tc<2><<<dim3(VOCABv / 128, NTOK / 128, 2), 256, 2 * A_TILE + B_TILE>>>(
        pxh, pxl, pwh + OFF_WO, nullptr, ppart, nullptr,
        NTOK, VOCABv, Dv, VOCABv, 256, 2);
    reduce2<<<(NTOK * VOCABv / 4 + 255) / 256, 256>>>(ppart, bout, out,
                                                      NTOK * VOCABv / 4, VOCABv - 1);
}

// round 13
// speedup vs baseline: 2.1167x; 1.0092x over previous
#include <cuda_runtime.h>
#include <cuda_fp16.h>
#include <math.h>
#include <stdint.h>

// Problem constants
#define Bv      2
#define Tv      2048
#define NTOK    (Bv * Tv)      // 4096
#define Dv      512
#define Hv      8
#define HDv     64
#define FFNv    2048
#define VOCABv  256
#define Lv      2
#define CHUNK   32
#define NCHUNK  (Tv / CHUNK)   // 64
#define QKVN    1536

// weight region offsets (elements) in the fp16 weight pool ([K,N] row-major)
#define OFF_QKV 0
#define OFF_WU  (OFF_QKV + Lv * Dv * QKVN)
#define OFF_WD  (OFF_WU + Lv * Dv * FFNv)
#define OFF_WO  (OFF_WD + Lv * FFNv * Dv)
#define W_TOTAL (OFF_WO + Dv * VOCABv)

#define QKV4 (Lv * Dv * QKVN / 4)
#define WU4  (Lv * Dv * FFNv / 4)
#define WD4  (Lv * FFNv * Dv / 4)
#define WO4  (Dv * VOCABv / 4)
#define TOT4 (QKV4 + WU4 + WD4 + WO4)
#define BIA4 (Lv * QKVN / 4)

// -------------------- scratch (device globals; no allocs) --------------------
__device__ float g_x[NTOK * Dv];
__device__ float g_a[NTOK * Dv];
__device__ float g_qkv[NTOK * QKVN];
__device__ float g_qf[NTOK * Dv];
__device__ float g_kf[NTOK * Dv];
__device__ float g_S[Bv * Hv * NCHUNK * HDv * HDv];
__device__ float g_z[Bv * Hv * NCHUNK * HDv];
__device__ float g_bqkv[Lv * QKVN];
__device__ float g_part[2 * NTOK * Dv];
__device__ __half g_xh[NTOK * Dv];
__device__ __half g_xl[NTOK * Dv];
__device__ __half g_hh[NTOK * FFNv];
__device__ __half g_wh[W_TOTAL];

__device__ __forceinline__ void split_fp16(float v, __half& h, __half& l) {
    h = __float2half_rn(v);
    l = __float2half_rn(v - __half2float(h));
}

// -------------------- ONE fused weight conversion + bias pack --------------------
__global__ void convw_all(const float* __restrict__ Wq, const float* __restrict__ Wk,
                          const float* __restrict__ Wv, const float* __restrict__ WU,
                          const float* __restrict__ WV, const float* __restrict__ Wout,
                          const float* __restrict__ bq, const float* __restrict__ bk,
                          const float* __restrict__ bvp) {
    int idx = blockIdx.x * blockDim.x + threadIdx.x;
    if (idx < TOT4) {
        const float* src;
        int e;
        if (idx < QKV4) {
            e = idx * 4;
            int l = e / (Dv * QKVN);
            int r = e % (Dv * QKVN);
            int k = r / QKVN, col = r % QKVN;
            if (col < 512)       src = Wq + (size_t)l * Dv * Dv + k * 512 + col;
            else if (col < 1024) src = Wk + (size_t)l * Dv * Dv + k * 512 + col - 512;
            else                 src = Wv + (size_t)l * Dv * Dv + k * 512 + col - 1024;
            e += OFF_QKV;
        } else if (idx < QKV4 + WU4) {
            int e2 = (idx - QKV4) * 4;
            src = WU + e2;
            e = OFF_WU + e2;
        } else if (idx < QKV4 + WU4 + WD4) {
            int e2 = (idx - QKV4 - WU4) * 4;
            src = WV + e2;
            e = OFF_WD + e2;
        } else {
            int e2 = (idx - QKV4 - WU4 - WD4) * 4;
            src = Wout + e2;
            e = OFF_WO + e2;
        }
        float4 v = *(const float4*)src;
        ((__half2*)(g_wh + e))[0] = __half2(__float2half_rn(v.x), __float2half_rn(v.y));
        ((__half2*)(g_wh + e))[1] = __half2(__float2half_rn(v.z), __float2half_rn(v.w));
    } else if (idx < TOT4 + BIA4) {
        int j = (idx - TOT4) * 4;
#pragma unroll
        for (int q = 0; q < 4; q++) {
            int jj = j + q;
            int l = jj / QKVN, c = jj % QKVN;
            float v;
            if (c < 512) v = bq[l * Dv + c];
            else if (c < 1024) v = bk[l * Dv + c - 512];
            else v = bvp[l * Dv + c - 1024];
            g_bqkv[jj] = v;
        }
    }
}

// -------------------- embedding + sinusoidal positions --------------------
__global__ void embed_kernel(const int* __restrict__ tokens,
                             const float* __restrict__ emb) {
    int idx = blockIdx.x * blockDim.x + threadIdx.x;
    if (idx >= NTOK * Dv) return;
    int n = idx >> 9;
    int j = idx & 511;
    int t = n & (Tv - 1);
    float val;
    const float c = 9.210340371976184f / 256.f;
    if (j < 256) {
        int tok = tokens[n];
        val = emb[tok * 256 + j];
    } else if (j < 384) {
        int i = j - 256;
        val = sinf((float)t * expf(-(2.f * (float)i) * c));
    } else {
        int i = j - 384;
        val = cosf((float)t * expf(-(2.f * (float)i) * c));
    }
    g_x[idx] = val;
    __half h, l;
    split_fp16(val, h, l);
    g_xh[idx] = h;
    g_xl[idx] = l;
}

// -------------------- tensor-core GEMM, fp16, BK=64, 2-stage cp.async ----------
__device__ __forceinline__ void ldsm_x4(uint32_t* r, const void* p) {
    uint32_t a = (uint32_t)__cvta_generic_to_shared(p);
    asm volatile("ldmatrix.sync.aligned.m8n8.x4.shared.b16 {%0,%1,%2,%3},[%4];"
        : "=r"(r[0]), "=r"(r[1]), "=r"(r[2]), "=r"(r[3]) : "r"(a));
}
__device__ __forceinline__ void ldsm_x4_t(uint32_t* r, const void* p) {
    uint32_t a = (uint32_t)__cvta_generic_to_shared(p);
    asm volatile("ldmatrix.sync.aligned.m8n8.x4.trans.shared.b16 {%0,%1,%2,%3},[%4];"
        : "=r"(r[0]), "=r"(r[1]), "=r"(r[2]), "=r"(r[3]) : "r"(a));
}
__device__ __forceinline__ void mma16816(float* c, const uint32_t* a, const uint32_t* b) {
    asm volatile("mma.sync.aligned.m16n8k16.row.col.f32.f16.f16.f32 "
        "{%0,%1,%2,%3},{%4,%5,%6,%7},{%8,%9},{%0,%1,%2,%3};"
        : "+f"(c[0]), "+f"(c[1]), "+f"(c[2]), "+f"(c[3])
        : "r"(a[0]), "r"(a[1]), "r"(a[2]), "r"(a[3]), "r"(b[0]), "r"(b[1]));
}
__device__ __forceinline__ void cp16(void* smem, const void* gmem) {
    uint32_t s = (uint32_t)__cvta_generic_to_shared(smem);
    asm volatile("cp.async.cg.shared.global [%0], [%1], 16;" :: "r"(s), "l"(gmem));
}
#define CP_COMMIT() asm volatile("cp.async.commit_group;")
#define CP_WAIT(n)  asm volatile("cp.async.wait_group %0;" :: "n"(n))

#define PADA 72
#define PADB 136
#define A_TILE 36864
#define B_TILE 34816

// mode 0: fp32 out + bias. mode 1: gelu -> fp16 (Ch). mode 2: split-K partials (no bias).
template <int TERMS>
__global__ void __launch_bounds__(256, 2)
gemm_tc(const __half* __restrict__ Ahg, const __half* __restrict__ Alg,
        const __half* __restrict__ Bhg,
        const float* __restrict__ bias, float* __restrict__ C,
        __half* __restrict__ Ch,
        int M, int N, int lda, int ldb, int Kext, int mode) {
    extern __shared__ char smraw[];
    __half* AsH = (__half*)(smraw);
    __half* AsL = (__half*)(smraw + A_TILE);
    __half* BsH = (__half*)(smraw + (TERMS == 2 ? 2 * A_TILE : A_TILE));

    if (mode == 2) {
        size_t ko = (size_t)blockIdx.z * Kext;
        Ahg += ko;
        if (TERMS == 2) Alg += ko;
        Bhg += ko * ldb;
        C += (size_t)blockIdx.z * M * N;
    }

    int tid = threadIdx.x;
    int wid = tid >> 5, lane = tid & 31;
    int m_w = (wid >> 1) * 32, n_w = (wid & 1) * 64;
    int row0 = blockIdx.y * 128, col0 = blockIdx.x * 128;

    float acc[2][8][4];
#pragma unroll
    for (int i = 0; i < 2; i++)
#pragma unroll
        for (int j = 0; j < 8; j++)
#pragma unroll
            for (int q = 0; q < 4; q++) acc[i][j][q] = 0.f;

    int a_row = tid >> 1, a_colb = (tid & 1) * 32;
    int b_row = tid >> 2, b_colb = (tid & 3) * 32;

    auto loadStage = [&](int stage, int buf) {
        int k0 = stage * 64;
        const __half* aH = Ahg + (size_t)(row0 + a_row) * lda + k0 + a_colb;
        int sa = (buf * 128 + a_row) * PADA + a_colb;
        const __half* bH = Bhg + (size_t)(k0 + b_row) * ldb + col0 + b_colb;
        int sb = (buf * 64 + b_row) * PADB + b_colb;
#pragma unroll
        for (int i = 0; i < 4; i++) {
            cp16(AsH + sa + i * 8, aH + i * 8);
            cp16(BsH + sb + i * 8, bH + i * 8);
        }
        if (TERMS == 2) {
            const __half* aL = Alg + (size_t)(row0 + a_row) * lda + k0 + a_colb;
#pragma unroll
            for (int i = 0; i < 4; i++) cp16(AsL + sa + i * 8, aL + i * 8);
        }
        CP_COMMIT();
    };

    auto compute = [&](int buf) {
#pragma unroll
        for (int kk = 0; kk < 64; kk += 16) {
            uint32_t Ahf[2][4], Alf[2][4], Bhf[8][2];
#pragma unroll
            for (int i = 0; i < 2; i++) {
                int idx = (buf * 128 + m_w + i * 16 + (lane & 15)) * PADA + kk + (lane >> 4) * 8;
                ldsm_x4(Ahf[i], AsH + idx);
                if (TERMS == 2) ldsm_x4(Alf[i], AsL + idx);
            }
#pragma unroll
            for (int p = 0; p < 4; p++) {
                int idx = (buf * 64 + kk + (lane & 15)) * PADB + n_w + p * 16 + (lane >> 4) * 8;
                uint32_t r[4];
                ldsm_x4_t(r, BsH + idx);
                Bhf[2 * p][0] = r[0]; Bhf[2 * p][1] = r[1];
                Bhf[2 * p + 1][0] = r[2]; Bhf[2 * p + 1][1] = r[3];
            }
#pragma unroll
            for (int i = 0; i < 2; i++)
#pragma unroll
                for (int j = 0; j < 8; j++) {
                    mma16816(acc[i][j], Ahf[i], Bhf[j]);
                    if (TERMS == 2) mma16816(acc[i][j], Alf[i], Bhf[j]);
                }
        }
    };

    int nsteps = Kext >> 6;
    loadStage(0, 0);
    for (int s = 0; s < nsteps; s++) {
        CP_WAIT(0);
        __syncthreads();
        if (s + 1 < nsteps) loadStage(s + 1, (s + 1) & 1);
        compute(s & 1);
    }

    int g = lane >> 2, tg = lane & 3;
#pragma unroll
    for (int i = 0; i < 2; i++) {
#pragma unroll
        for (int j = 0; j < 8; j++) {
            int cc = col0 + n_w + j * 8 + tg * 2;
            float b0 = 0.f, b1 = 0.f;
            if (mode != 2) { b0 = bias[cc]; b1 = bias[cc + 1]; }
#pragma unroll
            for (int half = 0; half < 2; half++) {
                int r = row0 + m_w + i * 16 + g + half * 8;
                float v0 = acc[i][j][half * 2 + 0] + b0;
                float v1 = acc[i][j][half * 2 + 1] + b1;
                if (mode == 1) {
                    v0 = 0.5f * v0 * (1.f + erff(v0 * 0.7071067811865475f));
                    v1 = 0.5f * v1 * (1.f + erff(v1 * 0.7071067811865475f));
                    *(__half2*)(Ch + (size_t)r * N + cc) =
                        __half2(__float2half_rn(v0), __float2half_rn(v1));
                } else {
                    *(float2*)(C + (size_t)r * N + cc) = make_float2(v0, v1);
                }
            }
        }
    }
}

// -------------------- generic split-K=2 reduce + bias (N = power of 2) ----------
__global__ void reduce2(const float* __restrict__ part, const float* __restrict__ bias,
                        float* __restrict__ out, int total4, int nmask) {
    int i = blockIdx.x * blockDim.x + threadIdx.x;
    if (i >= total4) return;
    float4 a = ((const float4*)part)[i];
    float4 b = ((const float4*)part)[i + total4];
    int col = (i * 4) & nmask;
    float4 o;
    o.x = a.x + b.x + bias[col + 0];
    o.y = a.y + b.y + bias[col + 1];
    o.z = a.z + b.z + bias[col + 2];
    o.w = a.w + b.w + bias[col + 3];
    ((float4*)out)[i] = o;
}

// -------------------- fused FAVOR+ features + per-chunk sums --------------------
// grid (NTOK/32, Hv), 128 threads, ONE chunk per block (max grid parallelism).
__global__ void __launch_bounds__(128)
favor_chunk(const float* __restrict__ rfs) {
    int tile = blockIdx.x, h = blockIdx.y;
    int b = tile >> 6, c = tile & 63;     // 64 chunks per batch
    int bh = b * Hv + h;
    __shared__ float rf[64][64];
    __shared__ float sq[32][68], sk[32][68];
    int tid = threadIdx.x;
    const float* rfh = rfs + h * 4096;
    const float sc = 0.3535533905932738f;
    int rg = tid >> 4, mg = tid & 15;
    int r0 = rg * 4, m0 = mg * 4;
    int om0 = (tid >> 3) * 4, od0 = (tid & 7) * 8;
    int t0 = c * CHUNK;

    for (int i = tid; i < 4096; i += 128) rf[i >> 6][i & 63] = rfh[i];
    for (int i = tid; i < 512; i += 128) {
        int tl = i >> 4, c4 = (i & 15) * 4;
        size_t gq = (size_t)(b * Tv + t0 + tl) * QKVN + h * HDv + c4;
        float4 qv = *(const float4*)(g_qkv + gq);
        float4 kv = *(const float4*)(g_qkv + gq + 512);
        qv.x *= sc; qv.y *= sc; qv.z *= sc; qv.w *= sc;
        kv.x *= sc; kv.y *= sc; kv.z *= sc; kv.w *= sc;
        *(float4*)&sq[tl][c4] = qv;
        *(float4*)&sk[tl][c4] = kv;
    }
    __syncthreads();

    float dq[4][4], dk[4][4], s2q[4], s2k[4];
#pragma unroll
    for (int r = 0; r < 4; r++) {
        s2q[r] = 0.f; s2k[r] = 0.f;
#pragma unroll
        for (int q = 0; q < 4; q++) { dq[r][q] = 0.f; dk[r][q] = 0.f; }
    }
#pragma unroll 4
    for (int d4 = 0; d4 < 16; d4++) {
        float4 rfv[4];
#pragma unroll
        for (int j = 0; j < 4; j++) rfv[j] = *(const float4*)&rf[d4 * 4 + j][m0];
#pragma unroll
        for (int r = 0; r < 4; r++) {
            float4 qv = *(const float4*)&sq[r0 + r][d4 * 4];
            float4 kv = *(const float4*)&sk[r0 + r][d4 * 4];
            float qa[4] = {qv.x, qv.y, qv.z, qv.w};
            float ka[4] = {kv.x, kv.y, kv.z, kv.w};
#pragma unroll
            for (int j = 0; j < 4; j++) {
                float rr[4] = {rfv[j].x, rfv[j].y, rfv[j].z, rfv[j].w};
#pragma unroll
                for (int q = 0; q < 4; q++) {
                    dq[r][q] += qa[j] * rr[q];
                    dk[r][q] += ka[j] * rr[q];
                }
                s2q[r] += qa[j] * qa[j];
                s2k[r] += ka[j] * ka[j];
            }
        }
    }
    float qfv[4][4], kfv[4][4];
#pragma unroll
    for (int r = 0; r < 4; r++) {
        float hq = 0.5f * s2q[r], hk = 0.5f * s2k[r];
#pragma unroll
        for (int q = 0; q < 4; q++) {
            qfv[r][q] = expf(dq[r][q] - hq);
            kfv[r][q] = expf(dk[r][q] - hk);
        }
    }
#pragma unroll
    for (int r = 0; r < 4; r++) {
        size_t base = (size_t)(b * Tv + t0 + r0 + r) * Dv + h * HDv + m0;
        *(float4*)(g_qf + base) = make_float4(qfv[r][0], qfv[r][1], qfv[r][2], qfv[r][3]);
        *(float4*)(g_kf + base) = make_float4(kfv[r][0], kfv[r][1], kfv[r][2], kfv[r][3]);
    }
    __syncthreads();

    // stash kf -> sk ; V -> sq
#pragma unroll
    for (int r = 0; r < 4; r++)
        *(float4*)&sk[r0 + r][m0] = make_float4(kfv[r][0], kfv[r][1], kfv[r][2], kfv[r][3]);
    for (int i = tid; i < 512; i += 128) {
        int tl = i >> 4, c4 = (i & 15) * 4;
        size_t vb = (size_t)(b * Tv + t0 + tl) * QKVN + 1024 + h * HDv + c4;
        *(float4*)&sq[tl][c4] = *(const float4*)(g_qkv + vb);
    }
    __syncthreads();

    float acc[4][8];
#pragma unroll
    for (int r = 0; r < 4; r++)
#pragma unroll
        for (int q = 0; q < 8; q++) acc[r][q] = 0.f;
#pragma unroll 8
    for (int t = 0; t < 32; t++) {
        float4 km = *(const float4*)&sk[t][om0];
        float4 v0 = *(const float4*)&sq[t][od0];
        float4 v1 = *(const float4*)&sq[t][od0 + 4];
        float kr[4] = {km.x, km.y, km.z, km.w};
        float vr[8] = {v0.x, v0.y, v0.z, v0.w, v1.x, v1.y, v1.z, v1.w};
#pragma unroll
        for (int r = 0; r < 4; r++)
#pragma unroll
            for (int q = 0; q < 8; q++) acc[r][q] += kr[r] * vr[q];
    }
    int sb = (bh * NCHUNK + c) * 4096;
#pragma unroll
    for (int r = 0; r < 4; r++) {
        *(float4*)(g_S + sb + (om0 + r) * 64 + od0) =
            make_float4(acc[r][0], acc[r][1], acc[r][2], acc[r][3]);
        *(float4*)(g_S + sb + (om0 + r) * 64 + od0 + 4) =
            make_float4(acc[r][4], acc[r][5], acc[r][6], acc[r][7]);
    }
    if (tid < 64) {
        float z = 0.f;
#pragma unroll
        for (int t = 0; t < 32; t++) z += sk[t][tid];
        g_z[(bh * NCHUNK + c) * 64 + tid] = z;
    }
}

// -------------------- exclusive scans over chunks (S and z fused) ---------------
__global__ void __launch_bounds__(64)
attn_scan() {
    int bh = blockIdx.x >> 6, m = blockIdx.x & 63, d = threadIdx.x;
    float v[NCHUNK];
#pragma unroll
    for (int c = 0; c < NCHUNK; c++)
        v[c] = g_S[((bh * NCHUNK + c) << 12) + m * 64 + d];
    float acc = 0.f;
#pragma unroll
    for (int c = 0; c < NCHUNK; c++) {
        g_S[((bh * NCHUNK + c) << 12) + m * 64 + d] = acc;
        acc += v[c];
    }
    if (m == 0) {
        float zv[NCHUNK];
#pragma unroll
        for (int c = 0; c < NCHUNK; c++) zv[c] = g_z[(bh * NCHUNK + c) * 64 + d];
        float za = 0.f;
#pragma unroll
        for (int c = 0; c < NCHUNK; c++) {
            g_z[(bh * NCHUNK + c) * 64 + d] = za;
            za += zv[c];
        }
    }
}

// -------------------- chunked-GEMM apply --------------------
__global__ void __launch_bounds__(128)
attn_apply() {
    int c = blockIdx.x, bh = blockIdx.y;
    int b = bh / Hv, h = bh % Hv;
    int tid = threadIdx.x;
    __shared__ float Qf[32][68], Kf[32][68], V[32][68];
    __shared__ float S0[64][68];
    __shared__ float A[32][36];
    __shared__ float z0[64], sden[32];
    int t0 = c * CHUNK;
    int sb = (bh * NCHUNK + c) * 4096;

    for (int i = tid; i < 512; i += 128) {
        int row = i >> 4, c4 = (i & 15) * 4;
        size_t qb = (size_t)(b * Tv + t0 + row) * Dv + h * HDv + c4;
        size_t vb = (size_t)(b * Tv + t0 + row) * QKVN + 1024 + h * HDv + c4;
        *(float4*)&Qf[row][c4] = *(const float4*)(g_qf + qb);
        *(float4*)&Kf[row][c4] = *(const float4*)(g_kf + qb);
        *(float4*)&V[row][c4] = *(const float4*)(g_qkv + vb);
    }
    for (int i = tid; i < 1024; i += 128) {
        int m = i >> 4, c4 = (i & 15) * 4;
        *(float4*)&S0[m][c4] = *(const float4*)(g_S + sb + m * 64 + c4);
    }
    if (tid < 16)
        *(float4*)&z0[tid * 4] = *(const float4*)(g_z + (bh * NCHUNK + c) * 64 + tid * 4);
    __syncthreads();

    int i0 = (tid >> 4) * 4;
    int j0 = tid & 15;
    {
        float a0[4] = {0.f, 0.f, 0.f, 0.f}, a1[4] = {0.f, 0.f, 0.f, 0.f};
#pragma unroll
        for (int k = 0; k < 64; k += 4) {
            float4 ka = *(const float4*)&Kf[j0][k];
            float4 kb = *(const float4*)&Kf[j0 + 16][k];
#pragma unroll
            for (int r = 0; r < 4; r++) {
                float4 q = *(const float4*)&Qf[i0 + r][k];
                a0[r] += q.x * ka.x + q.y * ka.y + q.z * ka.z + q.w * ka.w;
                a1[r] += q.x * kb.x + q.y * kb.y + q.z * kb.z + q.w * kb.w;
            }
        }
#pragma unroll
        for (int r = 0; r < 4; r++) {
            A[i0 + r][j0] = (j0 <= i0 + r) ? a0[r] : 0.f;
            A[i0 + r][j0 + 16] = (j0 + 16 <= i0 + r) ? a1[r] : 0.f;
        }
    }
    __syncthreads();

    if (tid < 32) {
        float dn = 1e-16f;
#pragma unroll 8
        for (int m = 0; m < 64; m++) dn += Qf[tid][m] * z0[m];
#pragma unroll
        for (int j = 0; j < 32; j++) dn += A[tid][j];
        sden[tid] = dn;
    }

    int d0 = (tid & 15) * 4;
    float acc[4][4];
#pragma unroll
    for (int r = 0; r < 4; r++)
#pragma unroll
        for (int q = 0; q < 4; q++) acc[r][q] = 0.f;
#pragma unroll 4
    for (int m = 0; m < 64; m += 4) {
        float4 qv[4], sv[4];
#pragma unroll
        for (int r = 0; r < 4; r++) qv[r] = *(const float4*)&Qf[i0 + r][m];
#pragma unroll
        for (int kk = 0; kk < 4; kk++) sv[kk] = *(const float4*)&S0[m + kk][d0];
#pragma unroll
        for (int r = 0; r < 4; r++) {
            float qr[4] = {qv[r].x, qv[r].y, qv[r].z, qv[r].w};
#pragma unroll
            for (int kk = 0; kk < 4; kk++) {
                acc[r][0] += qr[kk] * sv[kk].x;
                acc[r][1] += qr[kk] * sv[kk].y;
                acc[r][2] += qr[kk] * sv[kk].z;
                acc[r][3] += qr[kk] * sv[kk].w;
            }
        }
    }
#pragma unroll 2
    for (int j = 0; j < 32; j += 4) {
        float4 av[4], vv[4];
#pragma unroll
        for (int r = 0; r < 4; r++) av[r] = *(const float4*)&A[i0 + r][j];
#pragma unroll
        for (int kk = 0; kk < 4; kk++) vv[kk] = *(const float4*)&V[j + kk][d0];
#pragma unroll
        for (int r = 0; r < 4; r++) {
            float ar[4] = {av[r].x, av[r].y, av[r].z, av[r].w};
#pragma unroll
            for (int kk = 0; kk < 4; kk++) {
                acc[r][0] += ar[kk] * vv[kk].x;
                acc[r][1] += ar[kk] * vv[kk].y;
                acc[r][2] += ar[kk] * vv[kk].z;
                acc[r][3] += ar[kk] * vv[kk].w;
            }
        }
    }
    __syncthreads();
#pragma unroll
    for (int r = 0; r < 4; r++) {
        float inv = 1.f / sden[i0 + r];
        float4 o = make_float4(acc[r][0] * inv, acc[r][1] * inv,
                               acc[r][2] * inv, acc[r][3] * inv);
        *(float4*)(g_a + (size_t)(b * Tv + t0 + i0 + r) * Dv + h * HDv + d0) = o;
    }
}

// -------------------- LayerNorm + residual add (+ fp16 hi/lo of new x) ----------
// red=0: a = in0[row]. red=1: a = in0[row] + in1[row] + bias (split-K partials).
template <int RED>
__global__ void __launch_bounds__(128)
ln_add(const float* __restrict__ in0, const float* __restrict__ in1,
       const float* __restrict__ pbias,
       const float* __restrict__ g, const float* __restrict__ bl,
       float* __restrict__ x) {
    int n = blockIdx.x, tid = threadIdx.x;
    int lane = tid & 31, w = tid >> 5;
    float v[4];
    float s = 0.f, s2 = 0.f;
#pragma unroll
    for (int i = 0; i < 4; i++) {
        int j = tid + i * 128;
        float t = in0[(size_t)n * Dv + j];
        if (RED) t += in1[(size_t)n * Dv + j] + pbias[j];
        v[i] = t;
        s += t;
        s2 += t * t;
    }
    __shared__ float sh[8];
#pragma unroll
    for (int off = 16; off; off >>= 1) {
        s += __shfl_down_sync(0xffffffffu, s, off);
        s2 += __shfl_down_sync(0xffffffffu, s2, off);
    }
    if (lane == 0) { sh[w] = s; sh[4 + w] = s2; }
    __syncthreads();
    float S = sh[0] + sh[1] + sh[2] + sh[3];
    float S2 = sh[4] + sh[5] + sh[6] + sh[7];
    float mu = S * (1.f / Dv);
    float var = S2 * (1.f / Dv) - mu * mu;
    float rs = rsqrtf(var + 1e-5f);
#pragma unroll
    for (int i = 0; i < 4; i++) {
        int j = tid + i * 128;
        size_t idx = (size_t)n * Dv + j;
        float nv = x[idx] + (v[i] - mu) * rs * g[j] + bl[j];
        x[idx] = nv;
        __half h, l;
        split_fp16(nv, h, l);
        g_xh[idx] = h;
        g_xl[idx] = l;
    }
}

// -------------------- host driver --------------------
extern "C" void kernel_launch(void* const* d_in, const int* in_sizes, int n_in,
                              void* d_out, int out_size) {
    const int*   tokens = (const int*)d_in[0];
    const float* emb    = (const float*)d_in[1];
    const float* Wq     = (const float*)d_in[2];
    const float* bq     = (const float*)d_in[3];
    const float* Wk     = (const float*)d_in[4];
    const float* bk     = (const float*)d_in[5];
    const float* Wv     = (const float*)d_in[6];
    const float* bvp    = (const float*)d_in[7];
    const float* rfs    = (const float*)d_in[8];
    const float* ln1g   = (const float*)d_in[9];
    const float* ln1b   = (const float*)d_in[10];
    const float* ln2g   = (const float*)d_in[11];
    const float* ln2b   = (const float*)d_in[12];
    const float* WU     = (const float*)d_in[13];
    const float* bU     = (const float*)d_in[14];
    const float* WV     = (const float*)d_in[15];
    const float* bV     = (const float*)d_in[16];
    const float* Wout   = (const float*)d_in[17];
    const float* bout   = (const float*)d_in[18];
    float* out = (float*)d_out;

    static float *px = nullptr, *pa, *pqkv, *pbqkv, *ppart;
    static __half *pxh, *pxl, *phh, *pwh;
    if (!px) {
        cudaGetSymbolAddress((void**)&px, g_x);
        cudaGetSymbolAddress((void**)&pa, g_a);
        cudaGetSymbolAddress((void**)&pqkv, g_qkv);
        cudaGetSymbolAddress((void**)&pbqkv, g_bqkv);
        cudaGetSymbolAddress((void**)&ppart, g_part);
        cudaGetSymbolAddress((void**)&pxh, g_xh);
        cudaGetSymbolAddress((void**)&pxl, g_xl);
        cudaGetSymbolAddress((void**)&phh, g_hh);
        cudaGetSymbolAddress((void**)&pwh, g_wh);
        cudaFuncSetAttribute(gemm_tc<1>, cudaFuncAttributeMaxDynamicSharedMemorySize,
                             A_TILE + B_TILE);
        cudaFuncSetAttribute(gemm_tc<2>, cudaFuncAttributeMaxDynamicSharedMemorySize,
                             2 * A_TILE + B_TILE);
    }

    convw_all<<<(TOT4 + BIA4 + 255) / 256, 256>>>(Wq, Wk, Wv, WU, WV, Wout, bq, bk, bvp);
    embed_kernel<<<(NTOK * Dv + 255) / 256, 256>>>(tokens, emb);

    for (int l = 0; l < Lv; l++) {
        gemm_tc<1><<<dim3(QKVN / 128, NTOK / 128), 256, A_TILE + B_TILE>>>(
            pxh, nullptr, pwh + OFF_QKV + (size_t)l * Dv * QKVN, pbqkv + l * QKVN,
            pqkv, nullptr, NTOK, QKVN, Dv, QKVN, Dv, 0);

        favor_chunk<<<dim3(NTOK / 32, Hv), 128>>>(rfs + (size_t)l * Hv * HDv * HDv);
        attn_scan<<<Bv * Hv * HDv, 64>>>();
        attn_apply<<<dim3(NCHUNK, Bv * Hv), 128>>>();

        ln_add<0><<<NTOK, 128>>>(pa, nullptr, nullptr,
                                 ln1g + l * Dv, ln1b + l * Dv, px);

        gemm_tc<1><<<dim3(FFNv / 128, NTOK / 128), 256, A_TILE + B_TILE>>>(
            pxh, nullptr, pwh + OFF_WU + (size_t)l * Dv * FFNv, bU + l * FFNv,
            nullptr, phh, NTOK, FFNv, Dv, FFNv, Dv, 1);

        gemm_tc<1><<<dim3(Dv / 128, NTOK / 128, 2), 256, A_TILE + B_TILE>>>(
            phh, nullptr, pwh + OFF_WD + (size_t)l * FFNv * Dv, nullptr,
            ppart, nullptr, NTOK, Dv, FFNv, Dv, 1024, 2);

        ln_add<1><<<NTOK, 128>>>(ppart, ppart + (size_t)NTOK * Dv, bV + l * Dv,
                                 ln2g + l * Dv, ln2b + l * Dv, px);
    }

    gemm_tc<2><<<dim3(VOCABv / 128, NTOK / 128, 2), 256, 2 * A_TILE + B_TILE>>>(
        pxh, pxl, pwh + OFF_WO, nullptr, ppart, nullptr,
        NTOK, VOCABv, Dv, VOCABv, 256, 2);
    reduce2<<<(NTOK * VOCABv / 4 + 255) / 256, 256>>>(ppart, bout, out,
                                                      NTOK * VOCABv / 4, VOCABv - 1);
}

// round 14
// speedup vs baseline: 2.1443x; 1.0130x over previous
#include <cuda_runtime.h>
#include <cuda_fp16.h>
#include <math.h>
#include <stdint.h>

// Problem constants
#define Bv      2
#define Tv      2048
#define NTOK    (Bv * Tv)      // 4096
#define Dv      512
#define Hv      8
#define HDv     64
#define FFNv    2048
#define VOCABv  256
#define Lv      2
#define CHUNK   32
#define NCHUNK  (Tv / CHUNK)   // 64
#define QKVN    1536

// weight region offsets (elements) in the fp16 weight pool ([K,N] row-major)
#define OFF_QKV 0
#define OFF_WU  (OFF_QKV + Lv * Dv * QKVN)
#define OFF_WD  (OFF_WU + Lv * Dv * FFNv)
#define OFF_WO  (OFF_WD + Lv * FFNv * Dv)
#define W_TOTAL (OFF_WO + Dv * VOCABv)

#define QKV4 (Lv * Dv * QKVN / 4)
#define WU4  (Lv * Dv * FFNv / 4)
#define WD4  (Lv * FFNv * Dv / 4)
#define WO4  (Dv * VOCABv / 4)
#define TOT4 (QKV4 + WU4 + WD4 + WO4)
#define BIA4 (Lv * QKVN / 4)
#define RFN  (Lv * Hv * HDv * HDv)
#define RF4  (RFN / 4)

// -------------------- scratch (device globals; no allocs) --------------------
__device__ float g_x[NTOK * Dv];
__device__ float g_a[NTOK * Dv];
__device__ float g_qkv[NTOK * QKVN];
__device__ float g_qf[NTOK * Dv];
__device__ float g_kf[NTOK * Dv];
__device__ float g_S[Bv * Hv * NCHUNK * HDv * HDv];
__device__ float g_z[Bv * Hv * NCHUNK * HDv];
__device__ float g_bqkv[Lv * QKVN];
__device__ float g_part[2 * NTOK * Dv];
__device__ __half g_xh[NTOK * Dv];
__device__ __half g_xl[NTOK * Dv];
__device__ __half g_hh[NTOK * FFNv];
__device__ __half g_wh[W_TOTAL];
__device__ __half g_rfh[RFN];
__device__ __half g_rfl[RFN];

__device__ __forceinline__ void split_fp16(float v, __half& h, __half& l) {
    h = __float2half_rn(v);
    l = __float2half_rn(v - __half2float(h));
}

// -------------------- ONE fused weight conversion + bias pack + rf hi/lo ---------
__global__ void convw_all(const float* __restrict__ Wq, const float* __restrict__ Wk,
                          const float* __restrict__ Wv, const float* __restrict__ WU,
                          const float* __restrict__ WV, const float* __restrict__ Wout,
                          const float* __restrict__ bq, const float* __restrict__ bk,
                          const float* __restrict__ bvp, const float* __restrict__ rfs) {
    int idx = blockIdx.x * blockDim.x + threadIdx.x;
    if (idx < TOT4) {
        const float* src;
        int e;
        if (idx < QKV4) {
            e = idx * 4;
            int l = e / (Dv * QKVN);
            int r = e % (Dv * QKVN);
            int k = r / QKVN, col = r % QKVN;
            if (col < 512)       src = Wq + (size_t)l * Dv * Dv + k * 512 + col;
            else if (col < 1024) src = Wk + (size_t)l * Dv * Dv + k * 512 + col - 512;
            else                 src = Wv + (size_t)l * Dv * Dv + k * 512 + col - 1024;
            e += OFF_QKV;
        } else if (idx < QKV4 + WU4) {
            int e2 = (idx - QKV4) * 4;
            src = WU + e2;
            e = OFF_WU + e2;
        } else if (idx < QKV4 + WU4 + WD4) {
            int e2 = (idx - QKV4 - WU4) * 4;
            src = WV + e2;
            e = OFF_WD + e2;
        } else {
            int e2 = (idx - QKV4 - WU4 - WD4) * 4;
            src = Wout + e2;
            e = OFF_WO + e2;
        }
        float4 v = *(const float4*)src;
        ((__half2*)(g_wh + e))[0] = __half2(__float2half_rn(v.x), __float2half_rn(v.y));
        ((__half2*)(g_wh + e))[1] = __half2(__float2half_rn(v.z), __float2half_rn(v.w));
    } else if (idx < TOT4 + BIA4) {
        int j = (idx - TOT4) * 4;
#pragma unroll
        for (int q = 0; q < 4; q++) {
            int jj = j + q;
            int l = jj / QKVN, c = jj % QKVN;
            float v;
            if (c < 512) v = bq[l * Dv + c];
            else if (c < 1024) v = bk[l * Dv + c - 512];
            else v = bvp[l * Dv + c - 1024];
            g_bqkv[jj] = v;
        }
    } else if (idx < TOT4 + BIA4 + RF4) {
        int j = (idx - TOT4 - BIA4) * 4;
        float4 v = *(const float4*)(rfs + j);
        __half h0, h1, h2, h3, l0, l1, l2, l3;
        split_fp16(v.x, h0, l0); split_fp16(v.y, h1, l1);
        split_fp16(v.z, h2, l2); split_fp16(v.w, h3, l3);
        ((__half2*)(g_rfh + j))[0] = __half2(h0, h1);
        ((__half2*)(g_rfh + j))[1] = __half2(h2, h3);
        ((__half2*)(g_rfl + j))[0] = __half2(l0, l1);
        ((__half2*)(g_rfl + j))[1] = __half2(l2, l3);
    }
}

// -------------------- embedding + sinusoidal positions --------------------
__global__ void embed_kernel(const int* __restrict__ tokens,
                             const float* __restrict__ emb) {
    int idx = blockIdx.x * blockDim.x + threadIdx.x;
    if (idx >= NTOK * Dv) return;
    int n = idx >> 9;
    int j = idx & 511;
    int t = n & (Tv - 1);
    float val;
    const float c = 9.210340371976184f / 256.f;
    if (j < 256) {
        int tok = tokens[n];
        val = emb[tok * 256 + j];
    } else if (j < 384) {
        int i = j - 256;
        val = sinf((float)t * expf(-(2.f * (float)i) * c));
    } else {
        int i = j - 384;
        val = cosf((float)t * expf(-(2.f * (float)i) * c));
    }
    g_x[idx] = val;
    __half h, l;
    split_fp16(val, h, l);
    g_xh[idx] = h;
    g_xl[idx] = l;
}

// -------------------- mma helpers --------------------
__device__ __forceinline__ void ldsm_x4(uint32_t* r, const void* p) {
    uint32_t a = (uint32_t)__cvta_generic_to_shared(p);
    asm volatile("ldmatrix.sync.aligned.m8n8.x4.shared.b16 {%0,%1,%2,%3},[%4];"
        : "=r"(r[0]), "=r"(r[1]), "=r"(r[2]), "=r"(r[3]) : "r"(a));
}
__device__ __forceinline__ void ldsm_x4_t(uint32_t* r, const void* p) {
    uint32_t a = (uint32_t)__cvta_generic_to_shared(p);
    asm volatile("ldmatrix.sync.aligned.m8n8.x4.trans.shared.b16 {%0,%1,%2,%3},[%4];"
        : "=r"(r[0]), "=r"(r[1]), "=r"(r[2]), "=r"(r[3]) : "r"(a));
}
__device__ __forceinline__ void mma16816(float* c, const uint32_t* a, const uint32_t* b) {
    asm volatile("mma.sync.aligned.m16n8k16.row.col.f32.f16.f16.f32 "
        "{%0,%1,%2,%3},{%4,%5,%6,%7},{%8,%9},{%0,%1,%2,%3};"
        : "+f"(c[0]), "+f"(c[1]), "+f"(c[2]), "+f"(c[3])
        : "r"(a[0]), "r"(a[1]), "r"(a[2]), "r"(a[3]), "r"(b[0]), "r"(b[1]));
}
__device__ __forceinline__ void cp16(void* smem, const void* gmem) {
    uint32_t s = (uint32_t)__cvta_generic_to_shared(smem);
    asm volatile("cp.async.cg.shared.global [%0], [%1], 16;" :: "r"(s), "l"(gmem));
}
#define CP_COMMIT() asm volatile("cp.async.commit_group;")
#define CP_WAIT(n)  asm volatile("cp.async.wait_group %0;" :: "n"(n))

#define PADA 72
#define PADB 136
#define A_TILE 36864
#define B_TILE 34816

// -------------------- tensor-core GEMM, fp16, BK=64, 2-stage cp.async ----------
// mode 0: fp32 out + bias. mode 1: gelu -> fp16 (Ch). mode 2: split-K partials (no bias).
template <int TERMS>
__global__ void __launch_bounds__(256, 2)
gemm_tc(const __half* __restrict__ Ahg, const __half* __restrict__ Alg,
        const __half* __restrict__ Bhg,
        const float* __restrict__ bias, float* __restrict__ C,
        __half* __restrict__ Ch,
        int M, int N, int lda, int ldb, int Kext, int mode) {
    extern __shared__ char smraw[];
    __half* AsH = (__half*)(smraw);
    __half* AsL = (__half*)(smraw + A_TILE);
    __half* BsH = (__half*)(smraw + (TERMS == 2 ? 2 * A_TILE : A_TILE));

    if (mode == 2) {
        size_t ko = (size_t)blockIdx.z * Kext;
        Ahg += ko;
        if (TERMS == 2) Alg += ko;
        Bhg += ko * ldb;
        C += (size_t)blockIdx.z * M * N;
    }

    int tid = threadIdx.x;
    int wid = tid >> 5, lane = tid & 31;
    int m_w = (wid >> 1) * 32, n_w = (wid & 1) * 64;
    int row0 = blockIdx.y * 128, col0 = blockIdx.x * 128;

    float acc[2][8][4];
#pragma unroll
    for (int i = 0; i < 2; i++)
#pragma unroll
        for (int j = 0; j < 8; j++)
#pragma unroll
            for (int q = 0; q < 4; q++) acc[i][j][q] = 0.f;

    int a_row = tid >> 1, a_colb = (tid & 1) * 32;
    int b_row = tid >> 2, b_colb = (tid & 3) * 32;

    auto loadStage = [&](int stage, int buf) {
        int k0 = stage * 64;
        const __half* aH = Ahg + (size_t)(row0 + a_row) * lda + k0 + a_colb;
        int sa = (buf * 128 + a_row) * PADA + a_colb;
        const __half* bH = Bhg + (size_t)(k0 + b_row) * ldb + col0 + b_colb;
        int sb = (buf * 64 + b_row) * PADB + b_colb;
#pragma unroll
        for (int i = 0; i < 4; i++) {
            cp16(AsH + sa + i * 8, aH + i * 8);
            cp16(BsH + sb + i * 8, bH + i * 8);
        }
        if (TERMS == 2) {
            const __half* aL = Alg + (size_t)(row0 + a_row) * lda + k0 + a_colb;
#pragma unroll
            for (int i = 0; i < 4; i++) cp16(AsL + sa + i * 8, aL + i * 8);
        }
        CP_COMMIT();
    };

    auto compute = [&](int buf) {
#pragma unroll
        for (int kk = 0; kk < 64; kk += 16) {
            uint32_t Ahf[2][4], Alf[2][4], Bhf[8][2];
#pragma unroll
            for (int i = 0; i < 2; i++) {
                int idx = (buf * 128 + m_w + i * 16 + (lane & 15)) * PADA + kk + (lane >> 4) * 8;
                ldsm_x4(Ahf[i], AsH + idx);
                if (TERMS == 2) ldsm_x4(Alf[i], AsL + idx);
            }
#pragma unroll
            for (int p = 0; p < 4; p++) {
                int idx = (buf * 64 + kk + (lane & 15)) * PADB + n_w + p * 16 + (lane >> 4) * 8;
                uint32_t r[4];
                ldsm_x4_t(r, BsH + idx);
                Bhf[2 * p][0] = r[0]; Bhf[2 * p][1] = r[1];
                Bhf[2 * p + 1][0] = r[2]; Bhf[2 * p + 1][1] = r[3];
            }
#pragma unroll
            for (int i = 0; i < 2; i++)
#pragma unroll
                for (int j = 0; j < 8; j++) {
                    mma16816(acc[i][j], Ahf[i], Bhf[j]);
                    if (TERMS == 2) mma16816(acc[i][j], Alf[i], Bhf[j]);
                }
        }
    };

    int nsteps = Kext >> 6;
    loadStage(0, 0);
    for (int s = 0; s < nsteps; s++) {
        CP_WAIT(0);
        __syncthreads();
        if (s + 1 < nsteps) loadStage(s + 1, (s + 1) & 1);
        compute(s & 1);
    }

    int g = lane >> 2, tg = lane & 3;
#pragma unroll
    for (int i = 0; i < 2; i++) {
#pragma unroll
        for (int j = 0; j < 8; j++) {
            int cc = col0 + n_w + j * 8 + tg * 2;
            float b0 = 0.f, b1 = 0.f;
            if (mode != 2) { b0 = bias[cc]; b1 = bias[cc + 1]; }
#pragma unroll
            for (int half = 0; half < 2; half++) {
                int r = row0 + m_w + i * 16 + g + half * 8;
                float v0 = acc[i][j][half * 2 + 0] + b0;
                float v1 = acc[i][j][half * 2 + 1] + b1;
                if (mode == 1) {
                    v0 = 0.5f * v0 * (1.f + erff(v0 * 0.7071067811865475f));
                    v1 = 0.5f * v1 * (1.f + erff(v1 * 0.7071067811865475f));
                    *(__half2*)(Ch + (size_t)r * N + cc) =
                        __half2(__float2half_rn(v0), __float2half_rn(v1));
                } else {
                    *(float2*)(C + (size_t)r * N + cc) = make_float2(v0, v1);
                }
            }
        }
    }
}

// -------------------- generic split-K=2 reduce + bias (N = power of 2) ----------
__global__ void reduce2(const float* __restrict__ part, const float* __restrict__ bias,
                        float* __restrict__ out, int total4, int nmask) {
    int i = blockIdx.x * blockDim.x + threadIdx.x;
    if (i >= total4) return;
    float4 a = ((const float4*)part)[i];
    float4 b = ((const float4*)part)[i + total4];
    int col = (i * 4) & nmask;
    float4 o;
    o.x = a.x + b.x + bias[col + 0];
    o.y = a.y + b.y + bias[col + 1];
    o.z = a.z + b.z + bias[col + 2];
    o.w = a.w + b.w + bias[col + 3];
    ((float4*)out)[i] = o;
}

// -------------------- fused FAVOR+ features (tensor-core) + per-chunk sums -------
// grid (NTOK/32, Hv), 128 threads, ONE chunk per block.
// Features: dq = xp@rf via 3-term fp16 mma (fp32-accurate); exp in fp32.
// Outer product S_c, z_c stays scalar fp32 (range safety).
__global__ void __launch_bounds__(128)
favor_chunk(const __half* __restrict__ rfhp, const __half* __restrict__ rflp) {
    __shared__ __half XH[64][PADA];    // stacked xq(0-31), xk(32-63)
    __shared__ __half XL[64][PADA];
    __shared__ __half RFH[64][PADA];   // [d][m]
    __shared__ __half RFL[64][PADA];
    __shared__ float norm[64];

    int tile = blockIdx.x, h = blockIdx.y;
    int b = tile >> 6, c = tile & 63;
    int bh = b * Hv + h;
    int tid = threadIdx.x;
    int wid = tid >> 5, lane = tid & 31;
    int t0 = c * CHUNK;
    const float sc = 0.3535533905932738f;  // 64^{-1/4}
    const float sc2 = 0.125f;              // sc^2

    // stage X (scaled, fp16 hi/lo): 1024 float4-chunks of 4
    for (int i = tid; i < 1024; i += 128) {
        int row = i >> 4, c4 = (i & 15) * 4;
        size_t src = (size_t)(b * Tv + t0 + (row & 31)) * QKVN +
                     ((row < 32) ? 0 : 512) + h * HDv + c4;
        float4 v = *(const float4*)(g_qkv + src);
        v.x *= sc; v.y *= sc; v.z *= sc; v.w *= sc;
        __half h0, h1, h2, h3, l0, l1, l2, l3;
        split_fp16(v.x, h0, l0); split_fp16(v.y, h1, l1);
        split_fp16(v.z, h2, l2); split_fp16(v.w, h3, l3);
        *(__half2*)&XH[row][c4] = __half2(h0, h1);
        *(__half2*)&XH[row][c4 + 2] = __half2(h2, h3);
        *(__half2*)&XL[row][c4] = __half2(l0, l1);
        *(__half2*)&XL[row][c4 + 2] = __half2(l2, l3);
    }
    // stage rf hi/lo
    const __half* rh = rfhp + (size_t)h * 4096;
    const __half* rl = rflp + (size_t)h * 4096;
    for (int i = tid; i < 512; i += 128) {
        int row = i >> 3, c8 = (i & 7) * 8;
        *(uint4*)&RFH[row][c8] = *(const uint4*)(rh + row * 64 + c8);
        *(uint4*)&RFL[row][c8] = *(const uint4*)(rl + row * 64 + c8);
    }
    // norms: thread pair per row, from gmem (L1-hot)
    {
        int row = tid >> 1, hf = tid & 1;
        size_t src = (size_t)(b * Tv + t0 + (row & 31)) * QKVN +
                     ((row < 32) ? 0 : 512) + h * HDv + hf * 32;
        float s2 = 0.f;
#pragma unroll
        for (int i = 0; i < 8; i++) {
            float4 v = *(const float4*)(g_qkv + src + i * 4);
            s2 += v.x * v.x + v.y * v.y + v.z * v.z + v.w * v.w;
        }
        s2 += __shfl_xor_sync(0xffffffffu, s2, 1);
        if (hf == 0) norm[row] = s2 * sc2;
    }
    __syncthreads();

    // feature mma: warp w -> rows 16w..16w+15 (stacked), all 64 cols
    int m_w = wid * 16;
    float acc[8][4];
#pragma unroll
    for (int j = 0; j < 8; j++)
#pragma unroll
        for (int q = 0; q < 4; q++) acc[j][q] = 0.f;
#pragma unroll
    for (int k = 0; k < 4; k++) {
        int kk = k * 16;
        uint32_t AH[4], AL[4];
        int aidx = m_w + (lane & 15);
        ldsm_x4(AH, &XH[aidx][kk + (lane >> 4) * 8]);
        ldsm_x4(AL, &XL[aidx][kk + (lane >> 4) * 8]);
#pragma unroll
        for (int p = 0; p < 4; p++) {
            uint32_t BH[4], BL[4];
            int bidx = kk + (lane & 15);
            int bcol = p * 16 + (lane >> 4) * 8;
            ldsm_x4_t(BH, &RFH[bidx][bcol]);
            ldsm_x4_t(BL, &RFL[bidx][bcol]);
            mma16816(acc[2 * p], AH, BH);
            mma16816(acc[2 * p], AL, BH);
            mma16816(acc[2 * p], AH, BL);
            mma16816(acc[2 * p + 1], AH, BH + 2);
            mma16816(acc[2 * p + 1], AL, BH + 2);
            mma16816(acc[2 * p + 1], AH, BL + 2);
        }
    }
    __syncthreads();   // done with XH/XL/RFH/RFL -> safe to alias

    float (*kf_s)[68] = (float(*)[68])&XH[0][0];   // 32x68 fp32 (8704B <= 9216B)
    float (*V_s)[68]  = (float(*)[68])&RFH[0][0];

    // exp + write qf/kf; k-warps also scatter kf into kf_s
    int g = lane >> 2, tg = lane & 3;
#pragma unroll
    for (int j = 0; j < 8; j++) {
        int col = j * 8 + tg * 2;
#pragma unroll
        for (int half = 0; half < 2; half++) {
            int row = m_w + g + half * 8;
            float hn = 0.5f * norm[row];
            float v0 = expf(acc[j][half * 2 + 0] - hn);
            float v1 = expf(acc[j][half * 2 + 1] - hn);
            int trow = row & 31;
            size_t dst = (size_t)(b * Tv + t0 + trow) * Dv + h * HDv + col;
            if (row < 32) {
                *(float2*)(g_qf + dst) = make_float2(v0, v1);
            } else {
                *(float2*)(g_kf + dst) = make_float2(v0, v1);
                kf_s[trow][col] = v0;
                kf_s[trow][col + 1] = v1;
            }
        }
    }
    // stage V (fp32)
    for (int i = tid; i < 512; i += 128) {
        int tl = i >> 4, c4 = (i & 15) * 4;
        size_t vb = (size_t)(b * Tv + t0 + tl) * QKVN + 1024 + h * HDv + c4;
        *(float4*)&V_s[tl][c4] = *(const float4*)(g_qkv + vb);
    }
    __syncthreads();

    // chunk outer-product sums: S_c[m][d] = sum_t kf[t][m] V[t][d]
    int om0 = (tid >> 3) * 4, od0 = (tid & 7) * 8;
    float sacc[4][8];
#pragma unroll
    for (int r = 0; r < 4; r++)
#pragma unroll
        for (int q = 0; q < 8; q++) sacc[r][q] = 0.f;
#pragma unroll 8
    for (int t = 0; t < 32; t++) {
        float4 km = *(const float4*)&kf_s[t][om0];
        float4 v0 = *(const float4*)&V_s[t][od0];
        float4 v1 = *(const float4*)&V_s[t][od0 + 4];
        float kr[4] = {km.x, km.y, km.z, km.w};
        float vr[8] = {v0.x, v0.y, v0.z, v0.w, v1.x, v1.y, v1.z, v1.w};
#pragma unroll
        for (int r = 0; r < 4; r++)
#pragma unroll
            for (int q = 0; q < 8; q++) sacc[r][q] += kr[r] * vr[q];
    }
    int sb = (bh * NCHUNK + c) * 4096;
#pragma unroll
    for (int r = 0; r < 4; r++) {
        *(float4*)(g_S + sb + (om0 + r) * 64 + od0) =
            make_float4(sacc[r][0], sacc[r][1], sacc[r][2], sacc[r][3]);
        *(float4*)(g_S + sb + (om0 + r) * 64 + od0 + 4) =
            make_float4(sacc[r][4], sacc[r][5], sacc[r][6], sacc[r][7]);
    }
    if (tid < 64) {
        float z = 0.f;
#pragma unroll
        for (int t = 0; t < 32; t++) z += kf_s[t][tid];
        g_z[(bh * NCHUNK + c) * 64 + tid] = z;
    }
}

// -------------------- exclusive scans over chunks (S and z fused) ---------------
__global__ void __launch_bounds__(64)
attn_scan() {
    int bh = blockIdx.x >> 6, m = blockIdx.x & 63, d = threadIdx.x;
    float v[NCHUNK];
#pragma unroll
    for (int c = 0; c < NCHUNK; c++)
        v[c] = g_S[((bh * NCHUNK + c) << 12) + m * 64 + d];
    float acc = 0.f;
#pragma unroll
    for (int c = 0; c < NCHUNK; c++) {
        g_S[((bh * NCHUNK + c) << 12) + m * 64 + d] = acc;
        acc += v[c];
    }
    if (m == 0) {
        float zv[NCHUNK];
#pragma unroll
        for (int c = 0; c < NCHUNK; c++) zv[c] = g_z[(bh * NCHUNK + c) * 64 + d];
        float za = 0.f;
#pragma unroll
        for (int c = 0; c < NCHUNK; c++) {
            g_z[(bh * NCHUNK + c) * 64 + d] = za;
            za += zv[c];
        }
    }
}

// -------------------- chunked-GEMM apply --------------------
__global__ void __launch_bounds__(128)
attn_apply() {
    int c = blockIdx.x, bh = blockIdx.y;
    int b = bh / Hv, h = bh % Hv;
    int tid = threadIdx.x;
    __shared__ float Qf[32][68], Kf[32][68], V[32][68];
    __shared__ float S0[64][68];
    __shared__ float A[32][36];
    __shared__ float z0[64], sden[32];
    int t0 = c * CHUNK;
    int sb = (bh * NCHUNK + c) * 4096;

    for (int i = tid; i < 512; i += 128) {
        int row = i >> 4, c4 = (i & 15) * 4;
        size_t qb = (size_t)(b * Tv + t0 + row) * Dv + h * HDv + c4;
        size_t vb = (size_t)(b * Tv + t0 + row) * QKVN + 1024 + h * HDv + c4;
        *(float4*)&Qf[row][c4] = *(const float4*)(g_qf + qb);
        *(float4*)&Kf[row][c4] = *(const float4*)(g_kf + qb);
        *(float4*)&V[row][c4] = *(const float4*)(g_qkv + vb);
    }
    for (int i = tid; i < 1024; i += 128) {
        int m = i >> 4, c4 = (i & 15) * 4;
        *(float4*)&S0[m][c4] = *(const float4*)(g_S + sb + m * 64 + c4);
    }
    if (tid < 16)
        *(float4*)&z0[tid * 4] = *(const float4*)(g_z + (bh * NCHUNK + c) * 64 + tid * 4);
    __syncthreads();

    int i0 = (tid >> 4) * 4;
    int j0 = tid & 15;
    {
        float a0[4] = {0.f, 0.f, 0.f, 0.f}, a1[4] = {0.f, 0.f, 0.f, 0.f};
#pragma unroll
        for (int k = 0; k < 64; k += 4) {
            float4 ka = *(const float4*)&Kf[j0][k];
            float4 kb = *(const float4*)&Kf[j0 + 16][k];
#pragma unroll
            for (int r = 0; r < 4; r++) {
                float4 q = *(const float4*)&Qf[i0 + r][k];
                a0[r] += q.x * ka.x + q.y * ka.y + q.z * ka.z + q.w * ka.w;
                a1[r] += q.x * kb.x + q.y * kb.y + q.z * kb.z + q.w * kb.w;
            }
        }
#pragma unroll
        for (int r = 0; r < 4; r++) {
            A[i0 + r][j0] = (j0 <= i0 + r) ? a0[r] : 0.f;
            A[i0 + r][j0 + 16] = (j0 + 16 <= i0 + r) ? a1[r] : 0.f;
        }
    }
    __syncthreads();

    if (tid < 32) {
        float dn = 1e-16f;
#pragma unroll 8
        for (int m = 0; m < 64; m++) dn += Qf[tid][m] * z0[m];
#pragma unroll
        for (int j = 0; j < 32; j++) dn += A[tid][j];
        sden[tid] = dn;
    }

    int d0 = (tid & 15) * 4;
    float acc[4][4];
#pragma unroll
    for (int r = 0; r < 4; r++)
#pragma unroll
        for (int q = 0; q < 4; q++) acc[r][q] = 0.f;
#pragma unroll 4
    for (int m = 0; m < 64; m += 4) {
        float4 qv[4], sv[4];
#pragma unroll
        for (int r = 0; r < 4; r++) qv[r] = *(const float4*)&Qf[i0 + r][m];
#pragma unroll
        for (int kk = 0; kk < 4; kk++) sv[kk] = *(const float4*)&S0[m + kk][d0];
#pragma unroll
        for (int r = 0; r < 4; r++) {
            float qr[4] = {qv[r].x, qv[r].y, qv[r].z, qv[r].w};
#pragma unroll
            for (int kk = 0; kk < 4; kk++) {
                acc[r][0] += qr[kk] * sv[kk].x;
                acc[r][1] += qr[kk] * sv[kk].y;
                acc[r][2] += qr[kk] * sv[kk].z;
                acc[r][3] += qr[kk] * sv[kk].w;
            }
        }
    }
#pragma unroll 2
    for (int j = 0; j < 32; j += 4) {
        float4 av[4], vv[4];
#pragma unroll
        for (int r = 0; r < 4; r++) av[r] = *(const float4*)&A[i0 + r][j];
#pragma unroll
        for (int kk = 0; kk < 4; kk++) vv[kk] = *(const float4*)&V[j + kk][d0];
#pragma unroll
        for (int r = 0; r < 4; r++) {
            float ar[4] = {av[r].x, av[r].y, av[r].z, av[r].w};
#pragma unroll
            for (int kk = 0; kk < 4; kk++) {
                acc[r][0] += ar[kk] * vv[kk].x;
                acc[r][1] += ar[kk] * vv[kk].y;
                acc[r][2] += ar[kk] * vv[kk].z;
                acc[r][3] += ar[kk] * vv[kk].w;
            }
        }
    }
    __syncthreads();
#pragma unroll
    for (int r = 0; r < 4; r++) {
        float inv = 1.f / sden[i0 + r];
        float4 o = make_float4(acc[r][0] * inv, acc[r][1] * inv,
                               acc[r][2] * inv, acc[r][3] * inv);
        *(float4*)(g_a + (size_t)(b * Tv + t0 + i0 + r) * Dv + h * HDv + d0) = o;
    }
}

// -------------------- LayerNorm + residual add (+ fp16 hi/lo of new x) ----------
template <int RED>
__global__ void __launch_bounds__(128)
ln_add(const float* __restrict__ in0, const float* __restrict__ in1,
       const float* __restrict__ pbias,
       const float* __restrict__ g, const float* __restrict__ bl,
       float* __restrict__ x) {
    int n = blockIdx.x, tid = threadIdx.x;
    int lane = tid & 31, w = tid >> 5;
    float v[4];
    float s = 0.f, s2 = 0.f;
#pragma unroll
    for (int i = 0; i < 4; i++) {
        int j = tid + i * 128;
        float t = in0[(size_t)n * Dv + j];
        if (RED) t += in1[(size_t)n * Dv + j] + pbias[j];
        v[i] = t;
        s += t;
        s2 += t * t;
    }
    __shared__ float sh[8];
#pragma unroll
    for (int off = 16; off; off >>= 1) {
        s += __shfl_down_sync(0xffffffffu, s, off);
        s2 += __shfl_down_sync(0xffffffffu, s2, off);
    }
    if (lane == 0) { sh[w] = s; sh[4 + w] = s2; }
    __syncthreads();
    float S = sh[0] + sh[1] + sh[2] + sh[3];
    float S2 = sh[4] + sh[5] + sh[6] + sh[7];
    float mu = S * (1.f / Dv);
    float var = S2 * (1.f / Dv) - mu * mu;
    float rs = rsqrtf(var + 1e-5f);
#pragma unroll
    for (int i = 0; i < 4; i++) {
        int j = tid + i * 128;
        size_t idx = (size_t)n * Dv + j;
        float nv = x[idx] + (v[i] - mu) * rs * g[j] + bl[j];
        x[idx] = nv;
        __half h, l;
        split_fp16(nv, h, l);
        g_xh[idx] = h;
        g_xl[idx] = l;
    }
}

// -------------------- host driver --------------------
extern "C" void kernel_launch(void* const* d_in, const int* in_sizes, int n_in,
                              void* d_out, int out_size) {
    const int*   tokens = (const int*)d_in[0];
    const float* emb    = (const float*)d_in[1];
    const float* Wq     = (const float*)d_in[2];
    const float* bq     = (const float*)d_in[3];
    const float* Wk     = (const float*)d_in[4];
    const float* bk     = (const float*)d_in[5];
    const float* Wv     = (const float*)d_in[6];
    const float* bvp    = (const float*)d_in[7];
    const float* rfs    = (const float*)d_in[8];
    const float* ln1g   = (const float*)d_in[9];
    const float* ln1b   = (const float*)d_in[10];
    const float* ln2g   = (const float*)d_in[11];
    const float* ln2b   = (const float*)d_in[12];
    const float* WU     = (const float*)d_in[13];
    const float* bU     = (const float*)d_in[14];
    const float* WV     = (const float*)d_in[15];
    const float* bV     = (const float*)d_in[16];
    const float* Wout   = (const float*)d_in[17];
    const float* bout   = (const float*)d_in[18];
    float* out = (float*)d_out;

    static float *px = nullptr, *pa, *pqkv, *pbqkv, *ppart;
    static __half *pxh, *pxl, *phh, *pwh, *prfh, *prfl;
    if (!px) {
        cudaGetSymbolAddress((void**)&px, g_x);
        cudaGetSymbolAddress((void**)&pa, g_a);
        cudaGetSymbolAddress((void**)&pqkv, g_qkv);
        cudaGetSymbolAddress((void**)&pbqkv, g_bqkv);
        cudaGetSymbolAddress((void**)&ppart, g_part);
        cudaGetSymbolAddress((void**)&pxh, g_xh);
        cudaGetSymbolAddress((void**)&pxl, g_xl);
        cudaGetSymbolAddress((void**)&phh, g_hh);
        cudaGetSymbolAddress((void**)&pwh, g_wh);
        cudaGetSymbolAddress((void**)&prfh, g_rfh);
        cudaGetSymbolAddress((void**)&prfl, g_rfl);
        cudaFuncSetAttribute(gemm_tc<1>, cudaFuncAttributeMaxDynamicSharedMemorySize,
                             A_TILE + B_TILE);
        cudaFuncSetAttribute(gemm_tc<2>, cudaFuncAttributeMaxDynamicSharedMemorySize,
                             2 * A_TILE + B_TILE);
    }

    convw_all<<<(TOT4 + BIA4 + RF4 + 255) / 256, 256>>>(Wq, Wk, Wv, WU, WV, Wout,
                                                        bq, bk, bvp, rfs);
    embed_kernel<<<(NTOK * Dv + 255) / 256, 256>>>(tokens, emb);

    for (int l = 0; l < Lv; l++) {
        gemm_tc<1><<<dim3(QKVN / 128, NTOK / 128), 256, A_TILE + B_TILE>>>(
            pxh, nullptr, pwh + OFF_QKV + (size_t)l * Dv * QKVN, pbqkv + l * QKVN,
            pqkv, nullptr, NTOK, QKVN, Dv, QKVN, Dv, 0);

        favor_chunk<<<dim3(NTOK / 32, Hv), 128>>>(prfh + (size_t)l * Hv * 4096,
                                                  prfl + (size_t)l * Hv * 4096);
        attn_scan<<<Bv * Hv * HDv, 64>>>();
        attn_apply<<<dim3(NCHUNK, Bv * Hv), 128>>>();

        ln_add<0><<<NTOK, 128>>>(pa, nullptr, nullptr,
                                 ln1g + l * Dv, ln1b + l * Dv, px);

        gemm_tc<1><<<dim3(FFNv / 128, NTOK / 128), 256, A_TILE + B_TILE>>>(
            pxh, nullptr, pwh + OFF_WU + (size_t)l * Dv * FFNv, bU + l * FFNv,
            nullptr, phh, NTOK, FFNv, Dv, FFNv, Dv, 1);

        gemm_tc<1><<<dim3(Dv / 128, NTOK / 128, 2), 256, A_TILE + B_TILE>>>(
            phh, nullptr, pwh + OFF_WD + (size_t)l * FFNv * Dv, nullptr,
            ppart, nullptr, NTOK, Dv, FFNv, Dv, 1024, 2);

        ln_add<1><<<NTOK, 128>>>(ppart, ppart + (size_t)NTOK * Dv, bV + l * Dv,
                                 ln2g + l * Dv, ln2b + l * Dv, px);
    }

    gemm_tc<2><<<dim3(VOCABv / 128, NTOK / 128, 2), 256, 2 * A_TILE + B_TILE>>>(
        pxh, pxl, pwh + OFF_WO, nullptr, ppart, nullptr,
        NTOK, VOCABv, Dv, VOCABv, 256, 2);
    reduce2<<<(NTOK * VOCABv / 4 + 255) / 256, 256>>>(ppart, bout, out,
                                                      NTOK * VOCABv / 4, VOCABv - 1);
}

// round 15
// speedup vs baseline: 2.1749x; 1.0143x over previous
#include <cuda_runtime.h>
#include <cuda_fp16.h>
#include <math.h>
#include <stdint.h>

// Problem constants
#define Bv      2
#define Tv      2048
#define NTOK    (Bv * Tv)      // 4096
#define Dv      512
#define Hv      8
#define HDv     64
#define FFNv    2048
#define VOCABv  256
#define Lv      2
#define CHUNK   32
#define NCHUNK  (Tv / CHUNK)   // 64
#define QKVN    1536

// weight region offsets (elements) in the fp16 weight pool ([K,N] row-major)
#define OFF_QKV 0
#define OFF_WU  (OFF_QKV + Lv * Dv * QKVN)
#define OFF_WD  (OFF_WU + Lv * Dv * FFNv)
#define OFF_WO  (OFF_WD + Lv * FFNv * Dv)
#define W_TOTAL (OFF_WO + Dv * VOCABv)

#define QKV4 (Lv * Dv * QKVN / 4)
#define WU4  (Lv * Dv * FFNv / 4)
#define WD4  (Lv * FFNv * Dv / 4)
#define WO4  (Dv * VOCABv / 4)
#define TOT4 (QKV4 + WU4 + WD4 + WO4)
#define BIA4 (Lv * QKVN / 4)
#define RFN  (Lv * Hv * HDv * HDv)
#define RF4  (RFN / 4)

// -------------------- scratch (device globals; no allocs) --------------------
__device__ float g_x[NTOK * Dv];
__device__ float g_a[NTOK * Dv];
__device__ float g_qkv[NTOK * QKVN];
__device__ float g_qf[NTOK * Dv];
__device__ float g_kf[NTOK * Dv];
__device__ float g_S[Bv * Hv * NCHUNK * HDv * HDv];
__device__ float g_z[Bv * Hv * NCHUNK * HDv];
__device__ float g_bqkv[Lv * QKVN];
__device__ float g_part[2 * NTOK * Dv];
__device__ __half g_xh[NTOK * Dv];
__device__ __half g_xl[NTOK * Dv];
__device__ __half g_hh[NTOK * FFNv];
__device__ __half g_wh[W_TOTAL];
__device__ __half g_rfh[RFN];
__device__ __half g_rfl[RFN];

__device__ __forceinline__ void split_fp16(float v, __half& h, __half& l) {
    h = __float2half_rn(v);
    l = __float2half_rn(v - __half2float(h));
}

// -------------------- ONE fused weight conversion + bias pack + rf hi/lo ---------
__global__ void convw_all(const float* __restrict__ Wq, const float* __restrict__ Wk,
                          const float* __restrict__ Wv, const float* __restrict__ WU,
                          const float* __restrict__ WV, const float* __restrict__ Wout,
                          const float* __restrict__ bq, const float* __restrict__ bk,
                          const float* __restrict__ bvp, const float* __restrict__ rfs) {
    int idx = blockIdx.x * blockDim.x + threadIdx.x;
    if (idx < TOT4) {
        const float* src;
        int e;
        if (idx < QKV4) {
            e = idx * 4;
            int l = e / (Dv * QKVN);
            int r = e % (Dv * QKVN);
            int k = r / QKVN, col = r % QKVN;
            if (col < 512)       src = Wq + (size_t)l * Dv * Dv + k * 512 + col;
            else if (col < 1024) src = Wk + (size_t)l * Dv * Dv + k * 512 + col - 512;
            else                 src = Wv + (size_t)l * Dv * Dv + k * 512 + col - 1024;
            e += OFF_QKV;
        } else if (idx < QKV4 + WU4) {
            int e2 = (idx - QKV4) * 4;
            src = WU + e2;
            e = OFF_WU + e2;
        } else if (idx < QKV4 + WU4 + WD4) {
            int e2 = (idx - QKV4 - WU4) * 4;
            src = WV + e2;
            e = OFF_WD + e2;
        } else {
            int e2 = (idx - QKV4 - WU4 - WD4) * 4;
            src = Wout + e2;
            e = OFF_WO + e2;
        }
        float4 v = *(const float4*)src;
        ((__half2*)(g_wh + e))[0] = __half2(__float2half_rn(v.x), __float2half_rn(v.y));
        ((__half2*)(g_wh + e))[1] = __half2(__float2half_rn(v.z), __float2half_rn(v.w));
    } else if (idx < TOT4 + BIA4) {
        int j = (idx - TOT4) * 4;
#pragma unroll
        for (int q = 0; q < 4; q++) {
            int jj = j + q;
            int l = jj / QKVN, c = jj % QKVN;
            float v;
            if (c < 512) v = bq[l * Dv + c];
            else if (c < 1024) v = bk[l * Dv + c - 512];
            else v = bvp[l * Dv + c - 1024];
            g_bqkv[jj] = v;
        }
    } else if (idx < TOT4 + BIA4 + RF4) {
        int j = (idx - TOT4 - BIA4) * 4;
        float4 v = *(const float4*)(rfs + j);
        __half h0, h1, h2, h3, l0, l1, l2, l3;
        split_fp16(v.x, h0, l0); split_fp16(v.y, h1, l1);
        split_fp16(v.z, h2, l2); split_fp16(v.w, h3, l3);
        ((__half2*)(g_rfh + j))[0] = __half2(h0, h1);
        ((__half2*)(g_rfh + j))[1] = __half2(h2, h3);
        ((__half2*)(g_rfl + j))[0] = __half2(l0, l1);
        ((__half2*)(g_rfl + j))[1] = __half2(l2, l3);
    }
}

// -------------------- embedding + sinusoidal positions --------------------
__global__ void embed_kernel(const int* __restrict__ tokens,
                             const float* __restrict__ emb) {
    int idx = blockIdx.x * blockDim.x + threadIdx.x;
    if (idx >= NTOK * Dv) return;
    int n = idx >> 9;
    int j = idx & 511;
    int t = n & (Tv - 1);
    float val;
    const float c = 9.210340371976184f / 256.f;
    if (j < 256) {
        int tok = tokens[n];
        val = emb[tok * 256 + j];
    } else if (j < 384) {
        int i = j - 256;
        val = sinf((float)t * expf(-(2.f * (float)i) * c));
    } else {
        int i = j - 384;
        val = cosf((float)t * expf(-(2.f * (float)i) * c));
    }
    g_x[idx] = val;
    __half h, l;
    split_fp16(val, h, l);
    g_xh[idx] = h;
    g_xl[idx] = l;
}

// -------------------- mma helpers --------------------
__device__ __forceinline__ void ldsm_x4(uint32_t* r, const void* p) {
    uint32_t a = (uint32_t)__cvta_generic_to_shared(p);
    asm volatile("ldmatrix.sync.aligned.m8n8.x4.shared.b16 {%0,%1,%2,%3},[%4];"
        : "=r"(r[0]), "=r"(r[1]), "=r"(r[2]), "=r"(r[3]) : "r"(a));
}
__device__ __forceinline__ void ldsm_x4_t(uint32_t* r, const void* p) {
    uint32_t a = (uint32_t)__cvta_generic_to_shared(p);
    asm volatile("ldmatrix.sync.aligned.m8n8.x4.trans.shared.b16 {%0,%1,%2,%3},[%4];"
        : "=r"(r[0]), "=r"(r[1]), "=r"(r[2]), "=r"(r[3]) : "r"(a));
}
__device__ __forceinline__ void mma16816(float* c, const uint32_t* a, const uint32_t* b) {
    asm volatile("mma.sync.aligned.m16n8k16.row.col.f32.f16.f16.f32 "
        "{%0,%1,%2,%3},{%4,%5,%6,%7},{%8,%9},{%0,%1,%2,%3};"
        : "+f"(c[0]), "+f"(c[1]), "+f"(c[2]), "+f"(c[3])
        : "r"(a[0]), "r"(a[1]), "r"(a[2]), "r"(a[3]), "r"(b[0]), "r"(b[1]));
}
__device__ __forceinline__ void cp16(void* smem, const void* gmem) {
    uint32_t s = (uint32_t)__cvta_generic_to_shared(smem);
    asm volatile("cp.async.cg.shared.global [%0], [%1], 16;" :: "r"(s), "l"(gmem));
}
#define CP_COMMIT() asm volatile("cp.async.commit_group;")
#define CP_WAIT(n)  asm volatile("cp.async.wait_group %0;" :: "n"(n))

#define PADA 72
#define PADB 136
#define A_TILE 36864
#define B_TILE 34816

// -------------------- tensor-core GEMM, fp16, BK=64, 2-stage cp.async ----------
// mode 0: fp32 out + bias. mode 1: gelu -> fp16 (Ch). mode 2: split-K partials (no bias).
template <int TERMS>
__global__ void __launch_bounds__(256, 2)
gemm_tc(const __half* __restrict__ Ahg, const __half* __restrict__ Alg,
        const __half* __restrict__ Bhg,
        const float* __restrict__ bias, float* __restrict__ C,
        __half* __restrict__ Ch,
        int M, int N, int lda, int ldb, int Kext, int mode) {
    extern __shared__ char smraw[];
    __half* AsH = (__half*)(smraw);
    __half* AsL = (__half*)(smraw + A_TILE);
    __half* BsH = (__half*)(smraw + (TERMS == 2 ? 2 * A_TILE : A_TILE));

    if (mode == 2) {
        size_t ko = (size_t)blockIdx.z * Kext;
        Ahg += ko;
        if (TERMS == 2) Alg += ko;
        Bhg += ko * ldb;
        C += (size_t)blockIdx.z * M * N;
    }

    int tid = threadIdx.x;
    int wid = tid >> 5, lane = tid & 31;
    int m_w = (wid >> 1) * 32, n_w = (wid & 1) * 64;
    int row0 = blockIdx.y * 128, col0 = blockIdx.x * 128;

    float acc[2][8][4];
#pragma unroll
    for (int i = 0; i < 2; i++)
#pragma unroll
        for (int j = 0; j < 8; j++)
#pragma unroll
            for (int q = 0; q < 4; q++) acc[i][j][q] = 0.f;

    int a_row = tid >> 1, a_colb = (tid & 1) * 32;
    int b_row = tid >> 2, b_colb = (tid & 3) * 32;

    auto loadStage = [&](int stage, int buf) {
        int k0 = stage * 64;
        const __half* aH = Ahg + (size_t)(row0 + a_row) * lda + k0 + a_colb;
        int sa = (buf * 128 + a_row) * PADA + a_colb;
        const __half* bH = Bhg + (size_t)(k0 + b_row) * ldb + col0 + b_colb;
        int sb = (buf * 64 + b_row) * PADB + b_colb;
#pragma unroll
        for (int i = 0; i < 4; i++) {
            cp16(AsH + sa + i * 8, aH + i * 8);
            cp16(BsH + sb + i * 8, bH + i * 8);
        }
        if (TERMS == 2) {
            const __half* aL = Alg + (size_t)(row0 + a_row) * lda + k0 + a_colb;
#pragma unroll
            for (int i = 0; i < 4; i++) cp16(AsL + sa + i * 8, aL + i * 8);
        }
        CP_COMMIT();
    };

    auto compute = [&](int buf) {
#pragma unroll
        for (int kk = 0; kk < 64; kk += 16) {
            uint32_t Ahf[2][4], Alf[2][4], Bhf[8][2];
#pragma unroll
            for (int i = 0; i < 2; i++) {
                int idx = (buf * 128 + m_w + i * 16 + (lane & 15)) * PADA + kk + (lane >> 4) * 8;
                ldsm_x4(Ahf[i], AsH + idx);
                if (TERMS == 2) ldsm_x4(Alf[i], AsL + idx);
            }
#pragma unroll
            for (int p = 0; p < 4; p++) {
                int idx = (buf * 64 + kk + (lane & 15)) * PADB + n_w + p * 16 + (lane >> 4) * 8;
                uint32_t r[4];
                ldsm_x4_t(r, BsH + idx);
                Bhf[2 * p][0] = r[0]; Bhf[2 * p][1] = r[1];
                Bhf[2 * p + 1][0] = r[2]; Bhf[2 * p + 1][1] = r[3];
            }
#pragma unroll
            for (int i = 0; i < 2; i++)
#pragma unroll
                for (int j = 0; j < 8; j++) {
                    mma16816(acc[i][j], Ahf[i], Bhf[j]);
                    if (TERMS == 2) mma16816(acc[i][j], Alf[i], Bhf[j]);
                }
        }
    };

    int nsteps = Kext >> 6;
    loadStage(0, 0);
    for (int s = 0; s < nsteps; s++) {
        CP_WAIT(0);
        __syncthreads();
        if (s + 1 < nsteps) loadStage(s + 1, (s + 1) & 1);
        compute(s & 1);
    }

    int g = lane >> 2, tg = lane & 3;
#pragma unroll
    for (int i = 0; i < 2; i++) {
#pragma unroll
        for (int j = 0; j < 8; j++) {
            int cc = col0 + n_w + j * 8 + tg * 2;
            float b0 = 0.f, b1 = 0.f;
            if (mode != 2) { b0 = bias[cc]; b1 = bias[cc + 1]; }
#pragma unroll
            for (int half = 0; half < 2; half++) {
                int r = row0 + m_w + i * 16 + g + half * 8;
                float v0 = acc[i][j][half * 2 + 0] + b0;
                float v1 = acc[i][j][half * 2 + 1] + b1;
                if (mode == 1) {
                    v0 = 0.5f * v0 * (1.f + erff(v0 * 0.7071067811865475f));
                    v1 = 0.5f * v1 * (1.f + erff(v1 * 0.7071067811865475f));
                    *(__half2*)(Ch + (size_t)r * N + cc) =
                        __half2(__float2half_rn(v0), __float2half_rn(v1));
                } else {
                    *(float2*)(C + (size_t)r * N + cc) = make_float2(v0, v1);
                }
            }
        }
    }
}

// -------------------- generic split-K=2 reduce + bias (N = power of 2) ----------
__global__ void reduce2(const float* __restrict__ part, const float* __restrict__ bias,
                        float* __restrict__ out, int total4, int nmask) {
    int i = blockIdx.x * blockDim.x + threadIdx.x;
    if (i >= total4) return;
    float4 a = ((const float4*)part)[i];
    float4 b = ((const float4*)part)[i + total4];
    int col = (i * 4) & nmask;
    float4 o;
    o.x = a.x + b.x + bias[col + 0];
    o.y = a.y + b.y + bias[col + 1];
    o.z = a.z + b.z + bias[col + 2];
    o.w = a.w + b.w + bias[col + 3];
    ((float4*)out)[i] = o;
}

// -------------------- fused FAVOR+ features (tensor-core) + per-chunk sums -------
// grid (NTOK/32, Hv), 128 threads, ONE chunk per block.
// dq = xp@rf via 3-term fp16 mma. Norm via orthogonality: ||xp||^2 = sum_m dq[m]^2/64
// (rf rf^T = 64 I), computed from mma fragments — no second gmem pass.
__global__ void __launch_bounds__(128)
favor_chunk(const __half* __restrict__ rfhp, const __half* __restrict__ rflp) {
    __shared__ __half XH[64][PADA];    // stacked xq(0-31), xk(32-63)
    __shared__ __half XL[64][PADA];
    __shared__ __half RFH[64][PADA];   // [d][m]
    __shared__ __half RFL[64][PADA];

    int tile = blockIdx.x, h = blockIdx.y;
    int b = tile >> 6, c = tile & 63;
    int bh = b * Hv + h;
    int tid = threadIdx.x;
    int wid = tid >> 5, lane = tid & 31;
    int t0 = c * CHUNK;
    const float sc = 0.3535533905932738f;  // 64^{-1/4}

    // stage X (scaled, fp16 hi/lo)
    for (int i = tid; i < 1024; i += 128) {
        int row = i >> 4, c4 = (i & 15) * 4;
        size_t src = (size_t)(b * Tv + t0 + (row & 31)) * QKVN +
                     ((row < 32) ? 0 : 512) + h * HDv + c4;
        float4 v = *(const float4*)(g_qkv + src);
        v.x *= sc; v.y *= sc; v.z *= sc; v.w *= sc;
        __half h0, h1, h2, h3, l0, l1, l2, l3;
        split_fp16(v.x, h0, l0); split_fp16(v.y, h1, l1);
        split_fp16(v.z, h2, l2); split_fp16(v.w, h3, l3);
        *(__half2*)&XH[row][c4] = __half2(h0, h1);
        *(__half2*)&XH[row][c4 + 2] = __half2(h2, h3);
        *(__half2*)&XL[row][c4] = __half2(l0, l1);
        *(__half2*)&XL[row][c4 + 2] = __half2(l2, l3);
    }
    // stage rf hi/lo
    const __half* rh = rfhp + (size_t)h * 4096;
    const __half* rl = rflp + (size_t)h * 4096;
    for (int i = tid; i < 512; i += 128) {
        int row = i >> 3, c8 = (i & 7) * 8;
        *(uint4*)&RFH[row][c8] = *(const uint4*)(rh + row * 64 + c8);
        *(uint4*)&RFL[row][c8] = *(const uint4*)(rl + row * 64 + c8);
    }
    __syncthreads();

    // feature mma: warp w -> rows 16w..16w+15 (stacked), all 64 cols
    int m_w = wid * 16;
    float acc[8][4];
#pragma unroll
    for (int j = 0; j < 8; j++)
#pragma unroll
        for (int q = 0; q < 4; q++) acc[j][q] = 0.f;
#pragma unroll
    for (int k = 0; k < 4; k++) {
        int kk = k * 16;
        uint32_t AH[4], AL[4];
        int aidx = m_w + (lane & 15);
        ldsm_x4(AH, &XH[aidx][kk + (lane >> 4) * 8]);
        ldsm_x4(AL, &XL[aidx][kk + (lane >> 4) * 8]);
#pragma unroll
        for (int p = 0; p < 4; p++) {
            uint32_t BH[4], BL[4];
            int bidx = kk + (lane & 15);
            int bcol = p * 16 + (lane >> 4) * 8;
            ldsm_x4_t(BH, &RFH[bidx][bcol]);
            ldsm_x4_t(BL, &RFL[bidx][bcol]);
            mma16816(acc[2 * p], AH, BH);
            mma16816(acc[2 * p], AL, BH);
            mma16816(acc[2 * p], AH, BL);
            mma16816(acc[2 * p + 1], AH, BH + 2);
            mma16816(acc[2 * p + 1], AL, BH + 2);
            mma16816(acc[2 * p + 1], AH, BL + 2);
        }
    }

    // norms from fragments: hn[half] = 0.5 * sum_m dq^2 / 64  (rf rf^T = 64 I)
    float s20 = 0.f, s21 = 0.f;
#pragma unroll
    for (int j = 0; j < 8; j++) {
        s20 += acc[j][0] * acc[j][0] + acc[j][1] * acc[j][1];
        s21 += acc[j][2] * acc[j][2] + acc[j][3] * acc[j][3];
    }
    s20 += __shfl_xor_sync(0xffffffffu, s20, 1);
    s20 += __shfl_xor_sync(0xffffffffu, s20, 2);
    s21 += __shfl_xor_sync(0xffffffffu, s21, 1);
    s21 += __shfl_xor_sync(0xffffffffu, s21, 2);
    float hn[2] = {s20 * (1.f / 128.f), s21 * (1.f / 128.f)};
    __syncthreads();   // done with XH/XL/RFH/RFL -> safe to alias

    float (*kf_s)[68] = (float(*)[68])&XH[0][0];   // 32x68 fp32
    float (*V_s)[68]  = (float(*)[68])&RFH[0][0];

    // exp + write qf/kf; k-warps also scatter kf into kf_s
    int g = lane >> 2, tg = lane & 3;
#pragma unroll
    for (int j = 0; j < 8; j++) {
        int col = j * 8 + tg * 2;
#pragma unroll
        for (int half = 0; half < 2; half++) {
            int row = m_w + g + half * 8;
            float v0 = expf(acc[j][half * 2 + 0] - hn[half]);
            float v1 = expf(acc[j][half * 2 + 1] - hn[half]);
            int trow = row & 31;
            size_t dst = (size_t)(b * Tv + t0 + trow) * Dv + h * HDv + col;
            if (row < 32) {
                *(float2*)(g_qf + dst) = make_float2(v0, v1);
            } else {
                *(float2*)(g_kf + dst) = make_float2(v0, v1);
                kf_s[trow][col] = v0;
                kf_s[trow][col + 1] = v1;
            }
        }
    }
    // stage V (fp32)
    for (int i = tid; i < 512; i += 128) {
        int tl = i >> 4, c4 = (i & 15) * 4;
        size_t vb = (size_t)(b * Tv + t0 + tl) * QKVN + 1024 + h * HDv + c4;
        *(float4*)&V_s[tl][c4] = *(const float4*)(g_qkv + vb);
    }
    __syncthreads();

    // chunk outer-product sums: S_c[m][d] = sum_t kf[t][m] V[t][d]
    int om0 = (tid >> 3) * 4, od0 = (tid & 7) * 8;
    float sacc[4][8];
#pragma unroll
    for (int r = 0; r < 4; r++)
#pragma unroll
        for (int q = 0; q < 8; q++) sacc[r][q] = 0.f;
#pragma unroll 8
    for (int t = 0; t < 32; t++) {
        float4 km = *(const float4*)&kf_s[t][om0];
        float4 v0 = *(const float4*)&V_s[t][od0];
        float4 v1 = *(const float4*)&V_s[t][od0 + 4];
        float kr[4] = {km.x, km.y, km.z, km.w};
        float vr[8] = {v0.x, v0.y, v0.z, v0.w, v1.x, v1.y, v1.z, v1.w};
#pragma unroll
        for (int r = 0; r < 4; r++)
#pragma unroll
            for (int q = 0; q < 8; q++) sacc[r][q] += kr[r] * vr[q];
    }
    int sb = (bh * NCHUNK + c) * 4096;
#pragma unroll
    for (int r = 0; r < 4; r++) {
        *(float4*)(g_S + sb + (om0 + r) * 64 + od0) =
            make_float4(sacc[r][0], sacc[r][1], sacc[r][2], sacc[r][3]);
        *(float4*)(g_S + sb + (om0 + r) * 64 + od0 + 4) =
            make_float4(sacc[r][4], sacc[r][5], sacc[r][6], sacc[r][7]);
    }
    if (tid < 64) {
        float z = 0.f;
#pragma unroll
        for (int t = 0; t < 32; t++) z += kf_s[t][tid];
        g_z[(bh * NCHUNK + c) * 64 + tid] = z;
    }
}

// -------------------- exclusive scans over chunks (S and z fused) ---------------
__global__ void __launch_bounds__(64)
attn_scan() {
    int bh = blockIdx.x >> 6, m = blockIdx.x & 63, d = threadIdx.x;
    float v[NCHUNK];
#pragma unroll
    for (int c = 0; c < NCHUNK; c++)
        v[c] = g_S[((bh * NCHUNK + c) << 12) + m * 64 + d];
    float acc = 0.f;
#pragma unroll
    for (int c = 0; c < NCHUNK; c++) {
        g_S[((bh * NCHUNK + c) << 12) + m * 64 + d] = acc;
        acc += v[c];
    }
    if (m == 0) {
        float zv[NCHUNK];
#pragma unroll
        for (int c = 0; c < NCHUNK; c++) zv[c] = g_z[(bh * NCHUNK + c) * 64 + d];
        float za = 0.f;
#pragma unroll
        for (int c = 0; c < NCHUNK; c++) {
            g_z[(bh * NCHUNK + c) * 64 + d] = za;
            za += zv[c];
        }
    }
}

// -------------------- chunked-GEMM apply --------------------
__global__ void __launch_bounds__(128)
attn_apply() {
    int c = blockIdx.x, bh = blockIdx.y;
    int b = bh / Hv, h = bh % Hv;
    int tid = threadIdx.x;
    __shared__ float Qf[32][68], Kf[32][68], V[32][68];
    __shared__ float S0[64][68];
    __shared__ float A[32][36];
    __shared__ float z0[64], sden[32];
    int t0 = c * CHUNK;
    int sb = (bh * NCHUNK + c) * 4096;

    for (int i = tid; i < 512; i += 128) {
        int row = i >> 4, c4 = (i & 15) * 4;
        size_t qb = (size_t)(b * Tv + t0 + row) * Dv + h * HDv + c4;
        size_t vb = (size_t)(b * Tv + t0 + row) * QKVN + 1024 + h * HDv + c4;
        *(float4*)&Qf[row][c4] = *(const float4*)(g_qf + qb);
        *(float4*)&Kf[row][c4] = *(const float4*)(g_kf + qb);
        *(float4*)&V[row][c4] = *(const float4*)(g_qkv + vb);
    }
    for (int i = tid; i < 1024; i += 128) {
        int m = i >> 4, c4 = (i & 15) * 4;
        *(float4*)&S0[m][c4] = *(const float4*)(g_S + sb + m * 64 + c4);
    }
    if (tid < 16)
        *(float4*)&z0[tid * 4] = *(const float4*)(g_z + (bh * NCHUNK + c) * 64 + tid * 4);
    __syncthreads();

    int i0 = (tid >> 4) * 4;
    int j0 = tid & 15;
    {
        float a0[4] = {0.f, 0.f, 0.f, 0.f}, a1[4] = {0.f, 0.f, 0.f, 0.f};
#pragma unroll
        for (int k = 0; k < 64; k += 4) {
            float4 ka = *(const float4*)&Kf[j0][k];
            float4 kb = *(const float4*)&Kf[j0 + 16][k];
#pragma unroll
            for (int r = 0; r < 4; r++) {
                float4 q = *(const float4*)&Qf[i0 + r][k];
                a0[r] += q.x * ka.x + q.y * ka.y + q.z * ka.z + q.w * ka.w;
                a1[r] += q.x * kb.x + q.y * kb.y + q.z * kb.z + q.w * kb.w;
            }
        }
#pragma unroll
        for (int r = 0; r < 4; r++) {
            A[i0 + r][j0] = (j0 <= i0 + r) ? a0[r] : 0.f;
            A[i0 + r][j0 + 16] = (j0 + 16 <= i0 + r) ? a1[r] : 0.f;
        }
    }
    __syncthreads();

    if (tid < 32) {
        float dn = 1e-16f;
#pragma unroll 8
        for (int m = 0; m < 64; m++) dn += Qf[tid][m] * z0[m];
#pragma unroll
        for (int j = 0; j < 32; j++) dn += A[tid][j];
        sden[tid] = dn;
    }

    int d0 = (tid & 15) * 4;
    float acc[4][4];
#pragma unroll
    for (int r = 0; r < 4; r++)
#pragma unroll
        for (int q = 0; q < 4; q++) acc[r][q] = 0.f;
#pragma unroll 4
    for (int m = 0; m < 64; m += 4) {
        float4 qv[4], sv[4];
#pragma unroll
        for (int r = 0; r < 4; r++) qv[r] = *(const float4*)&Qf[i0 + r][m];
#pragma unroll
        for (int kk = 0; kk < 4; kk++) sv[kk] = *(const float4*)&S0[m + kk][d0];
#pragma unroll
        for (int r = 0; r < 4; r++) {
            float qr[4] = {qv[r].x, qv[r].y, qv[r].z, qv[r].w};
#pragma unroll
            for (int kk = 0; kk < 4; kk++) {
                acc[r][0] += qr[kk] * sv[kk].x;
                acc[r][1] += qr[kk] * sv[kk].y;
                acc[r][2] += qr[kk] * sv[kk].z;
                acc[r][3] += qr[kk] * sv[kk].w;
            }
        }
    }
#pragma unroll 2
    for (int j = 0; j < 32; j += 4) {
        float4 av[4], vv[4];
#pragma unroll
        for (int r = 0; r < 4; r++) av[r] = *(const float4*)&A[i0 + r][j];
#pragma unroll
        for (int kk = 0; kk < 4; kk++) vv[kk] = *(const float4*)&V[j + kk][d0];
#pragma unroll
        for (int r = 0; r < 4; r++) {
            float ar[4] = {av[r].x, av[r].y, av[r].z, av[r].w};
#pragma unroll
            for (int kk = 0; kk < 4; kk++) {
                acc[r][0] += ar[kk] * vv[kk].x;
                acc[r][1] += ar[kk] * vv[kk].y;
                acc[r][2] += ar[kk] * vv[kk].z;
                acc[r][3] += ar[kk] * vv[kk].w;
            }
        }
    }
    __syncthreads();
#pragma unroll
    for (int r = 0; r < 4; r++) {
        float inv = 1.f / sden[i0 + r];
        float4 o = make_float4(acc[r][0] * inv, acc[r][1] * inv,
                               acc[r][2] * inv, acc[r][3] * inv);
        *(float4*)(g_a + (size_t)(b * Tv + t0 + i0 + r) * Dv + h * HDv + d0) = o;
    }
}

// -------------------- LayerNorm + residual add (+ fp16 hi/lo of new x) ----------
template <int RED>
__global__ void __launch_bounds__(128)
ln_add(const float* __restrict__ in0, const float* __restrict__ in1,
       const float* __restrict__ pbias,
       const float* __restrict__ g, const float* __restrict__ bl,
       float* __restrict__ x) {
    int n = blockIdx.x, tid = threadIdx.x;
    int lane = tid & 31, w = tid >> 5;
    float v[4];
    float s = 0.f, s2 = 0.f;
#pragma unroll
    for (int i = 0; i < 4; i++) {
        int j = tid + i * 128;
        float t = in0[(size_t)n * Dv + j];
        if (RED) t += in1[(size_t)n * Dv + j] + pbias[j];
        v[i] = t;
        s += t;
        s2 += t * t;
    }
    __shared__ float sh[8];
#pragma unroll
    for (int off = 16; off; off >>= 1) {
        s += __shfl_down_sync(0xffffffffu, s, off);
        s2 += __shfl_down_sync(0xffffffffu, s2, off);
    }
    if (lane == 0) { sh[w] = s; sh[4 + w] = s2; }
    __syncthreads();
    float S = sh[0] + sh[1] + sh[2] + sh[3];
    float S2 = sh[4] + sh[5] + sh[6] + sh[7];
    float mu = S * (1.f / Dv);
    float var = S2 * (1.f / Dv) - mu * mu;
    float rs = rsqrtf(var + 1e-5f);
#pragma unroll
    for (int i = 0; i < 4; i++) {
        int j = tid + i * 128;
        size_t idx = (size_t)n * Dv + j;
        float nv = x[idx] + (v[i] - mu) * rs * g[j] + bl[j];
        x[idx] = nv;
        __half h, l;
        split_fp16(nv, h, l);
        g_xh[idx] = h;
        g_xl[idx] = l;
    }
}

// -------------------- host driver --------------------
extern "C" void kernel_launch(void* const* d_in, const int* in_sizes, int n_in,
                              void* d_out, int out_size) {
    const int*   tokens = (const int*)d_in[0];
    const float* emb    = (const float*)d_in[1];
    const float* Wq     = (const float*)d_in[2];
    const float* bq     = (const float*)d_in[3];
    const float* Wk     = (const float*)d_in[4];
    const float* bk     = (const float*)d_in[5];
    const float* Wv     = (const float*)d_in[6];
    const float* bvp    = (const float*)d_in[7];
    const float* rfs    = (const float*)d_in[8];
    const float* ln1g   = (const float*)d_in[9];
    const float* ln1b   = (const float*)d_in[10];
    const float* ln2g   = (const float*)d_in[11];
    const float* ln2b   = (const float*)d_in[12];
    const float* WU     = (const float*)d_in[13];
    const float* bU     = (const float*)d_in[14];
    const float* WV     = (const float*)d_in[15];
    const float* bV     = (const float*)d_in[16];
    const float* Wout   = (const float*)d_in[17];
    const float* bout   = (const float*)d_in[18];
    float* out = (float*)d_out;

    static float *px = nullptr, *pa, *pqkv, *pbqkv, *ppart;
    static __half *pxh, *pxl, *phh, *pwh, *prfh, *prfl;
    if (!px) {
        cudaGetSymbolAddress((void**)&px, g_x);
        cudaGetSymbolAddress((void**)&pa, g_a);
        cudaGetSymbolAddress((void**)&pqkv, g_qkv);
        cudaGetSymbolAddress((void**)&pbqkv, g_bqkv);
        cudaGetSymbolAddress((void**)&ppart, g_part);
        cudaGetSymbolAddress((void**)&pxh, g_xh);
        cudaGetSymbolAddress((void**)&pxl, g_xl);
        cudaGetSymbolAddress((void**)&phh, g_hh);
        cudaGetSymbolAddress((void**)&pwh, g_wh);
        cudaGetSymbolAddress((void**)&prfh, g_rfh);
        cudaGetSymbolAddress((void**)&prfl, g_rfl);
        cudaFuncSetAttribute(gemm_tc<1>, cudaFuncAttributeMaxDynamicSharedMemorySize,
                             A_TILE + B_TILE);
        cudaFuncSetAttribute(gemm_tc<2>, cudaFuncAttributeMaxDynamicSharedMemorySize,
                             2 * A_TILE + B_TILE);
    }

    convw_all<<<(TOT4 + BIA4 + RF4 + 255) / 256, 256>>>(Wq, Wk, Wv, WU, WV, Wout,
                                                        bq, bk, bvp, rfs);
    embed_kernel<<<(NTOK * Dv + 255) / 256, 256>>>(tokens, emb);

    for (int l = 0; l < Lv; l++) {
        gemm_tc<1><<<dim3(QKVN / 128, NTOK / 128), 256, A_TILE + B_TILE>>>(
            pxh, nullptr, pwh + OFF_QKV + (size_t)l * Dv * QKVN, pbqkv + l * QKVN,
            pqkv, nullptr, NTOK, QKVN, Dv, QKVN, Dv, 0);

        favor_chunk<<<dim3(NTOK / 32, Hv), 128>>>(prfh + (size_t)l * Hv * 4096,
                                                  prfl + (size_t)l * Hv * 4096);
        attn_scan<<<Bv * Hv * HDv, 64>>>();
        attn_apply<<<dim3(NCHUNK, Bv * Hv), 128>>>();

        ln_add<0><<<NTOK, 128>>>(pa, nullptr, nullptr,
                                 ln1g + l * Dv, ln1b + l * Dv, px);

        gemm_tc<1><<<dim3(FFNv / 128, NTOK / 128), 256, A_TILE + B_TILE>>>(
            pxh, nullptr, pwh + OFF_WU + (size_t)l * Dv * FFNv, bU + l * FFNv,
            nullptr, phh, NTOK, FFNv, Dv, FFNv, Dv, 1);

        gemm_tc<1><<<dim3(Dv / 128, NTOK / 128, 2), 256, A_TILE + B_TILE>>>(
            phh, nullptr, pwh + OFF_WD + (size_t)l * FFNv * Dv, nullptr,
            ppart, nullptr, NTOK, Dv, FFNv, Dv, 1024, 2);

        ln_add<1><<<NTOK, 128>>>(ppart, ppart + (size_t)NTOK * Dv, bV + l * Dv,
                                 ln2g + l * Dv, ln2b + l * Dv, px);
    }

    gemm_tc<2><<<dim3(VOCABv / 128, NTOK / 128, 2), 256, 2 * A_TILE + B_TILE>>>(
        pxh, pxl, pwh + OFF_WO, nullptr, ppart, nullptr,
        NTOK, VOCABv, Dv, VOCABv, 256, 2);
    reduce2<<<(NTOK * VOCABv / 4 + 255) / 256, 256>>>(ppart, bout, out,
                                                      NTOK * VOCABv / 4, VOCABv - 1);
}

// round 16
// speedup vs baseline: 2.2157x; 1.0188x over previous
#include <cuda_runtime.h>
#include <cuda_fp16.h>
#include <math.h>
#include <stdint.h>

// Problem constants
#define Bv      2
#define Tv      2048
#define NTOK    (Bv * Tv)      // 4096
#define Dv      512
#define Hv      8
#define HDv     64
#define FFNv    2048
#define VOCABv  256
#define Lv      2
#define CHUNK   32
#define NCHUNK  (Tv / CHUNK)   // 64
#define QKVN    1536

// weight region offsets (elements) in the fp16 weight pool ([K,N] row-major)
#define OFF_QKV 0
#define OFF_WU  (OFF_QKV + Lv * Dv * QKVN)
#define OFF_WD  (OFF_WU + Lv * Dv * FFNv)
#define OFF_WO  (OFF_WD + Lv * FFNv * Dv)
#define W_TOTAL (OFF_WO + Dv * VOCABv)

#define QKV4 (Lv * Dv * QKVN / 4)
#define WU4  (Lv * Dv * FFNv / 4)
#define WD4  (Lv * FFNv * Dv / 4)
#define WO4  (Dv * VOCABv / 4)
#define TOT4 (QKV4 + WU4 + WD4 + WO4)
#define BIA4 (Lv * QKVN / 4)
#define RFN  (Lv * Hv * HDv * HDv)
#define RF4  (RFN / 4)

// -------------------- scratch (device globals; no allocs) --------------------
__device__ float g_x[NTOK * Dv];
__device__ float g_a[NTOK * Dv];
__device__ float g_v[NTOK * Dv];
__device__ float g_qf[NTOK * Dv];
__device__ float g_kf[NTOK * Dv];
__device__ float g_S[Bv * Hv * NCHUNK * HDv * HDv];
__device__ float g_z[Bv * Hv * NCHUNK * HDv];
__device__ float g_bqkv[Lv * QKVN];
__device__ float g_part[2 * NTOK * Dv];
__device__ __half g_xh[NTOK * Dv];
__device__ __half g_xl[NTOK * Dv];
__device__ __half g_qkh[NTOK * 1024];
__device__ __half g_qkl[NTOK * 1024];
__device__ __half g_hh[NTOK * FFNv];
__device__ __half g_wh[W_TOTAL];
__device__ __half g_rfh[RFN];
__device__ __half g_rfl[RFN];

__device__ __forceinline__ void split_fp16(float v, __half& h, __half& l) {
    h = __float2half_rn(v);
    l = __float2half_rn(v - __half2float(h));
}

// -------------------- ONE fused weight conversion + bias pack + rf hi/lo ---------
__global__ void convw_all(const float* __restrict__ Wq, const float* __restrict__ Wk,
                          const float* __restrict__ Wv, const float* __restrict__ WU,
                          const float* __restrict__ WV, const float* __restrict__ Wout,
                          const float* __restrict__ bq, const float* __restrict__ bk,
                          const float* __restrict__ bvp, const float* __restrict__ rfs) {
    int idx = blockIdx.x * blockDim.x + threadIdx.x;
    if (idx < TOT4) {
        const float* src;
        int e;
        if (idx < QKV4) {
            e = idx * 4;
            int l = e / (Dv * QKVN);
            int r = e % (Dv * QKVN);
            int k = r / QKVN, col = r % QKVN;
            if (col < 512)       src = Wq + (size_t)l * Dv * Dv + k * 512 + col;
            else if (col < 1024) src = Wk + (size_t)l * Dv * Dv + k * 512 + col - 512;
            else                 src = Wv + (size_t)l * Dv * Dv + k * 512 + col - 1024;
            e += OFF_QKV;
        } else if (idx < QKV4 + WU4) {
            int e2 = (idx - QKV4) * 4;
            src = WU + e2;
            e = OFF_WU + e2;
        } else if (idx < QKV4 + WU4 + WD4) {
            int e2 = (idx - QKV4 - WU4) * 4;
            src = WV + e2;
            e = OFF_WD + e2;
        } else {
            int e2 = (idx - QKV4 - WU4 - WD4) * 4;
            src = Wout + e2;
            e = OFF_WO + e2;
        }
        float4 v = *(const float4*)src;
        ((__half2*)(g_wh + e))[0] = __half2(__float2half_rn(v.x), __float2half_rn(v.y));
        ((__half2*)(g_wh + e))[1] = __half2(__float2half_rn(v.z), __float2half_rn(v.w));
    } else if (idx < TOT4 + BIA4) {
        int j = (idx - TOT4) * 4;
#pragma unroll
        for (int q = 0; q < 4; q++) {
            int jj = j + q;
            int l = jj / QKVN, c = jj % QKVN;
            float v;
            if (c < 512) v = bq[l * Dv + c];
            else if (c < 1024) v = bk[l * Dv + c - 512];
            else v = bvp[l * Dv + c - 1024];
            g_bqkv[jj] = v;
        }
    } else if (idx < TOT4 + BIA4 + RF4) {
        int j = (idx - TOT4 - BIA4) * 4;
        float4 v = *(const float4*)(rfs + j);
        __half h0, h1, h2, h3, l0, l1, l2, l3;
        split_fp16(v.x, h0, l0); split_fp16(v.y, h1, l1);
        split_fp16(v.z, h2, l2); split_fp16(v.w, h3, l3);
        ((__half2*)(g_rfh + j))[0] = __half2(h0, h1);
        ((__half2*)(g_rfh + j))[1] = __half2(h2, h3);
        ((__half2*)(g_rfl + j))[0] = __half2(l0, l1);
        ((__half2*)(g_rfl + j))[1] = __half2(l2, l3);
    }
}

// -------------------- embedding + sinusoidal positions --------------------
__global__ void embed_kernel(const int* __restrict__ tokens,
                             const float* __restrict__ emb) {
    int idx = blockIdx.x * blockDim.x + threadIdx.x;
    if (idx >= NTOK * Dv) return;
    int n = idx >> 9;
    int j = idx & 511;
    int t = n & (Tv - 1);
    float val;
    const float c = 9.210340371976184f / 256.f;
    if (j < 256) {
        int tok = tokens[n];
        val = emb[tok * 256 + j];
    } else if (j < 384) {
        int i = j - 256;
        val = sinf((float)t * expf(-(2.f * (float)i) * c));
    } else {
        int i = j - 384;
        val = cosf((float)t * expf(-(2.f * (float)i) * c));
    }
    g_x[idx] = val;
    __half h, l;
    split_fp16(val, h, l);
    g_xh[idx] = h;
    g_xl[idx] = l;
}

// -------------------- mma helpers --------------------
__device__ __forceinline__ void ldsm_x4(uint32_t* r, const void* p) {
    uint32_t a = (uint32_t)__cvta_generic_to_shared(p);
    asm volatile("ldmatrix.sync.aligned.m8n8.x4.shared.b16 {%0,%1,%2,%3},[%4];"
        : "=r"(r[0]), "=r"(r[1]), "=r"(r[2]), "=r"(r[3]) : "r"(a));
}
__device__ __forceinline__ void ldsm_x4_t(uint32_t* r, const void* p) {
    uint32_t a = (uint32_t)__cvta_generic_to_shared(p);
    asm volatile("ldmatrix.sync.aligned.m8n8.x4.trans.shared.b16 {%0,%1,%2,%3},[%4];"
        : "=r"(r[0]), "=r"(r[1]), "=r"(r[2]), "=r"(r[3]) : "r"(a));
}
__device__ __forceinline__ void mma16816(float* c, const uint32_t* a, const uint32_t* b) {
    asm volatile("mma.sync.aligned.m16n8k16.row.col.f32.f16.f16.f32 "
        "{%0,%1,%2,%3},{%4,%5,%6,%7},{%8,%9},{%0,%1,%2,%3};"
        : "+f"(c[0]), "+f"(c[1]), "+f"(c[2]), "+f"(c[3])
        : "r"(a[0]), "r"(a[1]), "r"(a[2]), "r"(a[3]), "r"(b[0]), "r"(b[1]));
}
__device__ __forceinline__ void cp16(void* smem, const void* gmem) {
    uint32_t s = (uint32_t)__cvta_generic_to_shared(smem);
    asm volatile("cp.async.cg.shared.global [%0], [%1], 16;" :: "r"(s), "l"(gmem));
}
#define CP_COMMIT() asm volatile("cp.async.commit_group;")
#define CP_WAIT(n)  asm volatile("cp.async.wait_group %0;" :: "n"(n))

#define PADA 72
#define PADB 136
#define A_TILE 36864
#define B_TILE 34816

// -------------------- tensor-core GEMM, fp16, BK=64, 2-stage cp.async ----------
// mode 0: fp32 out + bias. mode 1: gelu -> fp16 (Ch). mode 2: split-K partials.
// mode 3 (QKV): cols<1024 -> scaled fp16 hi/lo (Ch/Cl, stride 1024); cols>=1024 ->
//               fp32 (C, stride 512).
template <int TERMS>
__global__ void __launch_bounds__(256, 2)
gemm_tc(const __half* __restrict__ Ahg, const __half* __restrict__ Alg,
        const __half* __restrict__ Bhg,
        const float* __restrict__ bias, float* __restrict__ C,
        __half* __restrict__ Ch, __half* __restrict__ Cl,
        int M, int N, int lda, int ldb, int Kext, int mode) {
    extern __shared__ char smraw[];
    __half* AsH = (__half*)(smraw);
    __half* AsL = (__half*)(smraw + A_TILE);
    __half* BsH = (__half*)(smraw + (TERMS == 2 ? 2 * A_TILE : A_TILE));

    if (mode == 2) {
        size_t ko = (size_t)blockIdx.z * Kext;
        Ahg += ko;
        if (TERMS == 2) Alg += ko;
        Bhg += ko * ldb;
        C += (size_t)blockIdx.z * M * N;
    }

    int tid = threadIdx.x;
    int wid = tid >> 5, lane = tid & 31;
    int m_w = (wid >> 1) * 32, n_w = (wid & 1) * 64;
    int row0 = blockIdx.y * 128, col0 = blockIdx.x * 128;

    float acc[2][8][4];
#pragma unroll
    for (int i = 0; i < 2; i++)
#pragma unroll
        for (int j = 0; j < 8; j++)
#pragma unroll
            for (int q = 0; q < 4; q++) acc[i][j][q] = 0.f;

    int a_row = tid >> 1, a_colb = (tid & 1) * 32;
    int b_row = tid >> 2, b_colb = (tid & 3) * 32;

    auto loadStage = [&](int stage, int buf) {
        int k0 = stage * 64;
        const __half* aH = Ahg + (size_t)(row0 + a_row) * lda + k0 + a_colb;
        int sa = (buf * 128 + a_row) * PADA + a_colb;
        const __half* bH = Bhg + (size_t)(k0 + b_row) * ldb + col0 + b_colb;
        int sb = (buf * 64 + b_row) * PADB + b_colb;
#pragma unroll
        for (int i = 0; i < 4; i++) {
            cp16(AsH + sa + i * 8, aH + i * 8);
            cp16(BsH + sb + i * 8, bH + i * 8);
        }
        if (TERMS == 2) {
            const __half* aL = Alg + (size_t)(row0 + a_row) * lda + k0 + a_colb;
#pragma unroll
            for (int i = 0; i < 4; i++) cp16(AsL + sa + i * 8, aL + i * 8);
        }
        CP_COMMIT();
    };

    auto compute = [&](int buf) {
#pragma unroll
        for (int kk = 0; kk < 64; kk += 16) {
            uint32_t Ahf[2][4], Alf[2][4], Bhf[8][2];
#pragma unroll
            for (int i = 0; i < 2; i++) {
                int idx = (buf * 128 + m_w + i * 16 + (lane & 15)) * PADA + kk + (lane >> 4) * 8;
                ldsm_x4(Ahf[i], AsH + idx);
                if (TERMS == 2) ldsm_x4(Alf[i], AsL + idx);
            }
#pragma unroll
            for (int p = 0; p < 4; p++) {
                int idx = (buf * 64 + kk + (lane & 15)) * PADB + n_w + p * 16 + (lane >> 4) * 8;
                uint32_t r[4];
                ldsm_x4_t(r, BsH + idx);
                Bhf[2 * p][0] = r[0]; Bhf[2 * p][1] = r[1];
                Bhf[2 * p + 1][0] = r[2]; Bhf[2 * p + 1][1] = r[3];
            }
#pragma unroll
            for (int i = 0; i < 2; i++)
#pragma unroll
                for (int j = 0; j < 8; j++) {
                    mma16816(acc[i][j], Ahf[i], Bhf[j]);
                    if (TERMS == 2) mma16816(acc[i][j], Alf[i], Bhf[j]);
                }
        }
    };

    int nsteps = Kext >> 6;
    loadStage(0, 0);
    for (int s = 0; s < nsteps; s++) {
        CP_WAIT(0);
        __syncthreads();
        if (s + 1 < nsteps) loadStage(s + 1, (s + 1) & 1);
        compute(s & 1);
    }

    const float sc = 0.3535533905932738f;
    int g = lane >> 2, tg = lane & 3;
#pragma unroll
    for (int i = 0; i < 2; i++) {
#pragma unroll
        for (int j = 0; j < 8; j++) {
            int cc = col0 + n_w + j * 8 + tg * 2;
            float b0 = 0.f, b1 = 0.f;
            if (mode != 2) { b0 = bias[cc]; b1 = bias[cc + 1]; }
#pragma unroll
            for (int half = 0; half < 2; half++) {
                int r = row0 + m_w + i * 16 + g + half * 8;
                float v0 = acc[i][j][half * 2 + 0] + b0;
                float v1 = acc[i][j][half * 2 + 1] + b1;
                if (mode == 1) {
                    v0 = 0.5f * v0 * (1.f + erff(v0 * 0.7071067811865475f));
                    v1 = 0.5f * v1 * (1.f + erff(v1 * 0.7071067811865475f));
                    *(__half2*)(Ch + (size_t)r * N + cc) =
                        __half2(__float2half_rn(v0), __float2half_rn(v1));
                } else if (mode == 3) {
                    if (cc < 1024) {
                        float s0 = v0 * sc, s1 = v1 * sc;
                        __half h0, l0, h1, l1;
                        split_fp16(s0, h0, l0);
                        split_fp16(s1, h1, l1);
                        *(__half2*)(Ch + (size_t)r * 1024 + cc) = __half2(h0, h1);
                        *(__half2*)(Cl + (size_t)r * 1024 + cc) = __half2(l0, l1);
                    } else {
                        *(float2*)(C + (size_t)r * 512 + cc - 1024) = make_float2(v0, v1);
                    }
                } else {
                    *(float2*)(C + (size_t)r * N + cc) = make_float2(v0, v1);
                }
            }
        }
    }
}

// -------------------- generic split-K=2 reduce + bias (N = power of 2) ----------
__global__ void reduce2(const float* __restrict__ part, const float* __restrict__ bias,
                        float* __restrict__ out, int total4, int nmask) {
    int i = blockIdx.x * blockDim.x + threadIdx.x;
    if (i >= total4) return;
    float4 a = ((const float4*)part)[i];
    float4 b = ((const float4*)part)[i + total4];
    int col = (i * 4) & nmask;
    float4 o;
    o.x = a.x + b.x + bias[col + 0];
    o.y = a.y + b.y + bias[col + 1];
    o.z = a.z + b.z + bias[col + 2];
    o.w = a.w + b.w + bias[col + 3];
    ((float4*)out)[i] = o;
}

// -------------------- fused FAVOR+ features (tensor-core) + per-chunk sums -------
// grid (NTOK/32, Hv), 128 threads, ONE chunk per block. All staging via cp.async
// (q/k pre-split by the QKV GEMM epilogue). Norm via orthogonality from fragments.
__global__ void __launch_bounds__(128)
favor_chunk(const __half* __restrict__ rfhp, const __half* __restrict__ rflp) {
    __shared__ __half XH[64][PADA];    // stacked xq(0-31), xk(32-63)
    __shared__ __half XL[64][PADA];
    __shared__ __half RFH[64][PADA];   // [d][m]
    __shared__ __half RFL[64][PADA];

    int tile = blockIdx.x, h = blockIdx.y;
    int b = tile >> 6, c = tile & 63;
    int bh = b * Hv + h;
    int tid = threadIdx.x;
    int wid = tid >> 5, lane = tid & 31;
    int t0 = c * CHUNK;

    const __half* rh = rfhp + (size_t)h * 4096;
    const __half* rl = rflp + (size_t)h * 4096;
    for (int i = tid; i < 512; i += 128) {
        int row = i >> 3, c8 = (i & 7) * 8;
        size_t src = (size_t)(b * Tv + t0 + (row & 31)) * 1024 +
                     ((row < 32) ? 0 : 512) + h * HDv + c8;
        cp16(&XH[row][c8], g_qkh + src);
        cp16(&XL[row][c8], g_qkl + src);
        cp16(&RFH[row][c8], rh + row * 64 + c8);
        cp16(&RFL[row][c8], rl + row * 64 + c8);
    }
    CP_COMMIT();
    CP_WAIT(0);
    __syncthreads();

    // feature mma: warp w -> rows 16w..16w+15 (stacked), all 64 cols
    int m_w = wid * 16;
    float acc[8][4];
#pragma unroll
    for (int j = 0; j < 8; j++)
#pragma unroll
        for (int q = 0; q < 4; q++) acc[j][q] = 0.f;
#pragma unroll
    for (int k = 0; k < 4; k++) {
        int kk = k * 16;
        uint32_t AH[4], AL[4];
        int aidx = m_w + (lane & 15);
        ldsm_x4(AH, &XH[aidx][kk + (lane >> 4) * 8]);
        ldsm_x4(AL, &XL[aidx][kk + (lane >> 4) * 8]);
#pragma unroll
        for (int p = 0; p < 4; p++) {
            uint32_t BH[4], BL[4];
            int bidx = kk + (lane & 15);
            int bcol = p * 16 + (lane >> 4) * 8;
            ldsm_x4_t(BH, &RFH[bidx][bcol]);
            ldsm_x4_t(BL, &RFL[bidx][bcol]);
            mma16816(acc[2 * p], AH, BH);
            mma16816(acc[2 * p], AL, BH);
            mma16816(acc[2 * p], AH, BL);
            mma16816(acc[2 * p + 1], AH, BH + 2);
            mma16816(acc[2 * p + 1], AL, BH + 2);
            mma16816(acc[2 * p + 1], AH, BL + 2);
        }
    }

    // norms from fragments: hn[half] = 0.5 * sum_m dq^2 / 64  (rf rf^T = 64 I)
    float s20 = 0.f, s21 = 0.f;
#pragma unroll
    for (int j = 0; j < 8; j++) {
        s20 += acc[j][0] * acc[j][0] + acc[j][1] * acc[j][1];
        s21 += acc[j][2] * acc[j][2] + acc[j][3] * acc[j][3];
    }
    s20 += __shfl_xor_sync(0xffffffffu, s20, 1);
    s20 += __shfl_xor_sync(0xffffffffu, s20, 2);
    s21 += __shfl_xor_sync(0xffffffffu, s21, 1);
    s21 += __shfl_xor_sync(0xffffffffu, s21, 2);
    float hn[2] = {s20 * (1.f / 128.f), s21 * (1.f / 128.f)};
    __syncthreads();   // done with XH/XL/RFH/RFL -> safe to alias

    float (*kf_s)[68] = (float(*)[68])&XH[0][0];   // 32x68 fp32
    float (*V_s)[68]  = (float(*)[68])&RFH[0][0];

    // stage V via cp.async (overlaps exp/store below)
    for (int i = tid; i < 512; i += 128) {
        int tl = i >> 4, c4 = (i & 15) * 4;
        cp16(&V_s[tl][c4], g_v + (size_t)(b * Tv + t0 + tl) * 512 + h * HDv + c4);
    }
    CP_COMMIT();

    // exp + write qf/kf; k-warps also scatter kf into kf_s
    int g = lane >> 2, tg = lane & 3;
#pragma unroll
    for (int j = 0; j < 8; j++) {
        int col = j * 8 + tg * 2;
#pragma unroll
        for (int half = 0; half < 2; half++) {
            int row = m_w + g + half * 8;
            float v0 = expf(acc[j][half * 2 + 0] - hn[half]);
            float v1 = expf(acc[j][half * 2 + 1] - hn[half]);
            int trow = row & 31;
            size_t dst = (size_t)(b * Tv + t0 + trow) * Dv + h * HDv + col;
            if (row < 32) {
                *(float2*)(g_qf + dst) = make_float2(v0, v1);
            } else {
                *(float2*)(g_kf + dst) = make_float2(v0, v1);
                kf_s[trow][col] = v0;
                kf_s[trow][col + 1] = v1;
            }
        }
    }
    CP_WAIT(0);
    __syncthreads();

    // chunk outer-product sums: S_c[m][d] = sum_t kf[t][m] V[t][d]
    int om0 = (tid >> 3) * 4, od0 = (tid & 7) * 8;
    float sacc[4][8];
#pragma unroll
    for (int r = 0; r < 4; r++)
#pragma unroll
        for (int q = 0; q < 8; q++) sacc[r][q] = 0.f;
#pragma unroll 8
    for (int t = 0; t < 32; t++) {
        float4 km = *(const float4*)&kf_s[t][om0];
        float4 v0 = *(const float4*)&V_s[t][od0];
        float4 v1 = *(const float4*)&V_s[t][od0 + 4];
        float kr[4] = {km.x, km.y, km.z, km.w};
        float vr[8] = {v0.x, v0.y, v0.z, v0.w, v1.x, v1.y, v1.z, v1.w};
#pragma unroll
        for (int r = 0; r < 4; r++)
#pragma unroll
            for (int q = 0; q < 8; q++) sacc[r][q] += kr[r] * vr[q];
    }
    int sb = (bh * NCHUNK + c) * 4096;
#pragma unroll
    for (int r = 0; r < 4; r++) {
        *(float4*)(g_S + sb + (om0 + r) * 64 + od0) =
            make_float4(sacc[r][0], sacc[r][1], sacc[r][2], sacc[r][3]);
        *(float4*)(g_S + sb + (om0 + r) * 64 + od0 + 4) =
            make_float4(sacc[r][4], sacc[r][5], sacc[r][6], sacc[r][7]);
    }
    if (tid < 64) {
        float z = 0.f;
#pragma unroll
        for (int t = 0; t < 32; t++) z += kf_s[t][tid];
        g_z[(bh * NCHUNK + c) * 64 + tid] = z;
    }
}

// -------------------- exclusive scans over chunks (S and z fused) ---------------
__global__ void __launch_bounds__(64)
attn_scan() {
    int bh = blockIdx.x >> 6, m = blockIdx.x & 63, d = threadIdx.x;
    float v[NCHUNK];
#pragma unroll
    for (int c = 0; c < NCHUNK; c++)
        v[c] = g_S[((bh * NCHUNK + c) << 12) + m * 64 + d];
    float acc = 0.f;
#pragma unroll
    for (int c = 0; c < NCHUNK; c++) {
        g_S[((bh * NCHUNK + c) << 12) + m * 64 + d] = acc;
        acc += v[c];
    }
    if (m == 0) {
        float zv[NCHUNK];
#pragma unroll
        for (int c = 0; c < NCHUNK; c++) zv[c] = g_z[(bh * NCHUNK + c) * 64 + d];
        float za = 0.f;
#pragma unroll
        for (int c = 0; c < NCHUNK; c++) {
            g_z[(bh * NCHUNK + c) * 64 + d] = za;
            za += zv[c];
        }
    }
}

// -------------------- chunked-GEMM apply --------------------
__global__ void __launch_bounds__(128)
attn_apply() {
    int c = blockIdx.x, bh = blockIdx.y;
    int b = bh / Hv, h = bh % Hv;
    int tid = threadIdx.x;
    __shared__ float Qf[32][68], Kf[32][68], V[32][68];
    __shared__ float S0[64][68];
    __shared__ float A[32][36];
    __shared__ float z0[64], sden[32];
    int t0 = c * CHUNK;
    int sb = (bh * NCHUNK + c) * 4096;

    for (int i = tid; i < 512; i += 128) {
        int row = i >> 4, c4 = (i & 15) * 4;
        size_t qb = (size_t)(b * Tv + t0 + row) * Dv + h * HDv + c4;
        size_t vb = (size_t)(b * Tv + t0 + row) * 512 + h * HDv + c4;
        *(float4*)&Qf[row][c4] = *(const float4*)(g_qf + qb);
        *(float4*)&Kf[row][c4] = *(const float4*)(g_kf + qb);
        *(float4*)&V[row][c4] = *(const float4*)(g_v + vb);
    }
    for (int i = tid; i < 1024; i += 128) {
        int m = i >> 4, c4 = (i & 15) * 4;
        *(float4*)&S0[m][c4] = *(const float4*)(g_S + sb + m * 64 + c4);
    }
    if (tid < 16)
        *(float4*)&z0[tid * 4] = *(const float4*)(g_z + (bh * NCHUNK + c) * 64 + tid * 4);
    __syncthreads();

    int i0 = (tid >> 4) * 4;
    int j0 = tid & 15;
    {
        float a0[4] = {0.f, 0.f, 0.f, 0.f}, a1[4] = {0.f, 0.f, 0.f, 0.f};
#pragma unroll
        for (int k = 0; k < 64; k += 4) {
            float4 ka = *(const float4*)&Kf[j0][k];
            float4 kb = *(const float4*)&Kf[j0 + 16][k];
#pragma unroll
            for (int r = 0; r < 4; r++) {
                float4 q = *(const float4*)&Qf[i0 + r][k];
                a0[r] += q.x * ka.x + q.y * ka.y + q.z * ka.z + q.w * ka.w;
                a1[r] += q.x * kb.x + q.y * kb.y + q.z * kb.z + q.w * kb.w;
            }
        }
#pragma unroll
        for (int r = 0; r < 4; r++) {
            A[i0 + r][j0] = (j0 <= i0 + r) ? a0[r] : 0.f;
            A[i0 + r][j0 + 16] = (j0 + 16 <= i0 + r) ? a1[r] : 0.f;
        }
    }
    __syncthreads();

    if (tid < 32) {
        float dn = 1e-16f;
#pragma unroll 8
        for (int m = 0; m < 64; m++) dn += Qf[tid][m] * z0[m];
#pragma unroll
        for (int j = 0; j < 32; j++) dn += A[tid][j];
        sden[tid] = dn;
    }

    int d0 = (tid & 15) * 4;
    float acc[4][4];
#pragma unroll
    for (int r = 0; r < 4; r++)
#pragma unroll
        for (int q = 0; q < 4; q++) acc[r][q] = 0.f;
#pragma unroll 4
    for (int m = 0; m < 64; m += 4) {
        float4 qv[4], sv[4];
#pragma unroll
        for (int r = 0; r < 4; r++) qv[r] = *(const float4*)&Qf[i0 + r][m];
#pragma unroll
        for (int kk = 0; kk < 4; kk++) sv[kk] = *(const float4*)&S0[m + kk][d0];
#pragma unroll
        for (int r = 0; r < 4; r++) {
            float qr[4] = {qv[r].x, qv[r].y, qv[r].z, qv[r].w};
#pragma unroll
            for (int kk = 0; kk < 4; kk++) {
                acc[r][0] += qr[kk] * sv[kk].x;
                acc[r][1] += qr[kk] * sv[kk].y;
                acc[r][2] += qr[kk] * sv[kk].z;
                acc[r][3] += qr[kk] * sv[kk].w;
            }
        }
    }
#pragma unroll 2
    for (int j = 0; j < 32; j += 4) {
        float4 av[4], vv[4];
#pragma unroll
        for (int r = 0; r < 4; r++) av[r] = *(const float4*)&A[i0 + r][j];
#pragma unroll
        for (int kk = 0; kk < 4; kk++) vv[kk] = *(const float4*)&V[j + kk][d0];
#pragma unroll
        for (int r = 0; r < 4; r++) {
            float ar[4] = {av[r].x, av[r].y, av[r].z, av[r].w};
#pragma unroll
            for (int kk = 0; kk < 4; kk++) {
                acc[r][0] += ar[kk] * vv[kk].x;
                acc[r][1] += ar[kk] * vv[kk].y;
                acc[r][2] += ar[kk] * vv[kk].z;
                acc[r][3] += ar[kk] * vv[kk].w;
            }
        }
    }
    __syncthreads();
#pragma unroll
    for (int r = 0; r < 4; r++) {
        float inv = 1.f / sden[i0 + r];
        float4 o = make_float4(acc[r][0] * inv, acc[r][1] * inv,
                               acc[r][2] * inv, acc[r][3] * inv);
        *(float4*)(g_a + (size_t)(b * Tv + t0 + i0 + r) * Dv + h * HDv + d0) = o;
    }
}

// -------------------- LayerNorm + residual add (+ fp16 hi/lo of new x) ----------
template <int RED>
__global__ void __launch_bounds__(128)
ln_add(const float* __restrict__ in0, const float* __restrict__ in1,
       const float* __restrict__ pbias,
       const float* __restrict__ g, const float* __restrict__ bl,
       float* __restrict__ x) {
    int n = blockIdx.x, tid = threadIdx.x;
    int lane = tid & 31, w = tid >> 5;
    float v[4];
    float s = 0.f, s2 = 0.f;
#pragma unroll
    for (int i = 0; i < 4; i++) {
        int j = tid + i * 128;
        float t = in0[(size_t)n * Dv + j];
        if (RED) t += in1[(size_t)n * Dv + j] + pbias[j];
        v[i] = t;
        s += t;
        s2 += t * t;
    }
    __shared__ float sh[8];
#pragma unroll
    for (int off = 16; off; off >>= 1) {
        s += __shfl_down_sync(0xffffffffu, s, off);
        s2 += __shfl_down_sync(0xffffffffu, s2, off);
    }
    if (lane == 0) { sh[w] = s; sh[4 + w] = s2; }
    __syncthreads();
    float S = sh[0] + sh[1] + sh[2] + sh[3];
    float S2 = sh[4] + sh[5] + sh[6] + sh[7];
    float mu = S * (1.f / Dv);
    float var = S2 * (1.f / Dv) - mu * mu;
    float rs = rsqrtf(var + 1e-5f);
#pragma unroll
    for (int i = 0; i < 4; i++) {
        int j = tid + i * 128;
        size_t idx = (size_t)n * Dv + j;
        float nv = x[idx] + (v[i] - mu) * rs * g[j] + bl[j];
        x[idx] = nv;
        __half h, l;
        split_fp16(nv, h, l);
        g_xh[idx] = h;
        g_xl[idx] = l;
    }
}

// -------------------- host driver --------------------
extern "C" void kernel_launch(void* const* d_in, const int* in_sizes, int n_in,
                              void* d_out, int out_size) {
    const int*   tokens = (const int*)d_in[0];
    const float* emb    = (const float*)d_in[1];
    const float* Wq     = (const float*)d_in[2];
    const float* bq     = (const float*)d_in[3];
    const float* Wk     = (const float*)d_in[4];
    const float* bk     = (const float*)d_in[5];
    const float* Wv     = (const float*)d_in[6];
    const float* bvp    = (const float*)d_in[7];
    const float* rfs    = (const float*)d_in[8];
    const float* ln1g   = (const float*)d_in[9];
    const float* ln1b   = (const float*)d_in[10];
    const float* ln2g   = (const float*)d_in[11];
    const float* ln2b   = (const float*)d_in[12];
    const float* WU     = (const float*)d_in[13];
    const float* bU     = (const float*)d_in[14];
    const float* WV     = (const float*)d_in[15];
    const float* bV     = (const float*)d_in[16];
    const float* Wout   = (const float*)d_in[17];
    const float* bout   = (const float*)d_in[18];
    float* out = (float*)d_out;

    static float *px = nullptr, *pa, *pv, *pbqkv, *ppart;
    static __half *pxh, *pxl, *pqkh, *pqkl, *phh, *pwh, *prfh, *prfl;
    if (!px) {
        cudaGetSymbolAddress((void**)&px, g_x);
        cudaGetSymbolAddress((void**)&pa, g_a);
        cudaGetSymbolAddress((void**)&pv, g_v);
        cudaGetSymbolAddress((void**)&pbqkv, g_bqkv);
        cudaGetSymbolAddress((void**)&ppart, g_part);
        cudaGetSymbolAddress((void**)&pxh, g_xh);
        cudaGetSymbolAddress((void**)&pxl, g_xl);
        cudaGetSymbolAddress((void**)&pqkh, g_qkh);
        cudaGetSymbolAddress((void**)&pqkl, g_qkl);
        cudaGetSymbolAddress((void**)&phh, g_hh);
        cudaGetSymbolAddress((void**)&pwh, g_wh);
        cudaGetSymbolAddress((void**)&prfh, g_rfh);
        cudaGetSymbolAddress((void**)&prfl, g_rfl);
        cudaFuncSetAttribute(gemm_tc<1>, cudaFuncAttributeMaxDynamicSharedMemorySize,
                             A_TILE + B_TILE);
        cudaFuncSetAttribute(gemm_tc<2>, cudaFuncAttributeMaxDynamicSharedMemorySize,
                             2 * A_TILE + B_TILE);
    }

    convw_all<<<(TOT4 + BIA4 + RF4 + 255) / 256, 256>>>(Wq, Wk, Wv, WU, WV, Wout,
                                                        bq, bk, bvp, rfs);
    embed_kernel<<<(NTOK * Dv + 255) / 256, 256>>>(tokens, emb);

    for (int l = 0; l < Lv; l++) {
        gemm_tc<1><<<dim3(QKVN / 128, NTOK / 128), 256, A_TILE + B_TILE>>>(
            pxh, nullptr, pwh + OFF_QKV + (size_t)l * Dv * QKVN, pbqkv + l * QKVN,
            pv, pqkh, pqkl, NTOK, QKVN, Dv, QKVN, Dv, 3);

        favor_chunk<<<dim3(NTOK / 32, Hv), 128>>>(prfh + (size_t)l * Hv * 4096,
                                                  prfl + (size_t)l * Hv * 4096);
        attn_scan<<<Bv * Hv * HDv, 64>>>();
        attn_apply<<<dim3(NCHUNK, Bv * Hv), 128>>>();

        ln_add<0><<<NTOK, 128>>>(pa, nullptr, nullptr,
                                 ln1g + l * Dv, ln1b + l * Dv, px);

        gemm_tc<1><<<dim3(FFNv / 128, NTOK / 128), 256, A_TILE + B_TILE>>>(
            pxh, nullptr, pwh + OFF_WU + (size_t)l * Dv * FFNv, bU + l * FFNv,
            nullptr, phh, nullptr, NTOK, FFNv, Dv, FFNv, Dv, 1);

        gemm_tc<1><<<dim3(Dv / 128, NTOK / 128, 2), 256, A_TILE + B_TILE>>>(
            phh, nullptr, pwh + OFF_WD + (size_t)l * FFNv * Dv, nullptr,
            ppart, nullptr, nullptr, NTOK, Dv, FFNv, Dv, 1024, 2);

        ln_add<1><<<NTOK, 128>>>(ppart, ppart + (size_t)NTOK * Dv, bV + l * Dv,
                                 ln2g + l * Dv, ln2b + l * Dv, px);
    }

    gemm_tc<2><<<dim3(VOCABv / 128, NTOK / 128, 2), 256, 2 * A_TILE + B_TILE>>>(
        pxh, pxl, pwh + OFF_WO, nullptr, ppart, nullptr, nullptr,
        NTOK, VOCABv, Dv, VOCABv, 256, 2);
    reduce2<<<(NTOK * VOCABv / 4 + 255) / 256, 256>>>(ppart, bout, out,
                                                      NTOK * VOCABv / 4, VOCABv - 1);
}